// round 2
// baseline (speedup 1.0000x reference)
#include <cuda_runtime.h>
#include <cstdint>
#include <math.h>

#define T_SEQ   256
#define BATCH   16
#define NINP    400
#define NHID    1150
#define VOCABP1 33279
#define M_TOK   (BATCH * T_SEQ)   // 4096

// ---------------- scratch (static device globals; no allocation) ----------------
__device__ float g_xa[(size_t)M_TOK * NHID];          // ping  (max width 1150)
__device__ float g_xb[(size_t)M_TOK * NHID];          // pong
__device__ float g_xg[(size_t)M_TOK * 4 * NHID];      // gate preactivations (max 4096x4600)
__device__ float g_h[2][BATCH * NHID];                // recurrent h ping-pong, layout [u][b]
__device__ float g_c[BATCH * NHID];                   // cell state, layout [u][b]
__device__ unsigned g_bar;                            // grid barrier counter

// ---------------- grid barrier (monotonic counter; reset kernel between launches) ----
__device__ __forceinline__ void grid_sync(unsigned target) {
    __syncthreads();
    if (threadIdx.x == 0) {
        __threadfence();
        atomicAdd(&g_bar, 1u);
        while (*(volatile unsigned*)&g_bar < target) { __nanosleep(40); }
        __threadfence();
    }
    __syncthreads();
}

__global__ void bar_reset_k() { g_bar = 0u; }

// ---------------- embedding gather ----------------
__global__ void embed_k(const int* __restrict__ tok, const float* __restrict__ emb,
                        float* __restrict__ x0) {
    int m = blockIdx.x;                  // m = b*T + t
    int t = tok[m];
    const float4* src = (const float4*)(emb + (size_t)t * NINP);
    float4* dst = (float4*)(x0 + (size_t)m * NINP);
    for (int i = threadIdx.x; i < NINP / 4; i += blockDim.x) dst[i] = src[i];
}

// ---------------- SGEMM: C[M,N] = A[M,K] * B (+bias) ----------------
// BTRANS=false: B is [K,N] row-major.  BTRANS=true: B is [N,K] row-major (C = A*B^T).
// M must be a multiple of 128 (always 4096 here). N,K arbitrary.
template<bool BTRANS, bool BIAS>
__global__ __launch_bounds__(256) void sgemm_k(
    const float* __restrict__ A, const float* __restrict__ B,
    const float* __restrict__ bias, float* __restrict__ C,
    int M, int N, int K)
{
    __shared__ float As[8][128];
    __shared__ float Bs[8][132];

    const int tid = threadIdx.x;
    const int bm = blockIdx.y * 128;
    const int bn = blockIdx.x * 128;
    const int tr = (tid >> 4) * 8;      // 0..120
    const int tc = (tid & 15) * 8;      // 0..120

    float acc[8][8];
#pragma unroll
    for (int y = 0; y < 8; y++)
#pragma unroll
        for (int x = 0; x < 8; x++) acc[y][x] = 0.f;

    const int a_m = tid >> 1;           // 0..127
    const int a_k = (tid & 1) * 4;      // 0 or 4

    for (int k0 = 0; k0 < K; k0 += 8) {
        // load A tile (transposed into As[k][m])
#pragma unroll
        for (int i = 0; i < 4; i++) {
            int gk = k0 + a_k + i;
            As[a_k + i][a_m] = (gk < K) ? A[(size_t)(bm + a_m) * K + gk] : 0.f;
        }
        // load B tile into Bs[k][n]
        if (BTRANS) {
            int n = tid >> 1;
            int kk = (tid & 1) * 4;
            int gn = bn + n;
            float v[4] = {0.f, 0.f, 0.f, 0.f};
            if (gn < N) {
                int gk = k0 + kk;
                if (((K & 3) == 0) && (gk + 3 < K)) {
                    float4 t4 = *(const float4*)&B[(size_t)gn * K + gk];
                    v[0] = t4.x; v[1] = t4.y; v[2] = t4.z; v[3] = t4.w;
                } else {
#pragma unroll
                    for (int i = 0; i < 4; i++)
                        if (gk + i < K) v[i] = B[(size_t)gn * K + gk + i];
                }
            }
#pragma unroll
            for (int i = 0; i < 4; i++) Bs[kk + i][n] = v[i];
        } else {
            int bk = tid >> 5;
            int nn = (tid & 31) * 4;
            int gk = k0 + bk;
            int gn = bn + nn;
            if (gk < K && gn + 3 < N) {
                float4 v = *(const float4*)&B[(size_t)gk * N + gn];
                *(float4*)&Bs[bk][nn] = v;
            } else {
#pragma unroll
                for (int i = 0; i < 4; i++)
                    Bs[bk][nn + i] = (gk < K && gn + i < N) ? B[(size_t)gk * N + gn + i] : 0.f;
            }
        }
        __syncthreads();

#pragma unroll
        for (int kk = 0; kk < 8; kk++) {
            float aF[8], bF[8];
            *(float4*)&aF[0] = *(const float4*)&As[kk][tr];
            *(float4*)&aF[4] = *(const float4*)&As[kk][tr + 4];
            *(float4*)&bF[0] = *(const float4*)&Bs[kk][tc];
            *(float4*)&bF[4] = *(const float4*)&Bs[kk][tc + 4];
#pragma unroll
            for (int y = 0; y < 8; y++)
#pragma unroll
                for (int x = 0; x < 8; x++) acc[y][x] = fmaf(aF[y], bF[x], acc[y][x]);
        }
        __syncthreads();
    }

#pragma unroll
    for (int y = 0; y < 8; y++) {
        int gm = bm + tr + y;
#pragma unroll
        for (int x = 0; x < 8; x++) {
            int gn = bn + tc + x;
            if (gn < N) {
                float v = acc[y][x];
                if (BIAS) v += bias[gn];
                C[(size_t)gm * N + gn] = v;
            }
        }
    }
}

// ---------------- persistent LSTM recurrence (one layer) ----------------
// grid = NCTA, block = 256. Each CTA owns 8 units (x4 gates = 32 dot columns).
// 256 threads = 32 column-lanes x 8 k-chunks. One grid barrier per timestep.
template<int U, int NCTA>
__global__ __launch_bounds__(256) void lstm_k(
    const float* __restrict__ Um,   // [U][4U]
    const float* __restrict__ xg,   // [4096][4U], row m = b*T + t
    float* __restrict__ xout)       // [4096][U]
{
    constexpr int N4 = 4 * U;
    constexpr int KC = (U + 7) / 8;

    extern __shared__ float sm[];
    float* h_s = sm;                      // [U][16]  (k-major, batch inner)
    float* red = sm + U * 16;             // [16][256] : red[b*256 + tid]
    float* gat = red + 16 * 256;          // [32][16]

    const int tid  = threadIdx.x;
    const int lane = tid & 31;
    const int kc   = tid >> 5;
    const int g    = lane >> 3;           // gate 0..3 (i,f,c,o)
    const int ul   = lane & 7;
    const int u    = blockIdx.x * 8 + ul;
    const bool uok = (u < U);
    const int j    = g * U + u;
    const int k0   = kc * KC;
    const int k1   = (k0 + KC < U) ? (k0 + KC) : U;

    // zero state
    for (int idx = blockIdx.x * 256 + tid; idx < 16 * U; idx += NCTA * 256) {
        g_h[0][idx] = 0.f; g_h[1][idx] = 0.f; g_c[idx] = 0.f;
    }
    unsigned gen = 1;
    grid_sync(gen * NCTA);

    for (int t = 0; t < T_SEQ; ++t) {
        const float* hg = g_h[t & 1];
        float* hn = g_h[(t & 1) ^ 1];

        // stage h into shared (L2 read: cross-CTA data, bypass L1)
        for (int idx = tid; idx < U * 16; idx += 256) h_s[idx] = __ldcg(&hg[idx]);
        __syncthreads();

        float acc[16];
#pragma unroll
        for (int b = 0; b < 16; b++) acc[b] = 0.f;

        if (uok) {
            const float* Up = Um + j;
#pragma unroll 4
            for (int k = k0; k < k1; ++k) {
                float uv = __ldg(&Up[(size_t)k * N4]);
                const float4* hv = (const float4*)(h_s + (k << 4));
                float4 ha = hv[0], hb = hv[1], hc = hv[2], hd = hv[3];
                acc[0]  = fmaf(ha.x, uv, acc[0]);
                acc[1]  = fmaf(ha.y, uv, acc[1]);
                acc[2]  = fmaf(ha.z, uv, acc[2]);
                acc[3]  = fmaf(ha.w, uv, acc[3]);
                acc[4]  = fmaf(hb.x, uv, acc[4]);
                acc[5]  = fmaf(hb.y, uv, acc[5]);
                acc[6]  = fmaf(hb.z, uv, acc[6]);
                acc[7]  = fmaf(hb.w, uv, acc[7]);
                acc[8]  = fmaf(hc.x, uv, acc[8]);
                acc[9]  = fmaf(hc.y, uv, acc[9]);
                acc[10] = fmaf(hc.z, uv, acc[10]);
                acc[11] = fmaf(hc.w, uv, acc[11]);
                acc[12] = fmaf(hd.x, uv, acc[12]);
                acc[13] = fmaf(hd.y, uv, acc[13]);
                acc[14] = fmaf(hd.z, uv, acc[14]);
                acc[15] = fmaf(hd.w, uv, acc[15]);
            }
        }
#pragma unroll
        for (int b = 0; b < 16; b++) red[b * 256 + tid] = acc[b];
        __syncthreads();

        // reduce across the 8 k-chunks: 512 outputs (32 cols x 16 batches)
#pragma unroll
        for (int o = tid; o < 512; o += 256) {
            int c = o & 31, b = o >> 5;
            float s = 0.f;
#pragma unroll
            for (int q = 0; q < 8; q++) s += red[b * 256 + q * 32 + c];
            int gg = c >> 3;
            int uu = blockIdx.x * 8 + (c & 7);
            if (uu < U) {
                s += __ldg(&xg[((size_t)b * T_SEQ + t) * N4 + (size_t)gg * U + uu]);
                gat[c * 16 + b] = s;
            }
        }
        __syncthreads();

        // gate math + state update (128 (b,u) pairs per CTA)
        if (tid < 128) {
            int b = tid & 15, w = tid >> 4;
            int uu = blockIdx.x * 8 + w;
            if (uu < U) {
                float iv = gat[(0 * 8 + w) * 16 + b];
                float fv = gat[(1 * 8 + w) * 16 + b];
                float cg = gat[(2 * 8 + w) * 16 + b];
                float ov = gat[(3 * 8 + w) * 16 + b];
                iv = 1.f / (1.f + __expf(-iv));
                fv = 1.f / (1.f + __expf(-fv));
                ov = 1.f / (1.f + __expf(-ov));
                cg = tanhf(cg);
                float cold = g_c[uu * 16 + b];
                float cn = fv * cold + iv * cg;
                float hv = ov * tanhf(cn);
                g_c[uu * 16 + b] = cn;
                hn[uu * 16 + b] = hv;
                xout[((size_t)b * T_SEQ + t) * U + uu] = hv;
            }
        }
        gen++;
        grid_sync(gen * NCTA);
    }
}

// ---------------- in-place row softmax over N columns ----------------
__global__ __launch_bounds__(256) void softmax_k(float* __restrict__ out, int N) {
    int m = blockIdx.x;
    float* row = out + (size_t)m * N;
    __shared__ float s1[8];
    __shared__ float sb;
    int tid = threadIdx.x, wid = tid >> 5, ln = tid & 31;

    float lm = -3.4e38f;
    for (int i = tid; i < N; i += 256) lm = fmaxf(lm, row[i]);
#pragma unroll
    for (int o = 16; o; o >>= 1) lm = fmaxf(lm, __shfl_xor_sync(0xffffffffu, lm, o));
    if (!ln) s1[wid] = lm;
    __syncthreads();
    if (tid == 0) {
        float v = s1[0];
#pragma unroll
        for (int q = 1; q < 8; q++) v = fmaxf(v, s1[q]);
        sb = v;
    }
    __syncthreads();
    float mx = sb;
    __syncthreads();

    float ls = 0.f;
    for (int i = tid; i < N; i += 256) ls += __expf(row[i] - mx);
#pragma unroll
    for (int o = 16; o; o >>= 1) ls += __shfl_xor_sync(0xffffffffu, ls, o);
    if (!ln) s1[wid] = ls;
    __syncthreads();
    if (tid == 0) {
        float v = 0.f;
#pragma unroll
        for (int q = 0; q < 8; q++) v += s1[q];
        sb = 1.f / v;
    }
    __syncthreads();
    float inv = sb;

    for (int i = tid; i < N; i += 256) row[i] = __expf(row[i] - mx) * inv;
}

// ---------------- launch ----------------
extern "C" void kernel_launch(void* const* d_in, const int* in_sizes, int n_in,
                              void* d_out, int out_size)
{
    (void)in_sizes; (void)n_in; (void)out_size;
    const int*   tok = (const int*)d_in[0];
    const float* emb = (const float*)d_in[1];
    const float* W0  = (const float*)d_in[2];
    const float* U0  = (const float*)d_in[3];
    const float* b0  = (const float*)d_in[4];
    const float* W1  = (const float*)d_in[5];
    const float* U1  = (const float*)d_in[6];
    const float* b1  = (const float*)d_in[7];
    const float* W2  = (const float*)d_in[8];
    const float* U2  = (const float*)d_in[9];
    const float* b2  = (const float*)d_in[10];
    float* out = (float*)d_out;

    float *xa, *xb, *xg;
    cudaGetSymbolAddress((void**)&xa, g_xa);
    cudaGetSymbolAddress((void**)&xb, g_xb);
    cudaGetSymbolAddress((void**)&xg, g_xg);

    const int SMEM_BIG   = (NHID * 16 + 256 * 16 + 32 * 16) * 4;   // 92032
    const int SMEM_SMALL = (NINP * 16 + 256 * 16 + 32 * 16) * 4;   // 44032
    cudaFuncSetAttribute(lstm_k<NHID, 144>, cudaFuncAttributeMaxDynamicSharedMemorySize, SMEM_BIG);
    cudaFuncSetAttribute(lstm_k<NINP, 50>,  cudaFuncAttributeMaxDynamicSharedMemorySize, SMEM_SMALL);

    // 1) embedding
    embed_k<<<M_TOK, 128>>>(tok, emb, xa);

    // 2) layer 0: xg = x @ W0 + b0 ; recurrence
    sgemm_k<false, true><<<dim3((4 * NHID + 127) / 128, M_TOK / 128), 256>>>(
        xa, W0, b0, xg, M_TOK, 4 * NHID, NINP);
    bar_reset_k<<<1, 1>>>();
    lstm_k<NHID, 144><<<144, 256, SMEM_BIG>>>(U0, xg, xb);

    // 3) layer 1
    sgemm_k<false, true><<<dim3((4 * NHID + 127) / 128, M_TOK / 128), 256>>>(
        xb, W1, b1, xg, M_TOK, 4 * NHID, NHID);
    bar_reset_k<<<1, 1>>>();
    lstm_k<NHID, 144><<<144, 256, SMEM_BIG>>>(U1, xg, xa);

    // 4) layer 2 (units = 400)
    sgemm_k<false, true><<<dim3((4 * NINP + 127) / 128, M_TOK / 128), 256>>>(
        xa, W2, b2, xg, M_TOK, 4 * NINP, NHID);
    bar_reset_k<<<1, 1>>>();
    lstm_k<NINP, 50><<<50, 256, SMEM_SMALL>>>(U2, xg, xb);

    // 5) tied decode: logits = x @ emb^T   -> write straight into d_out
    sgemm_k<true, false><<<dim3((VOCABP1 + 127) / 128, M_TOK / 128), 256>>>(
        xb, emb, nullptr, out, M_TOK, VOCABP1, NINP);

    // 6) in-place softmax
    softmax_k<<<M_TOK, 256>>>(out, VOCABP1);
}

// round 3
// speedup vs baseline: 1.0085x; 1.0085x over previous
#include <cuda_runtime.h>
#include <cstdint>
#include <math.h>

#define T_SEQ   256
#define BATCH   16
#define NINP    400
#define NHID    1150
#define VOCABP1 33279
#define M_TOK   (BATCH * T_SEQ)   // 4096

// ---------------- scratch (static device globals; no allocation) ----------------
__device__ float g_xa[(size_t)M_TOK * NHID];          // ping  (max width 1150)
__device__ float g_xb[(size_t)M_TOK * NHID];          // pong
__device__ float g_xg[(size_t)M_TOK * 4 * NHID];      // gate preactivations (max 4096x4600)
__device__ float g_h[2][BATCH * NHID];                // recurrent h ping-pong, layout [u][b]
__device__ float g_c[BATCH * NHID];                   // cell state, layout [u][b]
__device__ unsigned g_bar;                            // grid barrier counter

// ---------------- grid barrier (monotonic counter; reset kernel between launches) ----
__device__ __forceinline__ void grid_sync(unsigned target) {
    __syncthreads();
    if (threadIdx.x == 0) {
        __threadfence();
        atomicAdd(&g_bar, 1u);
        while (*(volatile unsigned*)&g_bar < target) { __nanosleep(40); }
        __threadfence();
    }
    __syncthreads();
}

__global__ void bar_reset_k() { g_bar = 0u; }

// ---------------- embedding gather ----------------
__global__ void embed_k(const int* __restrict__ tok, const float* __restrict__ emb,
                        float* __restrict__ x0) {
    int m = blockIdx.x;                  // m = b*T + t
    int t = tok[m];
    const float4* src = (const float4*)(emb + (size_t)t * NINP);
    float4* dst = (float4*)(x0 + (size_t)m * NINP);
    for (int i = threadIdx.x; i < NINP / 4; i += blockDim.x) dst[i] = src[i];
}

// ---------------- SGEMM: C[M,N] = A[M,K] * B (+bias) ----------------
// BTRANS=false: B is [K,N] row-major.  BTRANS=true: B is [N,K] row-major (C = A*B^T).
// M must be a multiple of 128 (always 4096 here). N,K arbitrary.
template<bool BTRANS, bool BIAS>
__global__ __launch_bounds__(256) void sgemm_k(
    const float* __restrict__ A, const float* __restrict__ B,
    const float* __restrict__ bias, float* __restrict__ C,
    int M, int N, int K)
{
    __shared__ float As[8][128];
    __shared__ float Bs[8][132];

    const int tid = threadIdx.x;
    const int bm = blockIdx.y * 128;
    const int bn = blockIdx.x * 128;
    const int tr = (tid >> 4) * 8;      // 0..120
    const int tc = (tid & 15) * 8;      // 0..120

    float acc[8][8];
#pragma unroll
    for (int y = 0; y < 8; y++)
#pragma unroll
        for (int x = 0; x < 8; x++) acc[y][x] = 0.f;

    const int a_m = tid >> 1;           // 0..127
    const int a_k = (tid & 1) * 4;      // 0 or 4

    for (int k0 = 0; k0 < K; k0 += 8) {
        // load A tile (transposed into As[k][m])
#pragma unroll
        for (int i = 0; i < 4; i++) {
            int gk = k0 + a_k + i;
            As[a_k + i][a_m] = (gk < K) ? A[(size_t)(bm + a_m) * K + gk] : 0.f;
        }
        // load B tile into Bs[k][n]
        if (BTRANS) {
            int n = tid >> 1;
            int kk = (tid & 1) * 4;
            int gn = bn + n;
            float v[4] = {0.f, 0.f, 0.f, 0.f};
            if (gn < N) {
                int gk = k0 + kk;
                if (((K & 3) == 0) && (gk + 3 < K)) {
                    float4 t4 = *(const float4*)&B[(size_t)gn * K + gk];
                    v[0] = t4.x; v[1] = t4.y; v[2] = t4.z; v[3] = t4.w;
                } else {
#pragma unroll
                    for (int i = 0; i < 4; i++)
                        if (gk + i < K) v[i] = B[(size_t)gn * K + gk + i];
                }
            }
#pragma unroll
            for (int i = 0; i < 4; i++) Bs[kk + i][n] = v[i];
        } else {
            int bk = tid >> 5;
            int nn = (tid & 31) * 4;
            int gk = k0 + bk;
            int gn = bn + nn;
            if (gk < K && gn + 3 < N) {
                float4 v = *(const float4*)&B[(size_t)gk * N + gn];
                *(float4*)&Bs[bk][nn] = v;
            } else {
#pragma unroll
                for (int i = 0; i < 4; i++)
                    Bs[bk][nn + i] = (gk < K && gn + i < N) ? B[(size_t)gk * N + gn + i] : 0.f;
            }
        }
        __syncthreads();

#pragma unroll
        for (int kk = 0; kk < 8; kk++) {
            float aF[8], bF[8];
            *(float4*)&aF[0] = *(const float4*)&As[kk][tr];
            *(float4*)&aF[4] = *(const float4*)&As[kk][tr + 4];
            *(float4*)&bF[0] = *(const float4*)&Bs[kk][tc];
            *(float4*)&bF[4] = *(const float4*)&Bs[kk][tc + 4];
#pragma unroll
            for (int y = 0; y < 8; y++)
#pragma unroll
                for (int x = 0; x < 8; x++) acc[y][x] = fmaf(aF[y], bF[x], acc[y][x]);
        }
        __syncthreads();
    }

#pragma unroll
    for (int y = 0; y < 8; y++) {
        int gm = bm + tr + y;
#pragma unroll
        for (int x = 0; x < 8; x++) {
            int gn = bn + tc + x;
            if (gn < N) {
                float v = acc[y][x];
                if (BIAS) v += bias[gn];
                C[(size_t)gm * N + gn] = v;
            }
        }
    }
}

// ---------------- persistent LSTM recurrence (one layer) ----------------
// grid = NCTA, block = 256. Each CTA owns 8 units (x4 gates = 32 dot columns).
// 256 threads = 32 column-lanes x 8 k-chunks. One grid barrier per timestep.
template<int U, int NCTA>
__global__ __launch_bounds__(256) void lstm_k(
    const float* __restrict__ Um,   // [U][4U]
    const float* __restrict__ xg,   // [4096][4U], row m = b*T + t
    float* __restrict__ xout)       // [4096][U]
{
    constexpr int N4 = 4 * U;
    constexpr int KC = (U + 7) / 8;

    extern __shared__ float sm[];
    float* h_s = sm;                      // [U][16]  (k-major, batch inner)
    float* red = sm + U * 16;             // [16][256] : red[b*256 + tid]
    float* gat = red + 16 * 256;          // [32][16]

    const int tid  = threadIdx.x;
    const int lane = tid & 31;
    const int kc   = tid >> 5;
    const int g    = lane >> 3;           // gate 0..3 (i,f,c,o)
    const int ul   = lane & 7;
    const int u    = blockIdx.x * 8 + ul;
    const bool uok = (u < U);
    const int j    = g * U + u;
    const int k0   = kc * KC;
    const int k1   = (k0 + KC < U) ? (k0 + KC) : U;

    // zero state
    for (int idx = blockIdx.x * 256 + tid; idx < 16 * U; idx += NCTA * 256) {
        g_h[0][idx] = 0.f; g_h[1][idx] = 0.f; g_c[idx] = 0.f;
    }
    unsigned gen = 1;
    grid_sync(gen * NCTA);

    for (int t = 0; t < T_SEQ; ++t) {
        const float* hg = g_h[t & 1];
        float* hn = g_h[(t & 1) ^ 1];

        // stage h into shared (L2 read: cross-CTA data, bypass L1)
        for (int idx = tid; idx < U * 16; idx += 256) h_s[idx] = __ldcg(&hg[idx]);
        __syncthreads();

        float acc[16];
#pragma unroll
        for (int b = 0; b < 16; b++) acc[b] = 0.f;

        if (uok) {
            const float* Up = Um + j;
#pragma unroll 4
            for (int k = k0; k < k1; ++k) {
                float uv = __ldg(&Up[(size_t)k * N4]);
                const float4* hv = (const float4*)(h_s + (k << 4));
                float4 ha = hv[0], hb = hv[1], hc = hv[2], hd = hv[3];
                acc[0]  = fmaf(ha.x, uv, acc[0]);
                acc[1]  = fmaf(ha.y, uv, acc[1]);
                acc[2]  = fmaf(ha.z, uv, acc[2]);
                acc[3]  = fmaf(ha.w, uv, acc[3]);
                acc[4]  = fmaf(hb.x, uv, acc[4]);
                acc[5]  = fmaf(hb.y, uv, acc[5]);
                acc[6]  = fmaf(hb.z, uv, acc[6]);
                acc[7]  = fmaf(hb.w, uv, acc[7]);
                acc[8]  = fmaf(hc.x, uv, acc[8]);
                acc[9]  = fmaf(hc.y, uv, acc[9]);
                acc[10] = fmaf(hc.z, uv, acc[10]);
                acc[11] = fmaf(hc.w, uv, acc[11]);
                acc[12] = fmaf(hd.x, uv, acc[12]);
                acc[13] = fmaf(hd.y, uv, acc[13]);
                acc[14] = fmaf(hd.z, uv, acc[14]);
                acc[15] = fmaf(hd.w, uv, acc[15]);
            }
        }
#pragma unroll
        for (int b = 0; b < 16; b++) red[b * 256 + tid] = acc[b];
        __syncthreads();

        // reduce across the 8 k-chunks: 512 outputs (32 cols x 16 batches)
#pragma unroll
        for (int o = tid; o < 512; o += 256) {
            int c = o & 31, b = o >> 5;
            float s = 0.f;
#pragma unroll
            for (int q = 0; q < 8; q++) s += red[b * 256 + q * 32 + c];
            int gg = c >> 3;
            int uu = blockIdx.x * 8 + (c & 7);
            if (uu < U) {
                s += __ldg(&xg[((size_t)b * T_SEQ + t) * N4 + (size_t)gg * U + uu]);
                gat[c * 16 + b] = s;
            }
        }
        __syncthreads();

        // gate math + state update (128 (b,u) pairs per CTA)
        if (tid < 128) {
            int b = tid & 15, w = tid >> 4;
            int uu = blockIdx.x * 8 + w;
            if (uu < U) {
                float iv = gat[(0 * 8 + w) * 16 + b];
                float fv = gat[(1 * 8 + w) * 16 + b];
                float cg = gat[(2 * 8 + w) * 16 + b];
                float ov = gat[(3 * 8 + w) * 16 + b];
                iv = 1.f / (1.f + __expf(-iv));
                fv = 1.f / (1.f + __expf(-fv));
                ov = 1.f / (1.f + __expf(-ov));
                cg = tanhf(cg);
                float cold = g_c[uu * 16 + b];
                float cn = fv * cold + iv * cg;
                float hv = ov * tanhf(cn);
                g_c[uu * 16 + b] = cn;
                hn[uu * 16 + b] = hv;
                xout[((size_t)b * T_SEQ + t) * U + uu] = hv;
            }
        }
        gen++;
        grid_sync(gen * NCTA);
    }
}

// ---------------- in-place row softmax over N columns ----------------
__global__ __launch_bounds__(256) void softmax_k(float* __restrict__ out, int N) {
    int m = blockIdx.x;
    float* row = out + (size_t)m * N;
    __shared__ float s1[8];
    __shared__ float sb;
    int tid = threadIdx.x, wid = tid >> 5, ln = tid & 31;

    float lm = -3.4e38f;
    for (int i = tid; i < N; i += 256) lm = fmaxf(lm, row[i]);
#pragma unroll
    for (int o = 16; o; o >>= 1) lm = fmaxf(lm, __shfl_xor_sync(0xffffffffu, lm, o));
    if (!ln) s1[wid] = lm;
    __syncthreads();
    if (tid == 0) {
        float v = s1[0];
#pragma unroll
        for (int q = 1; q < 8; q++) v = fmaxf(v, s1[q]);
        sb = v;
    }
    __syncthreads();
    float mx = sb;
    __syncthreads();

    float ls = 0.f;
    for (int i = tid; i < N; i += 256) ls += __expf(row[i] - mx);
#pragma unroll
    for (int o = 16; o; o >>= 1) ls += __shfl_xor_sync(0xffffffffu, ls, o);
    if (!ln) s1[wid] = ls;
    __syncthreads();
    if (tid == 0) {
        float v = 0.f;
#pragma unroll
        for (int q = 0; q < 8; q++) v += s1[q];
        sb = 1.f / v;
    }
    __syncthreads();
    float inv = sb;

    for (int i = tid; i < N; i += 256) row[i] = __expf(row[i] - mx) * inv;
}

// ---------------- launch ----------------
extern "C" void kernel_launch(void* const* d_in, const int* in_sizes, int n_in,
                              void* d_out, int out_size)
{
    (void)in_sizes; (void)n_in; (void)out_size;
    const int*   tok = (const int*)d_in[0];
    const float* emb = (const float*)d_in[1];
    const float* W0  = (const float*)d_in[2];
    const float* U0  = (const float*)d_in[3];
    const float* b0  = (const float*)d_in[4];
    const float* W1  = (const float*)d_in[5];
    const float* U1  = (const float*)d_in[6];
    const float* b1  = (const float*)d_in[7];
    const float* W2  = (const float*)d_in[8];
    const float* U2  = (const float*)d_in[9];
    const float* b2  = (const float*)d_in[10];
    float* out = (float*)d_out;

    float *xa, *xb, *xg;
    cudaGetSymbolAddress((void**)&xa, g_xa);
    cudaGetSymbolAddress((void**)&xb, g_xb);
    cudaGetSymbolAddress((void**)&xg, g_xg);

    const int SMEM_BIG   = (NHID * 16 + 256 * 16 + 32 * 16) * 4;   // 92032
    const int SMEM_SMALL = (NINP * 16 + 256 * 16 + 32 * 16) * 4;   // 44032
    cudaFuncSetAttribute(lstm_k<NHID, 144>, cudaFuncAttributeMaxDynamicSharedMemorySize, SMEM_BIG);
    cudaFuncSetAttribute(lstm_k<NINP, 50>,  cudaFuncAttributeMaxDynamicSharedMemorySize, SMEM_SMALL);

    // 1) embedding
    embed_k<<<M_TOK, 128>>>(tok, emb, xa);

    // 2) layer 0: xg = x @ W0 + b0 ; recurrence
    sgemm_k<false, true><<<dim3((4 * NHID + 127) / 128, M_TOK / 128), 256>>>(
        xa, W0, b0, xg, M_TOK, 4 * NHID, NINP);
    bar_reset_k<<<1, 1>>>();
    lstm_k<NHID, 144><<<144, 256, SMEM_BIG>>>(U0, xg, xb);

    // 3) layer 1
    sgemm_k<false, true><<<dim3((4 * NHID + 127) / 128, M_TOK / 128), 256>>>(
        xb, W1, b1, xg, M_TOK, 4 * NHID, NHID);
    bar_reset_k<<<1, 1>>>();
    lstm_k<NHID, 144><<<144, 256, SMEM_BIG>>>(U1, xg, xa);

    // 4) layer 2 (units = 400)
    sgemm_k<false, true><<<dim3((4 * NINP + 127) / 128, M_TOK / 128), 256>>>(
        xa, W2, b2, xg, M_TOK, 4 * NINP, NHID);
    bar_reset_k<<<1, 1>>>();
    lstm_k<NINP, 50><<<50, 256, SMEM_SMALL>>>(U2, xg, xb);

    // 5) tied decode: logits = x @ emb^T   -> write straight into d_out
    sgemm_k<true, false><<<dim3((VOCABP1 + 127) / 128, M_TOK / 128), 256>>>(
        xb, emb, nullptr, out, M_TOK, VOCABP1, NINP);

    // 6) in-place softmax
    softmax_k<<<M_TOK, 256>>>(out, VOCABP1);
}

// round 5
// speedup vs baseline: 1.2810x; 1.2702x over previous
#include <cuda_runtime.h>
#include <cstdint>
#include <math.h>

#define T_SEQ   256
#define BATCH   16
#define NINP    400
#define NHID    1150
#define VOCABP1 33279
#define M_TOK   (BATCH * T_SEQ)   // 4096

// ---------------- scratch (static device globals; no allocation) ----------------
__device__ float g_xa[(size_t)M_TOK * NHID];          // ping  (max width 1150)
__device__ float g_xb[(size_t)M_TOK * NHID];          // pong
__device__ float g_xg[(size_t)M_TOK * 4 * NHID];      // gate preactivations (max 4096x4600)
__device__ float g_h[2][BATCH * NHID];                // recurrent h ping-pong, layout [u][b]
__device__ float g_c[BATCH * NHID];                   // cell state, layout [u][b]
__device__ unsigned g_bar;                            // grid barrier counter

// ---------------- grid barrier ----------------
__device__ __forceinline__ void grid_sync(unsigned target) {
    __syncthreads();
    if (threadIdx.x == 0) {
        __threadfence();
        atomicAdd(&g_bar, 1u);
        while (*(volatile unsigned*)&g_bar < target) { __nanosleep(40); }
        __threadfence();
    }
    __syncthreads();
}

__global__ void bar_reset_k() { g_bar = 0u; }

// ---------------- embedding gather ----------------
__global__ void embed_k(const int* __restrict__ tok, const float* __restrict__ emb,
                        float* __restrict__ x0) {
    int m = blockIdx.x;                  // m = b*T + t
    int t = tok[m];
    const float4* src = (const float4*)(emb + (size_t)t * NINP);
    float4* dst = (float4*)(x0 + (size_t)m * NINP);
    for (int i = threadIdx.x; i < NINP / 4; i += blockDim.x) dst[i] = src[i];
}

// ---------------- tf32 helpers ----------------
__device__ __forceinline__ float tf32f(float x) {
    uint32_t u;
    asm("cvt.rna.tf32.f32 %0, %1;" : "=r"(u) : "f"(x));
    return __uint_as_float(u);
}

#define MMA_TF32(d, a, b)                                                     \
    asm volatile("mma.sync.aligned.m16n8k8.row.col.f32.tf32.tf32.f32 "        \
                 "{%0,%1,%2,%3}, {%4,%5,%6,%7}, {%8,%9}, {%0,%1,%2,%3};"      \
                 : "+f"(d[0]), "+f"(d[1]), "+f"(d[2]), "+f"(d[3])             \
                 : "r"(a[0]), "r"(a[1]), "r"(a[2]), "r"(a[3]),                \
                   "r"(b[0]), "r"(b[1]))

// alignment-safe 4-float row load into v[0..3]; p must be 4B aligned (always true).
// in-bounds for all 4 elements is the caller's responsibility.
__device__ __forceinline__ void ld4_safe(const float* p, float* v) {
    uintptr_t a = (uintptr_t)p;
    if ((a & 15u) == 0) {
        float4 t = *(const float4*)p;
        v[0] = t.x; v[1] = t.y; v[2] = t.z; v[3] = t.w;
    } else if ((a & 7u) == 0) {
        float2 t0 = *(const float2*)p;
        float2 t1 = *(const float2*)(p + 2);
        v[0] = t0.x; v[1] = t0.y; v[2] = t1.x; v[3] = t1.y;
    } else {
        v[0] = p[0]; v[1] = p[1]; v[2] = p[2]; v[3] = p[3];
    }
}

// ---------------- TF32 tensor-core GEMM: C[M,N] = A[M,K] * B (+bias) -------------
// BTRANS=false: B is [K,N] row-major.  BTRANS=true: B is [N,K] row-major (C = A*B^T).
// M must be a multiple of 128 (always 4096 here). N,K arbitrary.
// CTA tile 128x128, BK=16. 8 warps, each computes a 64x32 warp tile with
// m16n8k8 tf32 MMA. Global loads register-prefetched one k-tile ahead.
template<bool BTRANS, bool BIAS>
__global__ __launch_bounds__(256) void mma_gemm_k(
    const float* __restrict__ A, const float* __restrict__ B,
    const float* __restrict__ bias, float* __restrict__ C,
    int M, int N, int K)
{
    __shared__ float As[16][136];   // [k][m], pad 136 -> conflict-free frag loads
    __shared__ float Bs[16][136];   // [k][n]

    const int tid  = threadIdx.x;
    const int bm   = blockIdx.y * 128;
    const int bn   = blockIdx.x * 128;
    const int wid  = tid >> 5;
    const int lane = tid & 31;
    const int wm   = (wid >> 2) * 64;     // 0 or 64
    const int wn   = (wid & 3) * 32;      // 0,32,64,96
    const int gID  = lane >> 2;           // 0..7
    const int tg   = lane & 3;            // 0..3

    // global-load thread mappings
    const int arow = tid >> 2;            // 0..63  (rows arow, arow+64)
    const int acol = (tid & 3) * 4;       // 0,4,8,12
    const int bkr  = tid >> 5;            // 0..7   (rows bkr, bkr+8)      [!BTRANS]
    const int bnc  = (tid & 31) * 4;      // 0..124                        [!BTRANS]
    const int tnr  = tid >> 2;            // 0..63  (n rows tnr, tnr+64)   [BTRANS]
    const int tkc  = (tid & 3) * 4;       // 0,4,8,12                      [BTRANS]

    float acc[4][4][4];
#pragma unroll
    for (int mf = 0; mf < 4; mf++)
#pragma unroll
        for (int nf = 0; nf < 4; nf++)
#pragma unroll
            for (int i = 0; i < 4; i++) acc[mf][nf][i] = 0.f;

    float ar[8], br[8];

    auto loadg = [&](int k0) {
        // ---- A: [M,K] row-major, 128x16 tile ----
#pragma unroll
        for (int j = 0; j < 2; j++) {
            int r = arow + j * 64;
            const float* p = A + (size_t)(bm + r) * K + k0 + acol;
            if (k0 + acol + 3 < K) {
                ld4_safe(p, &ar[j * 4]);
            } else {
#pragma unroll
                for (int i = 0; i < 4; i++)
                    ar[j * 4 + i] = (k0 + acol + i < K) ? p[i] : 0.f;
            }
        }
        // ---- B ----
        if (BTRANS) {
#pragma unroll
            for (int j = 0; j < 2; j++) {
                int gn = bn + tnr + j * 64;
                int gk = k0 + tkc;
                const float* p = B + (size_t)gn * K + gk;
                if (gn < N && gk + 3 < K) {
                    ld4_safe(p, &br[j * 4]);
                } else {
#pragma unroll
                    for (int i = 0; i < 4; i++)
                        br[j * 4 + i] = (gn < N && gk + i < K) ? p[i] : 0.f;
                }
            }
        } else {
#pragma unroll
            for (int j = 0; j < 2; j++) {
                int gk = k0 + bkr + j * 8;
                int gn = bn + bnc;
                const float* p = B + (size_t)gk * N + gn;
                if (gk < K && gn + 3 < N) {
                    ld4_safe(p, &br[j * 4]);
                } else {
#pragma unroll
                    for (int i = 0; i < 4; i++)
                        br[j * 4 + i] = (gk < K && gn + i < N) ? p[i] : 0.f;
                }
            }
        }
    };

    auto stores = [&]() {
#pragma unroll
        for (int j = 0; j < 2; j++)
#pragma unroll
            for (int i = 0; i < 4; i++)
                As[acol + i][arow + j * 64] = tf32f(ar[j * 4 + i]);
        if (BTRANS) {
#pragma unroll
            for (int j = 0; j < 2; j++)
#pragma unroll
                for (int i = 0; i < 4; i++)
                    Bs[tkc + i][tnr + j * 64] = tf32f(br[j * 4 + i]);
        } else {
#pragma unroll
            for (int j = 0; j < 2; j++)
#pragma unroll
                for (int i = 0; i < 4; i++)
                    Bs[bkr + j * 8][bnc + i] = tf32f(br[j * 4 + i]);
        }
    };

    const int nkt = (K + 15) / 16;
    loadg(0);
    stores();
    __syncthreads();

    for (int kt = 0; kt < nkt; kt++) {
        const bool more = (kt + 1 < nkt);
        if (more) loadg((kt + 1) * 16);

#pragma unroll
        for (int kk = 0; kk < 16; kk += 8) {
            uint32_t af[4][4], bf[4][2];
#pragma unroll
            for (int mf = 0; mf < 4; mf++) {
                int m = wm + mf * 16 + gID;
                af[mf][0] = __float_as_uint(As[kk + tg][m]);
                af[mf][1] = __float_as_uint(As[kk + tg][m + 8]);
                af[mf][2] = __float_as_uint(As[kk + 4 + tg][m]);
                af[mf][3] = __float_as_uint(As[kk + 4 + tg][m + 8]);
            }
#pragma unroll
            for (int nf = 0; nf < 4; nf++) {
                int n = wn + nf * 8 + gID;
                bf[nf][0] = __float_as_uint(Bs[kk + tg][n]);
                bf[nf][1] = __float_as_uint(Bs[kk + 4 + tg][n]);
            }
#pragma unroll
            for (int mf = 0; mf < 4; mf++)
#pragma unroll
                for (int nf = 0; nf < 4; nf++)
                    MMA_TF32(acc[mf][nf], af[mf], bf[nf]);
        }
        __syncthreads();
        if (more) {
            stores();
            __syncthreads();
        }
    }

    // epilogue
#pragma unroll
    for (int mf = 0; mf < 4; mf++) {
        int r0 = bm + wm + mf * 16 + gID;
#pragma unroll
        for (int nf = 0; nf < 4; nf++) {
            int c0 = bn + wn + nf * 8 + tg * 2;
            float b0v = 0.f, b1v = 0.f;
            if (BIAS) {
                if (c0 < N)     b0v = bias[c0];
                if (c0 + 1 < N) b1v = bias[c0 + 1];
            }
            if (c0 < N) {
                C[(size_t)r0 * N + c0]       = acc[mf][nf][0] + b0v;
                C[(size_t)(r0 + 8) * N + c0] = acc[mf][nf][2] + b0v;
            }
            if (c0 + 1 < N) {
                C[(size_t)r0 * N + c0 + 1]       = acc[mf][nf][1] + b1v;
                C[(size_t)(r0 + 8) * N + c0 + 1] = acc[mf][nf][3] + b1v;
            }
        }
    }
}

// ---------------- persistent LSTM recurrence (one layer) ----------------
// grid = NCTA, block = 256. Each CTA owns 8 units (x4 gates = 32 dot columns).
// 256 threads = 32 column-lanes x 8 k-chunks. One grid barrier per timestep.
template<int U, int NCTA>
__global__ __launch_bounds__(256) void lstm_k(
    const float* __restrict__ Um,   // [U][4U]
    const float* __restrict__ xg,   // [4096][4U], row m = b*T + t
    float* __restrict__ xout)       // [4096][U]
{
    constexpr int N4 = 4 * U;
    constexpr int KC = (U + 7) / 8;

    extern __shared__ float sm[];
    float* h_s = sm;                      // [U][16]  (k-major, batch inner)
    float* red = sm + U * 16;             // [16][256] : red[b*256 + tid]
    float* gat = red + 16 * 256;          // [32][16]

    const int tid  = threadIdx.x;
    const int lane = tid & 31;
    const int kc   = tid >> 5;
    const int g    = lane >> 3;           // gate 0..3 (i,f,c,o)
    const int ul   = lane & 7;
    const int u    = blockIdx.x * 8 + ul;
    const bool uok = (u < U);
    const int j    = g * U + u;
    const int k0   = kc * KC;
    const int k1   = (k0 + KC < U) ? (k0 + KC) : U;

    // zero state
    for (int idx = blockIdx.x * 256 + tid; idx < 16 * U; idx += NCTA * 256) {
        g_h[0][idx] = 0.f; g_h[1][idx] = 0.f; g_c[idx] = 0.f;
    }
    unsigned gen = 1;
    grid_sync(gen * NCTA);

    for (int t = 0; t < T_SEQ; ++t) {
        const float* hg = g_h[t & 1];
        float* hn = g_h[(t & 1) ^ 1];

        // stage h into shared (L2 read: cross-CTA data, bypass L1)
        for (int idx = tid; idx < U * 16; idx += 256) h_s[idx] = __ldcg(&hg[idx]);
        __syncthreads();

        float acc[16];
#pragma unroll
        for (int b = 0; b < 16; b++) acc[b] = 0.f;

        if (uok) {
            const float* Up = Um + j;
#pragma unroll 8
            for (int k = k0; k < k1; ++k) {
                float uv = __ldg(&Up[(size_t)k * N4]);
                const float4* hv = (const float4*)(h_s + (k << 4));
                float4 ha = hv[0], hb = hv[1], hc = hv[2], hd = hv[3];
                acc[0]  = fmaf(ha.x, uv, acc[0]);
                acc[1]  = fmaf(ha.y, uv, acc[1]);
                acc[2]  = fmaf(ha.z, uv, acc[2]);
                acc[3]  = fmaf(ha.w, uv, acc[3]);
                acc[4]  = fmaf(hb.x, uv, acc[4]);
                acc[5]  = fmaf(hb.y, uv, acc[5]);
                acc[6]  = fmaf(hb.z, uv, acc[6]);
                acc[7]  = fmaf(hb.w, uv, acc[7]);
                acc[8]  = fmaf(hc.x, uv, acc[8]);
                acc[9]  = fmaf(hc.y, uv, acc[9]);
                acc[10] = fmaf(hc.z, uv, acc[10]);
                acc[11] = fmaf(hc.w, uv, acc[11]);
                acc[12] = fmaf(hd.x, uv, acc[12]);
                acc[13] = fmaf(hd.y, uv, acc[13]);
                acc[14] = fmaf(hd.z, uv, acc[14]);
                acc[15] = fmaf(hd.w, uv, acc[15]);
            }
        }
#pragma unroll
        for (int b = 0; b < 16; b++) red[b * 256 + tid] = acc[b];
        __syncthreads();

        // reduce across the 8 k-chunks: 512 outputs (32 cols x 16 batches)
#pragma unroll
        for (int o = tid; o < 512; o += 256) {
            int c = o & 31, b = o >> 5;
            float s = 0.f;
#pragma unroll
            for (int q = 0; q < 8; q++) s += red[b * 256 + q * 32 + c];
            int gg = c >> 3;
            int uu = blockIdx.x * 8 + (c & 7);
            if (uu < U) {
                s += __ldg(&xg[((size_t)b * T_SEQ + t) * N4 + (size_t)gg * U + uu]);
                gat[c * 16 + b] = s;
            }
        }
        __syncthreads();

        // gate math + state update (128 (b,u) pairs per CTA)
        if (tid < 128) {
            int b = tid & 15, w = tid >> 4;
            int uu = blockIdx.x * 8 + w;
            if (uu < U) {
                float iv = gat[(0 * 8 + w) * 16 + b];
                float fv = gat[(1 * 8 + w) * 16 + b];
                float cg = gat[(2 * 8 + w) * 16 + b];
                float ov = gat[(3 * 8 + w) * 16 + b];
                iv = 1.f / (1.f + __expf(-iv));
                fv = 1.f / (1.f + __expf(-fv));
                ov = 1.f / (1.f + __expf(-ov));
                cg = tanhf(cg);
                float cold = g_c[uu * 16 + b];
                float cn = fv * cold + iv * cg;
                float hv = ov * tanhf(cn);
                g_c[uu * 16 + b] = cn;
                hn[uu * 16 + b] = hv;
                xout[((size_t)b * T_SEQ + t) * U + uu] = hv;
            }
        }
        gen++;
        grid_sync(gen * NCTA);
    }
}

// ---------------- in-place row softmax over N columns ----------------
__global__ __launch_bounds__(256) void softmax_k(float* __restrict__ out, int N) {
    int m = blockIdx.x;
    float* row = out + (size_t)m * N;
    __shared__ float s1[8];
    __shared__ float sb;
    int tid = threadIdx.x, wid = tid >> 5, ln = tid & 31;

    float lm = -3.4e38f;
    for (int i = tid; i < N; i += 256) lm = fmaxf(lm, row[i]);
#pragma unroll
    for (int o = 16; o; o >>= 1) lm = fmaxf(lm, __shfl_xor_sync(0xffffffffu, lm, o));
    if (!ln) s1[wid] = lm;
    __syncthreads();
    if (tid == 0) {
        float v = s1[0];
#pragma unroll
        for (int q = 1; q < 8; q++) v = fmaxf(v, s1[q]);
        sb = v;
    }
    __syncthreads();
    float mx = sb;
    __syncthreads();

    float ls = 0.f;
    for (int i = tid; i < N; i += 256) ls += __expf(row[i] - mx);
#pragma unroll
    for (int o = 16; o; o >>= 1) ls += __shfl_xor_sync(0xffffffffu, ls, o);
    if (!ln) s1[wid] = ls;
    __syncthreads();
    if (tid == 0) {
        float v = 0.f;
#pragma unroll
        for (int q = 0; q < 8; q++) v += s1[q];
        sb = 1.f / v;
    }
    __syncthreads();
    float inv = sb;

    for (int i = tid; i < N; i += 256) row[i] = __expf(row[i] - mx) * inv;
}

// ---------------- launch ----------------
extern "C" void kernel_launch(void* const* d_in, const int* in_sizes, int n_in,
                              void* d_out, int out_size)
{
    (void)in_sizes; (void)n_in; (void)out_size;
    const int*   tok = (const int*)d_in[0];
    const float* emb = (const float*)d_in[1];
    const float* W0  = (const float*)d_in[2];
    const float* U0  = (const float*)d_in[3];
    const float* b0  = (const float*)d_in[4];
    const float* W1  = (const float*)d_in[5];
    const float* U1  = (const float*)d_in[6];
    const float* b1  = (const float*)d_in[7];
    const float* W2  = (const float*)d_in[8];
    const float* U2  = (const float*)d_in[9];
    const float* b2  = (const float*)d_in[10];
    float* out = (float*)d_out;

    float *xa, *xb, *xg;
    cudaGetSymbolAddress((void**)&xa, g_xa);
    cudaGetSymbolAddress((void**)&xb, g_xb);
    cudaGetSymbolAddress((void**)&xg, g_xg);

    const int SMEM_BIG   = (NHID * 16 + 256 * 16 + 32 * 16) * 4;   // 92032
    const int SMEM_SMALL = (NINP * 16 + 256 * 16 + 32 * 16) * 4;   // 44032
    cudaFuncSetAttribute(lstm_k<NHID, 144>, cudaFuncAttributeMaxDynamicSharedMemorySize, SMEM_BIG);
    cudaFuncSetAttribute(lstm_k<NINP, 50>,  cudaFuncAttributeMaxDynamicSharedMemorySize, SMEM_SMALL);

    // 1) embedding
    embed_k<<<M_TOK, 128>>>(tok, emb, xa);

    // 2) layer 0: xg = x @ W0 + b0 ; recurrence
    mma_gemm_k<false, true><<<dim3((4 * NHID + 127) / 128, M_TOK / 128), 256>>>(
        xa, W0, b0, xg, M_TOK, 4 * NHID, NINP);
    bar_reset_k<<<1, 1>>>();
    lstm_k<NHID, 144><<<144, 256, SMEM_BIG>>>(U0, xg, xb);

    // 3) layer 1
    mma_gemm_k<false, true><<<dim3((4 * NHID + 127) / 128, M_TOK / 128), 256>>>(
        xb, W1, b1, xg, M_TOK, 4 * NHID, NHID);
    bar_reset_k<<<1, 1>>>();
    lstm_k<NHID, 144><<<144, 256, SMEM_BIG>>>(U1, xg, xa);

    // 4) layer 2 (units = 400)
    mma_gemm_k<false, true><<<dim3((4 * NINP + 127) / 128, M_TOK / 128), 256>>>(
        xa, W2, b2, xg, M_TOK, 4 * NINP, NHID);
    bar_reset_k<<<1, 1>>>();
    lstm_k<NINP, 50><<<50, 256, SMEM_SMALL>>>(U2, xg, xb);

    // 5) tied decode: logits = x @ emb^T   -> write straight into d_out
    mma_gemm_k<true, false><<<dim3((VOCABP1 + 127) / 128, M_TOK / 128), 256>>>(
        xb, emb, nullptr, out, M_TOK, VOCABP1, NINP);

    // 6) in-place softmax
    softmax_k<<<M_TOK, 256>>>(out, VOCABP1);
}

// round 6
// speedup vs baseline: 1.2891x; 1.0064x over previous
#include <cuda_runtime.h>
#include <cstdint>
#include <math.h>

#define T_SEQ   256
#define BATCH   16
#define NINP    400
#define NHID    1150
#define VOCABP1 33279
#define M_TOK   (BATCH * T_SEQ)   // 4096

// ---------------- scratch (static device globals; no allocation) ----------------
__device__ float g_xa[(size_t)M_TOK * NHID];          // ping  (max width 1150)
__device__ float g_xb[(size_t)M_TOK * NHID];          // pong
__device__ float g_xg[(size_t)M_TOK * 4 * NHID];      // gate preactivations (max 4096x4600)
__device__ float g_h[2][BATCH * NHID];                // recurrent h ping-pong, layout [u][b]
__device__ float g_c[BATCH * NHID];                   // cell state, layout [u][b]
__device__ unsigned g_bar;                            // grid barrier counter

// ---------------- grid barrier ----------------
__device__ __forceinline__ void grid_sync(unsigned target) {
    __syncthreads();
    if (threadIdx.x == 0) {
        __threadfence();
        atomicAdd(&g_bar, 1u);
        while (*(volatile unsigned*)&g_bar < target) { __nanosleep(40); }
        __threadfence();
    }
    __syncthreads();
}

__global__ void bar_reset_k() { g_bar = 0u; }

// ---------------- embedding gather ----------------
__global__ void embed_k(const int* __restrict__ tok, const float* __restrict__ emb,
                        float* __restrict__ x0) {
    int m = blockIdx.x;                  // m = b*T + t
    int t = tok[m];
    const float4* src = (const float4*)(emb + (size_t)t * NINP);
    float4* dst = (float4*)(x0 + (size_t)m * NINP);
    for (int i = threadIdx.x; i < NINP / 4; i += blockDim.x) dst[i] = src[i];
}

// ---------------- tf32 helpers ----------------
__device__ __forceinline__ float tf32f(float x) {
    uint32_t u;
    asm("cvt.rna.tf32.f32 %0, %1;" : "=r"(u) : "f"(x));
    return __uint_as_float(u);
}

#define MMA_TF32(d, a, b)                                                     \
    asm volatile("mma.sync.aligned.m16n8k8.row.col.f32.tf32.tf32.f32 "        \
                 "{%0,%1,%2,%3}, {%4,%5,%6,%7}, {%8,%9}, {%0,%1,%2,%3};"      \
                 : "+f"(d[0]), "+f"(d[1]), "+f"(d[2]), "+f"(d[3])             \
                 : "r"(a[0]), "r"(a[1]), "r"(a[2]), "r"(a[3]),                \
                   "r"(b[0]), "r"(b[1]))

// alignment-safe 4-float row load into v[0..3]; p must be 4B aligned (always true).
// in-bounds for all 4 elements is the caller's responsibility.
__device__ __forceinline__ void ld4_safe(const float* p, float* v) {
    uintptr_t a = (uintptr_t)p;
    if ((a & 15u) == 0) {
        float4 t = *(const float4*)p;
        v[0] = t.x; v[1] = t.y; v[2] = t.z; v[3] = t.w;
    } else if ((a & 7u) == 0) {
        float2 t0 = *(const float2*)p;
        float2 t1 = *(const float2*)(p + 2);
        v[0] = t0.x; v[1] = t0.y; v[2] = t1.x; v[3] = t1.y;
    } else {
        v[0] = p[0]; v[1] = p[1]; v[2] = p[2]; v[3] = p[3];
    }
}

// ---------------- TF32 tensor-core GEMM: C[M,N] = A[M,K] * B (+bias) -------------
// BTRANS=false: B is [K,N] row-major.  BTRANS=true: B is [N,K] row-major (C = A*B^T).
// M must be a multiple of 128 (always 4096 here). N,K arbitrary.
// CTA tile 128x128, BK=16. 8 warps, each computes a 64x32 warp tile with
// m16n8k8 tf32 MMA. Global loads register-prefetched one k-tile ahead.
template<bool BTRANS, bool BIAS>
__global__ __launch_bounds__(256) void mma_gemm_k(
    const float* __restrict__ A, const float* __restrict__ B,
    const float* __restrict__ bias, float* __restrict__ C,
    int M, int N, int K)
{
    __shared__ float As[16][136];   // [k][m], pad 136 -> conflict-free frag loads
    __shared__ float Bs[16][136];   // [k][n]

    const int tid  = threadIdx.x;
    const int bm   = blockIdx.y * 128;
    const int bn   = blockIdx.x * 128;
    const int wid  = tid >> 5;
    const int lane = tid & 31;
    const int wm   = (wid >> 2) * 64;     // 0 or 64
    const int wn   = (wid & 3) * 32;      // 0,32,64,96
    const int gID  = lane >> 2;           // 0..7
    const int tg   = lane & 3;            // 0..3

    // global-load thread mappings
    const int arow = tid >> 2;            // 0..63  (rows arow, arow+64)
    const int acol = (tid & 3) * 4;       // 0,4,8,12
    const int bkr  = tid >> 5;            // 0..7   (rows bkr, bkr+8)      [!BTRANS]
    const int bnc  = (tid & 31) * 4;      // 0..124                        [!BTRANS]
    const int tnr  = tid >> 2;            // 0..63  (n rows tnr, tnr+64)   [BTRANS]
    const int tkc  = (tid & 3) * 4;       // 0,4,8,12                      [BTRANS]

    float acc[4][4][4];
#pragma unroll
    for (int mf = 0; mf < 4; mf++)
#pragma unroll
        for (int nf = 0; nf < 4; nf++)
#pragma unroll
            for (int i = 0; i < 4; i++) acc[mf][nf][i] = 0.f;

    float ar[8], br[8];

    auto loadg = [&](int k0) {
        // ---- A: [M,K] row-major, 128x16 tile ----
#pragma unroll
        for (int j = 0; j < 2; j++) {
            int r = arow + j * 64;
            const float* p = A + (size_t)(bm + r) * K + k0 + acol;
            if (k0 + acol + 3 < K) {
                ld4_safe(p, &ar[j * 4]);
            } else {
#pragma unroll
                for (int i = 0; i < 4; i++)
                    ar[j * 4 + i] = (k0 + acol + i < K) ? p[i] : 0.f;
            }
        }
        // ---- B ----
        if (BTRANS) {
#pragma unroll
            for (int j = 0; j < 2; j++) {
                int gn = bn + tnr + j * 64;
                int gk = k0 + tkc;
                const float* p = B + (size_t)gn * K + gk;
                if (gn < N && gk + 3 < K) {
                    ld4_safe(p, &br[j * 4]);
                } else {
#pragma unroll
                    for (int i = 0; i < 4; i++)
                        br[j * 4 + i] = (gn < N && gk + i < K) ? p[i] : 0.f;
                }
            }
        } else {
#pragma unroll
            for (int j = 0; j < 2; j++) {
                int gk = k0 + bkr + j * 8;
                int gn = bn + bnc;
                const float* p = B + (size_t)gk * N + gn;
                if (gk < K && gn + 3 < N) {
                    ld4_safe(p, &br[j * 4]);
                } else {
#pragma unroll
                    for (int i = 0; i < 4; i++)
                        br[j * 4 + i] = (gk < K && gn + i < N) ? p[i] : 0.f;
                }
            }
        }
    };

    auto stores = [&]() {
#pragma unroll
        for (int j = 0; j < 2; j++)
#pragma unroll
            for (int i = 0; i < 4; i++)
                As[acol + i][arow + j * 64] = tf32f(ar[j * 4 + i]);
        if (BTRANS) {
#pragma unroll
            for (int j = 0; j < 2; j++)
#pragma unroll
                for (int i = 0; i < 4; i++)
                    Bs[tkc + i][tnr + j * 64] = tf32f(br[j * 4 + i]);
        } else {
#pragma unroll
            for (int j = 0; j < 2; j++)
#pragma unroll
                for (int i = 0; i < 4; i++)
                    Bs[bkr + j * 8][bnc + i] = tf32f(br[j * 4 + i]);
        }
    };

    const int nkt = (K + 15) / 16;
    loadg(0);
    stores();
    __syncthreads();

    for (int kt = 0; kt < nkt; kt++) {
        const bool more = (kt + 1 < nkt);
        if (more) loadg((kt + 1) * 16);

#pragma unroll
        for (int kk = 0; kk < 16; kk += 8) {
            uint32_t af[4][4], bf[4][2];
#pragma unroll
            for (int mf = 0; mf < 4; mf++) {
                int m = wm + mf * 16 + gID;
                af[mf][0] = __float_as_uint(As[kk + tg][m]);
                af[mf][1] = __float_as_uint(As[kk + tg][m + 8]);
                af[mf][2] = __float_as_uint(As[kk + 4 + tg][m]);
                af[mf][3] = __float_as_uint(As[kk + 4 + tg][m + 8]);
            }
#pragma unroll
            for (int nf = 0; nf < 4; nf++) {
                int n = wn + nf * 8 + gID;
                bf[nf][0] = __float_as_uint(Bs[kk + tg][n]);
                bf[nf][1] = __float_as_uint(Bs[kk + 4 + tg][n]);
            }
#pragma unroll
            for (int mf = 0; mf < 4; mf++)
#pragma unroll
                for (int nf = 0; nf < 4; nf++)
                    MMA_TF32(acc[mf][nf], af[mf], bf[nf]);
        }
        __syncthreads();
        if (more) {
            stores();
            __syncthreads();
        }
    }

    // epilogue
#pragma unroll
    for (int mf = 0; mf < 4; mf++) {
        int r0 = bm + wm + mf * 16 + gID;
#pragma unroll
        for (int nf = 0; nf < 4; nf++) {
            int c0 = bn + wn + nf * 8 + tg * 2;
            float b0v = 0.f, b1v = 0.f;
            if (BIAS) {
                if (c0 < N)     b0v = bias[c0];
                if (c0 + 1 < N) b1v = bias[c0 + 1];
            }
            if (c0 < N) {
                C[(size_t)r0 * N + c0]       = acc[mf][nf][0] + b0v;
                C[(size_t)(r0 + 8) * N + c0] = acc[mf][nf][2] + b0v;
            }
            if (c0 + 1 < N) {
                C[(size_t)r0 * N + c0 + 1]       = acc[mf][nf][1] + b1v;
                C[(size_t)(r0 + 8) * N + c0 + 1] = acc[mf][nf][3] + b1v;
            }
        }
    }
}

// ---------------- persistent LSTM recurrence (one layer) ----------------
// grid = NCTA, block = 256. Each CTA owns 8 units (x4 gates = 32 dot columns).
// 256 threads = 32 column-lanes x 8 k-chunks. One grid barrier per timestep.
template<int U, int NCTA>
__global__ __launch_bounds__(256) void lstm_k(
    const float* __restrict__ Um,   // [U][4U]
    const float* __restrict__ xg,   // [4096][4U], row m = b*T + t
    float* __restrict__ xout)       // [4096][U]
{
    constexpr int N4 = 4 * U;
    constexpr int KC = (U + 7) / 8;

    extern __shared__ float sm[];
    float* h_s = sm;                      // [U][16]  (k-major, batch inner)
    float* red = sm + U * 16;             // [16][256] : red[b*256 + tid]
    float* gat = red + 16 * 256;          // [32][16]

    const int tid  = threadIdx.x;
    const int lane = tid & 31;
    const int kc   = tid >> 5;
    const int g    = lane >> 3;           // gate 0..3 (i,f,c,o)
    const int ul   = lane & 7;
    const int u    = blockIdx.x * 8 + ul;
    const bool uok = (u < U);
    const int j    = g * U + u;
    const int k0   = kc * KC;
    const int k1   = (k0 + KC < U) ? (k0 + KC) : U;

    // zero state
    for (int idx = blockIdx.x * 256 + tid; idx < 16 * U; idx += NCTA * 256) {
        g_h[0][idx] = 0.f; g_h[1][idx] = 0.f; g_c[idx] = 0.f;
    }
    unsigned gen = 1;
    grid_sync(gen * NCTA);

    for (int t = 0; t < T_SEQ; ++t) {
        const float* hg = g_h[t & 1];
        float* hn = g_h[(t & 1) ^ 1];

        // stage h into shared (L2 read: cross-CTA data, bypass L1)
        for (int idx = tid; idx < U * 16; idx += 256) h_s[idx] = __ldcg(&hg[idx]);
        __syncthreads();

        float acc[16];
#pragma unroll
        for (int b = 0; b < 16; b++) acc[b] = 0.f;

        if (uok) {
            const float* Up = Um + j;
#pragma unroll 8
            for (int k = k0; k < k1; ++k) {
                float uv = __ldg(&Up[(size_t)k * N4]);
                const float4* hv = (const float4*)(h_s + (k << 4));
                float4 ha = hv[0], hb = hv[1], hc = hv[2], hd = hv[3];
                acc[0]  = fmaf(ha.x, uv, acc[0]);
                acc[1]  = fmaf(ha.y, uv, acc[1]);
                acc[2]  = fmaf(ha.z, uv, acc[2]);
                acc[3]  = fmaf(ha.w, uv, acc[3]);
                acc[4]  = fmaf(hb.x, uv, acc[4]);
                acc[5]  = fmaf(hb.y, uv, acc[5]);
                acc[6]  = fmaf(hb.z, uv, acc[6]);
                acc[7]  = fmaf(hb.w, uv, acc[7]);
                acc[8]  = fmaf(hc.x, uv, acc[8]);
                acc[9]  = fmaf(hc.y, uv, acc[9]);
                acc[10] = fmaf(hc.z, uv, acc[10]);
                acc[11] = fmaf(hc.w, uv, acc[11]);
                acc[12] = fmaf(hd.x, uv, acc[12]);
                acc[13] = fmaf(hd.y, uv, acc[13]);
                acc[14] = fmaf(hd.z, uv, acc[14]);
                acc[15] = fmaf(hd.w, uv, acc[15]);
            }
        }
#pragma unroll
        for (int b = 0; b < 16; b++) red[b * 256 + tid] = acc[b];
        __syncthreads();

        // reduce across the 8 k-chunks: 512 outputs (32 cols x 16 batches)
#pragma unroll
        for (int o = tid; o < 512; o += 256) {
            int c = o & 31, b = o >> 5;
            float s = 0.f;
#pragma unroll
            for (int q = 0; q < 8; q++) s += red[b * 256 + q * 32 + c];
            int gg = c >> 3;
            int uu = blockIdx.x * 8 + (c & 7);
            if (uu < U) {
                s += __ldg(&xg[((size_t)b * T_SEQ + t) * N4 + (size_t)gg * U + uu]);
                gat[c * 16 + b] = s;
            }
        }
        __syncthreads();

        // gate math + state update (128 (b,u) pairs per CTA)
        if (tid < 128) {
            int b = tid & 15, w = tid >> 4;
            int uu = blockIdx.x * 8 + w;
            if (uu < U) {
                float iv = gat[(0 * 8 + w) * 16 + b];
                float fv = gat[(1 * 8 + w) * 16 + b];
                float cg = gat[(2 * 8 + w) * 16 + b];
                float ov = gat[(3 * 8 + w) * 16 + b];
                iv = 1.f / (1.f + __expf(-iv));
                fv = 1.f / (1.f + __expf(-fv));
                ov = 1.f / (1.f + __expf(-ov));
                cg = tanhf(cg);
                float cold = g_c[uu * 16 + b];
                float cn = fv * cold + iv * cg;
                float hv = ov * tanhf(cn);
                g_c[uu * 16 + b] = cn;
                hn[uu * 16 + b] = hv;
                xout[((size_t)b * T_SEQ + t) * U + uu] = hv;
            }
        }
        gen++;
        grid_sync(gen * NCTA);
    }
}

// ---------------- in-place row softmax over N columns ----------------
__global__ __launch_bounds__(256) void softmax_k(float* __restrict__ out, int N) {
    int m = blockIdx.x;
    float* row = out + (size_t)m * N;
    __shared__ float s1[8];
    __shared__ float sb;
    int tid = threadIdx.x, wid = tid >> 5, ln = tid & 31;

    float lm = -3.4e38f;
    for (int i = tid; i < N; i += 256) lm = fmaxf(lm, row[i]);
#pragma unroll
    for (int o = 16; o; o >>= 1) lm = fmaxf(lm, __shfl_xor_sync(0xffffffffu, lm, o));
    if (!ln) s1[wid] = lm;
    __syncthreads();
    if (tid == 0) {
        float v = s1[0];
#pragma unroll
        for (int q = 1; q < 8; q++) v = fmaxf(v, s1[q]);
        sb = v;
    }
    __syncthreads();
    float mx = sb;
    __syncthreads();

    float ls = 0.f;
    for (int i = tid; i < N; i += 256) ls += __expf(row[i] - mx);
#pragma unroll
    for (int o = 16; o; o >>= 1) ls += __shfl_xor_sync(0xffffffffu, ls, o);
    if (!ln) s1[wid] = ls;
    __syncthreads();
    if (tid == 0) {
        float v = 0.f;
#pragma unroll
        for (int q = 0; q < 8; q++) v += s1[q];
        sb = 1.f / v;
    }
    __syncthreads();
    float inv = sb;

    for (int i = tid; i < N; i += 256) row[i] = __expf(row[i] - mx) * inv;
}

// ---------------- launch ----------------
extern "C" void kernel_launch(void* const* d_in, const int* in_sizes, int n_in,
                              void* d_out, int out_size)
{
    (void)in_sizes; (void)n_in; (void)out_size;
    const int*   tok = (const int*)d_in[0];
    const float* emb = (const float*)d_in[1];
    const float* W0  = (const float*)d_in[2];
    const float* U0  = (const float*)d_in[3];
    const float* b0  = (const float*)d_in[4];
    const float* W1  = (const float*)d_in[5];
    const float* U1  = (const float*)d_in[6];
    const float* b1  = (const float*)d_in[7];
    const float* W2  = (const float*)d_in[8];
    const float* U2  = (const float*)d_in[9];
    const float* b2  = (const float*)d_in[10];
    float* out = (float*)d_out;

    float *xa, *xb, *xg;
    cudaGetSymbolAddress((void**)&xa, g_xa);
    cudaGetSymbolAddress((void**)&xb, g_xb);
    cudaGetSymbolAddress((void**)&xg, g_xg);

    const int SMEM_BIG   = (NHID * 16 + 256 * 16 + 32 * 16) * 4;   // 92032
    const int SMEM_SMALL = (NINP * 16 + 256 * 16 + 32 * 16) * 4;   // 44032
    cudaFuncSetAttribute(lstm_k<NHID, 144>, cudaFuncAttributeMaxDynamicSharedMemorySize, SMEM_BIG);
    cudaFuncSetAttribute(lstm_k<NINP, 50>,  cudaFuncAttributeMaxDynamicSharedMemorySize, SMEM_SMALL);

    // 1) embedding
    embed_k<<<M_TOK, 128>>>(tok, emb, xa);

    // 2) layer 0: xg = x @ W0 + b0 ; recurrence
    mma_gemm_k<false, true><<<dim3((4 * NHID + 127) / 128, M_TOK / 128), 256>>>(
        xa, W0, b0, xg, M_TOK, 4 * NHID, NINP);
    bar_reset_k<<<1, 1>>>();
    lstm_k<NHID, 144><<<144, 256, SMEM_BIG>>>(U0, xg, xb);

    // 3) layer 1
    mma_gemm_k<false, true><<<dim3((4 * NHID + 127) / 128, M_TOK / 128), 256>>>(
        xb, W1, b1, xg, M_TOK, 4 * NHID, NHID);
    bar_reset_k<<<1, 1>>>();
    lstm_k<NHID, 144><<<144, 256, SMEM_BIG>>>(U1, xg, xa);

    // 4) layer 2 (units = 400)
    mma_gemm_k<false, true><<<dim3((4 * NINP + 127) / 128, M_TOK / 128), 256>>>(
        xa, W2, b2, xg, M_TOK, 4 * NINP, NHID);
    bar_reset_k<<<1, 1>>>();
    lstm_k<NINP, 50><<<50, 256, SMEM_SMALL>>>(U2, xg, xb);

    // 5) tied decode: logits = x @ emb^T   -> write straight into d_out
    mma_gemm_k<true, false><<<dim3((VOCABP1 + 127) / 128, M_TOK / 128), 256>>>(
        xb, emb, nullptr, out, M_TOK, VOCABP1, NINP);

    // 6) in-place softmax
    softmax_k<<<M_TOK, 256>>>(out, VOCABP1);
}

// round 7
// speedup vs baseline: 2.0241x; 1.5701x over previous
#include <cuda_runtime.h>
#include <cstdint>
#include <math.h>

#define T_SEQ   256
#define BATCH   16
#define NINP    400
#define NHID    1150
#define VOCABP1 33279
#define M_TOK   (BATCH * T_SEQ)   // 4096

// ---------------- scratch (static device globals; no allocation) ----------------
__device__ float g_xa[(size_t)M_TOK * NHID];          // ping  (max width 1150)
__device__ float g_xb[(size_t)M_TOK * NHID];          // pong
__device__ float g_xg[(size_t)M_TOK * 4 * NHID];      // gate preactivations (max 4096x4600)
__device__ float g_h[2][BATCH * NHID];                // recurrent h ping-pong, layout [u][b]
__device__ float g_c[BATCH * NHID];                   // cell state, layout [u][b]
__device__ unsigned g_bar;                            // grid barrier counter

// ---------------- grid barrier ----------------
__device__ __forceinline__ void grid_sync(unsigned target) {
    __syncthreads();
    if (threadIdx.x == 0) {
        __threadfence();
        atomicAdd(&g_bar, 1u);
        while (*(volatile unsigned*)&g_bar < target) { __nanosleep(40); }
        __threadfence();
    }
    __syncthreads();
}

__global__ void bar_reset_k() { g_bar = 0u; }

// ---------------- embedding gather ----------------
__global__ void embed_k(const int* __restrict__ tok, const float* __restrict__ emb,
                        float* __restrict__ x0) {
    int m = blockIdx.x;                  // m = b*T + t
    int t = tok[m];
    const float4* src = (const float4*)(emb + (size_t)t * NINP);
    float4* dst = (float4*)(x0 + (size_t)m * NINP);
    for (int i = threadIdx.x; i < NINP / 4; i += blockDim.x) dst[i] = src[i];
}

// ---------------- packed f32x2 helpers (Blackwell) ----------------
__device__ __forceinline__ unsigned long long dup2(float x) {
    unsigned long long d;
    asm("mov.b64 %0, {%1, %1};" : "=l"(d) : "f"(x));
    return d;
}
__device__ __forceinline__ void fma2(unsigned long long& d,
                                     unsigned long long a, unsigned long long b) {
    asm("fma.rn.f32x2 %0, %1, %2, %0;" : "+l"(d) : "l"(a), "l"(b));
}
__device__ __forceinline__ void unpack2(unsigned long long v, float& lo, float& hi) {
    asm("mov.b64 {%0, %1}, %2;" : "=f"(lo), "=f"(hi) : "l"(v));
}

// ---------------- tf32 helpers ----------------
__device__ __forceinline__ float tf32f(float x) {
    uint32_t u;
    asm("cvt.rna.tf32.f32 %0, %1;" : "=r"(u) : "f"(x));
    return __uint_as_float(u);
}

#define MMA_TF32(d, a, b)                                                     \
    asm volatile("mma.sync.aligned.m16n8k8.row.col.f32.tf32.tf32.f32 "        \
                 "{%0,%1,%2,%3}, {%4,%5,%6,%7}, {%8,%9}, {%0,%1,%2,%3};"      \
                 : "+f"(d[0]), "+f"(d[1]), "+f"(d[2]), "+f"(d[3])             \
                 : "r"(a[0]), "r"(a[1]), "r"(a[2]), "r"(a[3]),                \
                   "r"(b[0]), "r"(b[1]))

// alignment-safe 4-float row load into v[0..3]; p must be 4B aligned.
__device__ __forceinline__ void ld4_safe(const float* p, float* v) {
    uintptr_t a = (uintptr_t)p;
    if ((a & 15u) == 0) {
        float4 t = *(const float4*)p;
        v[0] = t.x; v[1] = t.y; v[2] = t.z; v[3] = t.w;
    } else if ((a & 7u) == 0) {
        float2 t0 = *(const float2*)p;
        float2 t1 = *(const float2*)(p + 2);
        v[0] = t0.x; v[1] = t0.y; v[2] = t1.x; v[3] = t1.y;
    } else {
        v[0] = p[0]; v[1] = p[1]; v[2] = p[2]; v[3] = p[3];
    }
}

// ---------------- TF32 tensor-core GEMM (unchanged from R6) ----------------
template<bool BTRANS, bool BIAS>
__global__ __launch_bounds__(256) void mma_gemm_k(
    const float* __restrict__ A, const float* __restrict__ B,
    const float* __restrict__ bias, float* __restrict__ C,
    int M, int N, int K)
{
    __shared__ float As[16][136];
    __shared__ float Bs[16][136];

    const int tid  = threadIdx.x;
    const int bm   = blockIdx.y * 128;
    const int bn   = blockIdx.x * 128;
    const int wid  = tid >> 5;
    const int lane = tid & 31;
    const int wm   = (wid >> 2) * 64;
    const int wn   = (wid & 3) * 32;
    const int gID  = lane >> 2;
    const int tg   = lane & 3;

    const int arow = tid >> 2;
    const int acol = (tid & 3) * 4;
    const int bkr  = tid >> 5;
    const int bnc  = (tid & 31) * 4;
    const int tnr  = tid >> 2;
    const int tkc  = (tid & 3) * 4;

    float acc[4][4][4];
#pragma unroll
    for (int mf = 0; mf < 4; mf++)
#pragma unroll
        for (int nf = 0; nf < 4; nf++)
#pragma unroll
            for (int i = 0; i < 4; i++) acc[mf][nf][i] = 0.f;

    float ar[8], br[8];

    auto loadg = [&](int k0) {
#pragma unroll
        for (int j = 0; j < 2; j++) {
            int r = arow + j * 64;
            const float* p = A + (size_t)(bm + r) * K + k0 + acol;
            if (k0 + acol + 3 < K) {
                ld4_safe(p, &ar[j * 4]);
            } else {
#pragma unroll
                for (int i = 0; i < 4; i++)
                    ar[j * 4 + i] = (k0 + acol + i < K) ? p[i] : 0.f;
            }
        }
        if (BTRANS) {
#pragma unroll
            for (int j = 0; j < 2; j++) {
                int gn = bn + tnr + j * 64;
                int gk = k0 + tkc;
                const float* p = B + (size_t)gn * K + gk;
                if (gn < N && gk + 3 < K) {
                    ld4_safe(p, &br[j * 4]);
                } else {
#pragma unroll
                    for (int i = 0; i < 4; i++)
                        br[j * 4 + i] = (gn < N && gk + i < K) ? p[i] : 0.f;
                }
            }
        } else {
#pragma unroll
            for (int j = 0; j < 2; j++) {
                int gk = k0 + bkr + j * 8;
                int gn = bn + bnc;
                const float* p = B + (size_t)gk * N + gn;
                if (gk < K && gn + 3 < N) {
                    ld4_safe(p, &br[j * 4]);
                } else {
#pragma unroll
                    for (int i = 0; i < 4; i++)
                        br[j * 4 + i] = (gk < K && gn + i < N) ? p[i] : 0.f;
                }
            }
        }
    };

    auto stores = [&]() {
#pragma unroll
        for (int j = 0; j < 2; j++)
#pragma unroll
            for (int i = 0; i < 4; i++)
                As[acol + i][arow + j * 64] = tf32f(ar[j * 4 + i]);
        if (BTRANS) {
#pragma unroll
            for (int j = 0; j < 2; j++)
#pragma unroll
                for (int i = 0; i < 4; i++)
                    Bs[tkc + i][tnr + j * 64] = tf32f(br[j * 4 + i]);
        } else {
#pragma unroll
            for (int j = 0; j < 2; j++)
#pragma unroll
                for (int i = 0; i < 4; i++)
                    Bs[bkr + j * 8][bnc + i] = tf32f(br[j * 4 + i]);
        }
    };

    const int nkt = (K + 15) / 16;
    loadg(0);
    stores();
    __syncthreads();

    for (int kt = 0; kt < nkt; kt++) {
        const bool more = (kt + 1 < nkt);
        if (more) loadg((kt + 1) * 16);

#pragma unroll
        for (int kk = 0; kk < 16; kk += 8) {
            uint32_t af[4][4], bf[4][2];
#pragma unroll
            for (int mf = 0; mf < 4; mf++) {
                int m = wm + mf * 16 + gID;
                af[mf][0] = __float_as_uint(As[kk + tg][m]);
                af[mf][1] = __float_as_uint(As[kk + tg][m + 8]);
                af[mf][2] = __float_as_uint(As[kk + 4 + tg][m]);
                af[mf][3] = __float_as_uint(As[kk + 4 + tg][m + 8]);
            }
#pragma unroll
            for (int nf = 0; nf < 4; nf++) {
                int n = wn + nf * 8 + gID;
                bf[nf][0] = __float_as_uint(Bs[kk + tg][n]);
                bf[nf][1] = __float_as_uint(Bs[kk + 4 + tg][n]);
            }
#pragma unroll
            for (int mf = 0; mf < 4; mf++)
#pragma unroll
                for (int nf = 0; nf < 4; nf++)
                    MMA_TF32(acc[mf][nf], af[mf], bf[nf]);
        }
        __syncthreads();
        if (more) {
            stores();
            __syncthreads();
        }
    }

#pragma unroll
    for (int mf = 0; mf < 4; mf++) {
        int r0 = bm + wm + mf * 16 + gID;
#pragma unroll
        for (int nf = 0; nf < 4; nf++) {
            int c0 = bn + wn + nf * 8 + tg * 2;
            float b0v = 0.f, b1v = 0.f;
            if (BIAS) {
                if (c0 < N)     b0v = bias[c0];
                if (c0 + 1 < N) b1v = bias[c0 + 1];
            }
            if (c0 < N) {
                C[(size_t)r0 * N + c0]       = acc[mf][nf][0] + b0v;
                C[(size_t)(r0 + 8) * N + c0] = acc[mf][nf][2] + b0v;
            }
            if (c0 + 1 < N) {
                C[(size_t)r0 * N + c0 + 1]       = acc[mf][nf][1] + b1v;
                C[(size_t)(r0 + 8) * N + c0 + 1] = acc[mf][nf][3] + b1v;
            }
        }
    }
}

// ---------------- persistent LSTM recurrence (smem-resident U, f32x2) ----------
// grid = NCTA (<=148, co-resident), block = 256. CTA owns 8 units = 32 cols
// (col cc = g*8+ul). U slice [U][32] loaded to smem ONCE (reused 256 steps).
// Thread tile: 8 cols x 8 batches. lane: kk=lane>>3 (k-subchunk), cg=(lane>>1)&3
// (col octet), bh=lane&1 (batch octet). kc = warp*4+kk -> 32 k-chunks.
// One grid barrier per timestep.
#define RED_STRIDE 520                     // 512 + 8 pad (bank shift per chunk)
#define RED_FLOATS (32 * RED_STRIDE + 512) // red + gat = 17152 floats

template<int U, int NCTA>
__global__ __launch_bounds__(256) void lstm_k(
    const float* __restrict__ Um,   // [U][4U]
    const float* __restrict__ xg,   // [4096][4U], row m = b*T + t
    float* __restrict__ xout)       // [4096][U]
{
    constexpr int N4  = 4 * U;
    constexpr int KC  = (U + 31) / 32;     // per-chunk k length

    extern __shared__ float sm[];
    float* U_s = sm;                       // [U][32]
    float* h_s = sm + U * 32;              // [U][16]  (aliased by red/gat below)
    float* red = h_s;                      // [32][RED_STRIDE]
    float* gat = h_s + 32 * RED_STRIDE;    // [512]

    const int tid  = threadIdx.x;
    const int w    = tid >> 5;
    const int lane = tid & 31;
    const int kk   = lane >> 3;            // 0..3
    const int cg   = (lane >> 1) & 3;      // 0..3 : cols cg*8 .. cg*8+7
    const int bh   = lane & 1;             // 0..1 : batches bh*8 .. bh*8+7
    const int cgbh = lane & 7;             // cg*2+bh, distinct within octet
    const int kc   = w * 4 + kk;           // 0..31
    const int k0   = kc * KC;
    const int k1   = (k0 + KC < U) ? (k0 + KC) : U;
    const int ub   = blockIdx.x * 8;

    // ---- one-time: stage U slice into smem (zero-fill invalid units) ----
    for (int idx = tid; idx < U * 32; idx += 256) {
        int k = idx >> 5, cc = idx & 31;
        int g = cc >> 3, ul = cc & 7;
        int uu = ub + ul;
        U_s[idx] = (uu < U) ? Um[(size_t)k * N4 + (size_t)g * U + uu] : 0.f;
    }

    // zero recurrent state
    for (int idx = blockIdx.x * 256 + tid; idx < 16 * U; idx += NCTA * 256) {
        g_h[0][idx] = 0.f; g_h[1][idx] = 0.f; g_c[idx] = 0.f;
    }
    unsigned gen = 1;
    grid_sync(gen * NCTA);

    const float* hb  = nullptr;
    const float* ubp = U_s + cg * 8;

    for (int t = 0; t < T_SEQ; ++t) {
        const float* hg = g_h[t & 1];
        float* hn = g_h[(t & 1) ^ 1];

        // stage h into shared (overwrites last step's red/gat alias)
        for (int idx = tid; idx < U * 16; idx += 256) h_s[idx] = __ldcg(&hg[idx]);
        __syncthreads();

        unsigned long long acc[32];
#pragma unroll
        for (int i = 0; i < 32; i++) acc[i] = 0ull;

        hb = h_s + bh * 8;
#pragma unroll 2
        for (int k = k0; k < k1; ++k) {
            ulonglong2 hpa = *(const ulonglong2*)(hb + k * 16);      // b: bh*8+0..3
            ulonglong2 hpb = *(const ulonglong2*)(hb + k * 16 + 4);  // b: bh*8+4..7
            float4 ua = *(const float4*)(ubp + k * 32);
            float4 ubv = *(const float4*)(ubp + k * 32 + 4);
            unsigned long long hh[4] = { hpa.x, hpa.y, hpb.x, hpb.y };
            unsigned long long uu8[8] = {
                dup2(ua.x), dup2(ua.y), dup2(ua.z), dup2(ua.w),
                dup2(ubv.x), dup2(ubv.y), dup2(ubv.z), dup2(ubv.w)
            };
#pragma unroll
            for (int c = 0; c < 8; c++)
#pragma unroll
                for (int p = 0; p < 4; p++)
                    fma2(acc[c * 4 + p], hh[p], uu8[c]);
        }
        __syncthreads();   // all h reads done; red aliases h_s

        // write partials: slot = (i*8+j)*8 + cgbh, region per kc (bank-shifted)
#pragma unroll
        for (int c = 0; c < 8; c++)
#pragma unroll
            for (int p = 0; p < 4; p++) {
                float lo, hi;
                unpack2(acc[c * 4 + p], lo, hi);
                red[kc * RED_STRIDE + (c * 8 + 2 * p) * 8 + cgbh]     = lo;
                red[kc * RED_STRIDE + (c * 8 + 2 * p + 1) * 8 + cgbh] = hi;
            }
        __syncthreads();

        // reduce 32 chunks -> 512 gate preacts (+xg)
#pragma unroll
        for (int r = 0; r < 2; r++) {
            int s   = tid + r * 256;
            int i8j = s >> 3, cb = s & 7;
            int i   = i8j >> 3, j = i8j & 7;
            int cg2 = cb >> 1, bh2 = cb & 1;
            int cc  = cg2 * 8 + i;
            int b   = bh2 * 8 + j;
            float v = 0.f;
#pragma unroll
            for (int q = 0; q < 32; q++) v += red[q * RED_STRIDE + s];
            int g = cc >> 3, ul = cc & 7;
            int uu = ub + ul;
            float xv = (uu < U)
                ? __ldg(&xg[((size_t)b * T_SEQ + t) * N4 + (size_t)g * U + uu]) : 0.f;
            gat[cc * 16 + b] = v + xv;
        }
        __syncthreads();

        // gate math + state update (128 (b,u) pairs per CTA)
        if (tid < 128) {
            int b = tid & 15, ul = tid >> 4;
            int uu = ub + ul;
            if (uu < U) {
                float iv = gat[(0 * 8 + ul) * 16 + b];
                float fv = gat[(1 * 8 + ul) * 16 + b];
                float cgv = gat[(2 * 8 + ul) * 16 + b];
                float ov = gat[(3 * 8 + ul) * 16 + b];
                iv = 1.f / (1.f + __expf(-iv));
                fv = 1.f / (1.f + __expf(-fv));
                ov = 1.f / (1.f + __expf(-ov));
                cgv = tanhf(cgv);
                float cold = g_c[uu * 16 + b];
                float cn = fv * cold + iv * cgv;
                float hv = ov * tanhf(cn);
                g_c[uu * 16 + b] = cn;
                hn[uu * 16 + b] = hv;
                xout[((size_t)b * T_SEQ + t) * U + uu] = hv;
            }
        }
        gen++;
        grid_sync(gen * NCTA);
    }
}

// ---------------- in-place row softmax over N columns ----------------
__global__ __launch_bounds__(256) void softmax_k(float* __restrict__ out, int N) {
    int m = blockIdx.x;
    float* row = out + (size_t)m * N;
    __shared__ float s1[8];
    __shared__ float sb;
    int tid = threadIdx.x, wid = tid >> 5, ln = tid & 31;

    float lm = -3.4e38f;
    for (int i = tid; i < N; i += 256) lm = fmaxf(lm, row[i]);
#pragma unroll
    for (int o = 16; o; o >>= 1) lm = fmaxf(lm, __shfl_xor_sync(0xffffffffu, lm, o));
    if (!ln) s1[wid] = lm;
    __syncthreads();
    if (tid == 0) {
        float v = s1[0];
#pragma unroll
        for (int q = 1; q < 8; q++) v = fmaxf(v, s1[q]);
        sb = v;
    }
    __syncthreads();
    float mx = sb;
    __syncthreads();

    float ls = 0.f;
    for (int i = tid; i < N; i += 256) ls += __expf(row[i] - mx);
#pragma unroll
    for (int o = 16; o; o >>= 1) ls += __shfl_xor_sync(0xffffffffu, ls, o);
    if (!ln) s1[wid] = ls;
    __syncthreads();
    if (tid == 0) {
        float v = 0.f;
#pragma unroll
        for (int q = 0; q < 8; q++) v += s1[q];
        sb = 1.f / v;
    }
    __syncthreads();
    float inv = sb;

    for (int i = tid; i < N; i += 256) row[i] = __expf(row[i] - mx) * inv;
}

// ---------------- launch ----------------
extern "C" void kernel_launch(void* const* d_in, const int* in_sizes, int n_in,
                              void* d_out, int out_size)
{
    (void)in_sizes; (void)n_in; (void)out_size;
    const int*   tok = (const int*)d_in[0];
    const float* emb = (const float*)d_in[1];
    const float* W0  = (const float*)d_in[2];
    const float* U0  = (const float*)d_in[3];
    const float* b0  = (const float*)d_in[4];
    const float* W1  = (const float*)d_in[5];
    const float* U1  = (const float*)d_in[6];
    const float* b1  = (const float*)d_in[7];
    const float* W2  = (const float*)d_in[8];
    const float* U2  = (const float*)d_in[9];
    const float* b2  = (const float*)d_in[10];
    float* out = (float*)d_out;

    float *xa, *xb, *xg;
    cudaGetSymbolAddress((void**)&xa, g_xa);
    cudaGetSymbolAddress((void**)&xb, g_xb);
    cudaGetSymbolAddress((void**)&xg, g_xg);

    // smem: U_s[U][32] + max(h_s[U][16], red+gat)
    auto smem_for = [](int U) {
        int hreg = U * 16 > RED_FLOATS ? U * 16 : RED_FLOATS;
        return (U * 32 + hreg) * 4;
    };
    const int SMEM_BIG   = smem_for(NHID);   // (36800 + 18400)*4 = 220800
    const int SMEM_SMALL = smem_for(NINP);   // (12800 + 17152)*4 = 119808
    cudaFuncSetAttribute(lstm_k<NHID, 144>, cudaFuncAttributeMaxDynamicSharedMemorySize, SMEM_BIG);
    cudaFuncSetAttribute(lstm_k<NINP, 50>,  cudaFuncAttributeMaxDynamicSharedMemorySize, SMEM_SMALL);

    // 1) embedding
    embed_k<<<M_TOK, 128>>>(tok, emb, xa);

    // 2) layer 0: xg = x @ W0 + b0 ; recurrence
    mma_gemm_k<false, true><<<dim3((4 * NHID + 127) / 128, M_TOK / 128), 256>>>(
        xa, W0, b0, xg, M_TOK, 4 * NHID, NINP);
    bar_reset_k<<<1, 1>>>();
    lstm_k<NHID, 144><<<144, 256, SMEM_BIG>>>(U0, xg, xb);

    // 3) layer 1
    mma_gemm_k<false, true><<<dim3((4 * NHID + 127) / 128, M_TOK / 128), 256>>>(
        xb, W1, b1, xg, M_TOK, 4 * NHID, NHID);
    bar_reset_k<<<1, 1>>>();
    lstm_k<NHID, 144><<<144, 256, SMEM_BIG>>>(U1, xg, xa);

    // 4) layer 2 (units = 400)
    mma_gemm_k<false, true><<<dim3((4 * NINP + 127) / 128, M_TOK / 128), 256>>>(
        xa, W2, b2, xg, M_TOK, 4 * NINP, NHID);
    bar_reset_k<<<1, 1>>>();
    lstm_k<NINP, 50><<<50, 256, SMEM_SMALL>>>(U2, xg, xb);

    // 5) tied decode: logits = x @ emb^T   -> write straight into d_out
    mma_gemm_k<true, false><<<dim3((VOCABP1 + 127) / 128, M_TOK / 128), 256>>>(
        xb, emb, nullptr, out, M_TOK, VOCABP1, NINP);

    // 6) in-place softmax
    softmax_k<<<M_TOK, 256>>>(out, VOCABP1);
}

// round 8
// speedup vs baseline: 2.1221x; 1.0484x over previous
#include <cuda_runtime.h>
#include <cuda_bf16.h>
#include <cstdint>
#include <math.h>

#define T_SEQ   256
#define BATCH   16
#define NINP    400
#define NHID    1150
#define VOCABP1 33279
#define M_TOK   (BATCH * T_SEQ)   // 4096

// ---------------- scratch (static device globals; no allocation) ----------------
__device__ float g_xa[(size_t)M_TOK * NHID];          // ping  (max width 1150)
__device__ float g_xb[(size_t)M_TOK * NHID];          // pong
__device__ float g_xg[(size_t)M_TOK * 4 * NHID];      // gate preactivations (max 4096x4600)
__device__ float g_h[2][BATCH * NHID];                // recurrent h ping-pong, layout [u][b]
__device__ float g_c[BATCH * NHID];                   // cell state, layout [u][b]
__device__ unsigned g_bar;                            // grid barrier counter

// ---------------- grid barrier ----------------
__device__ __forceinline__ void grid_sync(unsigned target) {
    __syncthreads();
    if (threadIdx.x == 0) {
        __threadfence();
        atomicAdd(&g_bar, 1u);
        while (*(volatile unsigned*)&g_bar < target) { __nanosleep(40); }
        __threadfence();
    }
    __syncthreads();
}

__global__ void bar_reset_k() { g_bar = 0u; }

// ---------------- embedding gather ----------------
__global__ void embed_k(const int* __restrict__ tok, const float* __restrict__ emb,
                        float* __restrict__ x0) {
    int m = blockIdx.x;                  // m = b*T + t
    int t = tok[m];
    const float4* src = (const float4*)(emb + (size_t)t * NINP);
    float4* dst = (float4*)(x0 + (size_t)m * NINP);
    for (int i = threadIdx.x; i < NINP / 4; i += blockDim.x) dst[i] = src[i];
}

// ---------------- packed f32x2 helpers (Blackwell) ----------------
__device__ __forceinline__ unsigned long long dup2(float x) {
    unsigned long long d;
    asm("mov.b64 %0, {%1, %1};" : "=l"(d) : "f"(x));
    return d;
}
__device__ __forceinline__ void fma2(unsigned long long& d,
                                     unsigned long long a, unsigned long long b) {
    asm("fma.rn.f32x2 %0, %1, %2, %0;" : "+l"(d) : "l"(a), "l"(b));
}
__device__ __forceinline__ void unpack2(unsigned long long v, float& lo, float& hi) {
    asm("mov.b64 {%0, %1}, %2;" : "=f"(lo), "=f"(hi) : "l"(v));
}

// ---------------- bf16 helpers ----------------
__device__ __forceinline__ uint32_t bf2(float a, float b) {
    __nv_bfloat162 t = __floats2bfloat162_rn(a, b);   // x=a (low k), y=b (high k)
    return *reinterpret_cast<uint32_t*>(&t);
}

#define MMA_BF16(d, a, b)                                                     \
    asm volatile("mma.sync.aligned.m16n8k16.row.col.f32.bf16.bf16.f32 "      \
                 "{%0,%1,%2,%3}, {%4,%5,%6,%7}, {%8,%9}, {%0,%1,%2,%3};"      \
                 : "+f"(d[0]), "+f"(d[1]), "+f"(d[2]), "+f"(d[3])             \
                 : "r"(a[0]), "r"(a[1]), "r"(a[2]), "r"(a[3]),                \
                   "r"(b[0]), "r"(b[1]))

// alignment-safe 4-float row load into v[0..3]; p must be 4B aligned.
__device__ __forceinline__ void ld4_safe(const float* p, float* v) {
    uintptr_t a = (uintptr_t)p;
    if ((a & 15u) == 0) {
        float4 t = *(const float4*)p;
        v[0] = t.x; v[1] = t.y; v[2] = t.z; v[3] = t.w;
    } else if ((a & 7u) == 0) {
        float2 t0 = *(const float2*)p;
        float2 t1 = *(const float2*)(p + 2);
        v[0] = t0.x; v[1] = t0.y; v[2] = t1.x; v[3] = t1.y;
    } else {
        v[0] = p[0]; v[1] = p[1]; v[2] = p[2]; v[3] = p[3];
    }
}

// smem column swizzle for the packed-bf16 tiles: constant per k2-row,
// makes both the packed stores and the fragment loads bank-conflict-free.
#define SWZ(k2) ((((k2) >> 2) & 3) << 3)

// ---------------- BF16 tensor-core GEMM: C[M,N] = A[M,K] * B (+bias) ------------
// BTRANS=false: B is [K,N] row-major.  BTRANS=true: B is [N,K] row-major (C=A*B^T).
// M multiple of 128 (always 4096). CTA tile 128x128, BK=32, double-buffered smem,
// 8 warps x (64x32) warp tiles, m16n8k16 bf16 MMA, fp32 accumulate.
template<bool BTRANS, bool BIAS>
__global__ __launch_bounds__(256, 2) void mma_gemm_k(
    const float* __restrict__ A, const float* __restrict__ B,
    const float* __restrict__ bias, float* __restrict__ C,
    int M, int N, int K)
{
    // [buf][k2][col], packed bf16x2 (k even in low half). 2*2*16*136*4 = 34816 B
    __shared__ uint32_t As[2][16][136];
    __shared__ uint32_t Bs[2][16][136];

    const int tid  = threadIdx.x;
    const int bm   = blockIdx.y * 128;
    const int bn   = blockIdx.x * 128;
    const int wid  = tid >> 5;
    const int lane = tid & 31;
    const int wm   = (wid >> 2) * 64;     // 0 or 64
    const int wn   = (wid & 3) * 32;      // 0,32,64,96
    const int gID  = lane >> 2;           // 0..7
    const int tg   = lane & 3;            // 0..3

    // global-load thread mappings
    const int arow = tid >> 2;            // 0..63 (rows arow, arow+64)  [A, BTRANS-B]
    const int aq   = tid & 3;             // k-octet selector
    const int akb  = aq * 8;              // k offset within 32-k tile
    const int q    = tid >> 5;            // 0..7                        [!BTRANS B]
    const int bnc  = (tid & 31) * 4;      // 0..124                      [!BTRANS B]

    float acc[4][4][4];
#pragma unroll
    for (int mf = 0; mf < 4; mf++)
#pragma unroll
        for (int nf = 0; nf < 4; nf++)
#pragma unroll
            for (int i = 0; i < 4; i++) acc[mf][nf][i] = 0.f;

    uint32_t ar2[8];
    alignas(16) uint32_t br2[8];

    auto loadg = [&](int k0) {
        // ---- A: [M,K] row-major, 128x32 tile, pack k-pairs ----
#pragma unroll
        for (int j = 0; j < 2; j++) {
            const float* p = A + (size_t)(bm + arow + j * 64) * K + k0 + akb;
            float v[8];
            if (k0 + akb + 7 < K) {
                ld4_safe(p, v); ld4_safe(p + 4, v + 4);
            } else {
#pragma unroll
                for (int i = 0; i < 8; i++)
                    v[i] = (k0 + akb + i < K) ? p[i] : 0.f;
            }
#pragma unroll
            for (int i = 0; i < 4; i++)
                ar2[j * 4 + i] = bf2(v[2 * i], v[2 * i + 1]);
        }
        // ---- B ----
        if (BTRANS) {   // B[N,K]: same shape as A
#pragma unroll
            for (int j = 0; j < 2; j++) {
                int gn = bn + arow + j * 64;
                const float* p = B + (size_t)gn * K + k0 + akb;
                float v[8];
                if (gn < N && k0 + akb + 7 < K) {
                    ld4_safe(p, v); ld4_safe(p + 4, v + 4);
                } else {
#pragma unroll
                    for (int i = 0; i < 8; i++)
                        v[i] = (gn < N && k0 + akb + i < K) ? p[i] : 0.f;
                }
#pragma unroll
                for (int i = 0; i < 4; i++)
                    br2[j * 4 + i] = bf2(v[2 * i], v[2 * i + 1]);
            }
        } else {        // B[K,N]: pack adjacent k-rows
            int gn0 = bn + bnc;
            bool nok = (gn0 + 3 < N);
#pragma unroll
            for (int p2 = 0; p2 < 2; p2++) {
                int gk = k0 + p2 * 16 + 2 * q;
                const float* pe = B + (size_t)gk * N + gn0;
                const float* po = pe + N;
                float e[4], o[4];
                if (gk < K && nok) {
                    ld4_safe(pe, e);
                } else {
#pragma unroll
                    for (int i = 0; i < 4; i++)
                        e[i] = (gk < K && gn0 + i < N) ? pe[i] : 0.f;
                }
                if (gk + 1 < K && nok) {
                    ld4_safe(po, o);
                } else {
#pragma unroll
                    for (int i = 0; i < 4; i++)
                        o[i] = (gk + 1 < K && gn0 + i < N) ? po[i] : 0.f;
                }
#pragma unroll
                for (int i = 0; i < 4; i++)
                    br2[p2 * 4 + i] = bf2(e[i], o[i]);
            }
        }
    };

    auto stores = [&](int b) {
#pragma unroll
        for (int j = 0; j < 2; j++)
#pragma unroll
            for (int i = 0; i < 4; i++)
                As[b][aq * 4 + i][(arow + j * 64) ^ (aq << 3)] = ar2[j * 4 + i];
        if (BTRANS) {
#pragma unroll
            for (int j = 0; j < 2; j++)
#pragma unroll
                for (int i = 0; i < 4; i++)
                    Bs[b][aq * 4 + i][(arow + j * 64) ^ (aq << 3)] = br2[j * 4 + i];
        } else {
#pragma unroll
            for (int p2 = 0; p2 < 2; p2++) {
                int k2 = q + p2 * 8;
                *(uint4*)&Bs[b][k2][bnc ^ SWZ(k2)] = *(const uint4*)&br2[p2 * 4];
            }
        }
    };

    const int nkt = (K + 31) / 32;
    loadg(0);
    stores(0);
    __syncthreads();

    for (int kt = 0; kt < nkt; kt++) {
        const int  buf  = kt & 1;
        const bool more = (kt + 1 < nkt);
        if (more) loadg((kt + 1) * 32);

#pragma unroll
        for (int s = 0; s < 2; s++) {
            const int r0 = s * 8 + tg;
            const int r1 = s * 8 + 4 + tg;
            const int x0 = SWZ(r0);
            const int x1 = SWZ(r1);
            uint32_t af[4][4], bfr[4][2];
#pragma unroll
            for (int mf = 0; mf < 4; mf++) {
                int m = wm + mf * 16 + gID;
                af[mf][0] = As[buf][r0][m ^ x0];
                af[mf][1] = As[buf][r0][(m + 8) ^ x0];
                af[mf][2] = As[buf][r1][m ^ x1];
                af[mf][3] = As[buf][r1][(m + 8) ^ x1];
            }
#pragma unroll
            for (int nf = 0; nf < 4; nf++) {
                int n = wn + nf * 8 + gID;
                bfr[nf][0] = Bs[buf][r0][n ^ x0];
                bfr[nf][1] = Bs[buf][r1][n ^ x1];
            }
#pragma unroll
            for (int mf = 0; mf < 4; mf++)
#pragma unroll
                for (int nf = 0; nf < 4; nf++)
                    MMA_BF16(acc[mf][nf], af[mf], bfr[nf]);
        }

        if (more) stores(buf ^ 1);
        __syncthreads();
    }

    // epilogue
#pragma unroll
    for (int mf = 0; mf < 4; mf++) {
        int r0 = bm + wm + mf * 16 + gID;
#pragma unroll
        for (int nf = 0; nf < 4; nf++) {
            int c0 = bn + wn + nf * 8 + tg * 2;
            float b0v = 0.f, b1v = 0.f;
            if (BIAS) {
                if (c0 < N)     b0v = bias[c0];
                if (c0 + 1 < N) b1v = bias[c0 + 1];
            }
            if (c0 < N) {
                C[(size_t)r0 * N + c0]       = acc[mf][nf][0] + b0v;
                C[(size_t)(r0 + 8) * N + c0] = acc[mf][nf][2] + b0v;
            }
            if (c0 + 1 < N) {
                C[(size_t)r0 * N + c0 + 1]       = acc[mf][nf][1] + b1v;
                C[(size_t)(r0 + 8) * N + c0 + 1] = acc[mf][nf][3] + b1v;
            }
        }
    }
}

// ---------------- persistent LSTM recurrence (smem-resident U, f32x2) ----------
#define RED_STRIDE 520                     // 512 + 8 pad (bank shift per chunk)
#define RED_FLOATS (32 * RED_STRIDE + 512) // red + gat = 17152 floats

template<int U, int NCTA>
__global__ __launch_bounds__(256) void lstm_k(
    const float* __restrict__ Um,   // [U][4U]
    const float* __restrict__ xg,   // [4096][4U], row m = b*T + t
    float* __restrict__ xout)       // [4096][U]
{
    constexpr int N4  = 4 * U;
    constexpr int KC  = (U + 31) / 32;     // per-chunk k length

    extern __shared__ float sm[];
    float* U_s = sm;                       // [U][32]
    float* h_s = sm + U * 32;              // [U][16]  (aliased by red/gat below)
    float* red = h_s;                      // [32][RED_STRIDE]
    float* gat = h_s + 32 * RED_STRIDE;    // [512]

    const int tid  = threadIdx.x;
    const int w    = tid >> 5;
    const int lane = tid & 31;
    const int kk   = lane >> 3;            // 0..3
    const int cg   = (lane >> 1) & 3;      // 0..3 : cols cg*8 .. cg*8+7
    const int bh   = lane & 1;             // 0..1 : batches bh*8 .. bh*8+7
    const int cgbh = lane & 7;             // cg*2+bh, distinct within octet
    const int kc   = w * 4 + kk;           // 0..31
    const int k0   = kc * KC;
    const int k1   = (k0 + KC < U) ? (k0 + KC) : U;
    const int ub   = blockIdx.x * 8;

    // ---- one-time: stage U slice into smem (zero-fill invalid units) ----
    for (int idx = tid; idx < U * 32; idx += 256) {
        int k = idx >> 5, cc = idx & 31;
        int g = cc >> 3, ul = cc & 7;
        int uu = ub + ul;
        U_s[idx] = (uu < U) ? Um[(size_t)k * N4 + (size_t)g * U + uu] : 0.f;
    }

    // zero recurrent state
    for (int idx = blockIdx.x * 256 + tid; idx < 16 * U; idx += NCTA * 256) {
        g_h[0][idx] = 0.f; g_h[1][idx] = 0.f; g_c[idx] = 0.f;
    }
    unsigned gen = 1;
    grid_sync(gen * NCTA);

    const float* hb  = nullptr;
    const float* ubp = U_s + cg * 8;

    for (int t = 0; t < T_SEQ; ++t) {
        const float* hg = g_h[t & 1];
        float* hn = g_h[(t & 1) ^ 1];

        // stage h into shared (overwrites last step's red/gat alias)
        for (int idx = tid; idx < U * 16; idx += 256) h_s[idx] = __ldcg(&hg[idx]);
        __syncthreads();

        unsigned long long acc[32];
#pragma unroll
        for (int i = 0; i < 32; i++) acc[i] = 0ull;

        hb = h_s + bh * 8;
#pragma unroll 2
        for (int k = k0; k < k1; ++k) {
            ulonglong2 hpa = *(const ulonglong2*)(hb + k * 16);      // b: bh*8+0..3
            ulonglong2 hpb = *(const ulonglong2*)(hb + k * 16 + 4);  // b: bh*8+4..7
            float4 ua = *(const float4*)(ubp + k * 32);
            float4 ubv = *(const float4*)(ubp + k * 32 + 4);
            unsigned long long hh[4] = { hpa.x, hpa.y, hpb.x, hpb.y };
            unsigned long long uu8[8] = {
                dup2(ua.x), dup2(ua.y), dup2(ua.z), dup2(ua.w),
                dup2(ubv.x), dup2(ubv.y), dup2(ubv.z), dup2(ubv.w)
            };
#pragma unroll
            for (int c = 0; c < 8; c++)
#pragma unroll
                for (int p = 0; p < 4; p++)
                    fma2(acc[c * 4 + p], hh[p], uu8[c]);
        }
        __syncthreads();   // all h reads done; red aliases h_s

        // write partials: slot = (i*8+j)*8 + cgbh, region per kc (bank-shifted)
#pragma unroll
        for (int c = 0; c < 8; c++)
#pragma unroll
            for (int p = 0; p < 4; p++) {
                float lo, hi;
                unpack2(acc[c * 4 + p], lo, hi);
                red[kc * RED_STRIDE + (c * 8 + 2 * p) * 8 + cgbh]     = lo;
                red[kc * RED_STRIDE + (c * 8 + 2 * p + 1) * 8 + cgbh] = hi;
            }
        __syncthreads();

        // reduce 32 chunks -> 512 gate preacts (+xg)
#pragma unroll
        for (int r = 0; r < 2; r++) {
            int s   = tid + r * 256;
            int i8j = s >> 3, cb = s & 7;
            int i   = i8j >> 3, j = i8j & 7;
            int cg2 = cb >> 1, bh2 = cb & 1;
            int cc  = cg2 * 8 + i;
            int b   = bh2 * 8 + j;
            float v = 0.f;
#pragma unroll
            for (int q = 0; q < 32; q++) v += red[q * RED_STRIDE + s];
            int g = cc >> 3, ul = cc & 7;
            int uu = ub + ul;
            float xv = (uu < U)
                ? __ldg(&xg[((size_t)b * T_SEQ + t) * N4 + (size_t)g * U + uu]) : 0.f;
            gat[cc * 16 + b] = v + xv;
        }
        __syncthreads();

        // gate math + state update (128 (b,u) pairs per CTA)
        if (tid < 128) {
            int b = tid & 15, ul = tid >> 4;
            int uu = ub + ul;
            if (uu < U) {
                float iv = gat[(0 * 8 + ul) * 16 + b];
                float fv = gat[(1 * 8 + ul) * 16 + b];
                float cgv = gat[(2 * 8 + ul) * 16 + b];
                float ov = gat[(3 * 8 + ul) * 16 + b];
                iv = 1.f / (1.f + __expf(-iv));
                fv = 1.f / (1.f + __expf(-fv));
                ov = 1.f / (1.f + __expf(-ov));
                cgv = tanhf(cgv);
                float cold = g_c[uu * 16 + b];
                float cn = fv * cold + iv * cgv;
                float hv = ov * tanhf(cn);
                g_c[uu * 16 + b] = cn;
                hn[uu * 16 + b] = hv;
                xout[((size_t)b * T_SEQ + t) * U + uu] = hv;
            }
        }
        gen++;
        grid_sync(gen * NCTA);
    }
}

// ---------------- in-place row softmax over N columns ----------------
__global__ __launch_bounds__(256) void softmax_k(float* __restrict__ out, int N) {
    int m = blockIdx.x;
    float* row = out + (size_t)m * N;
    __shared__ float s1[8];
    __shared__ float sb;
    int tid = threadIdx.x, wid = tid >> 5, ln = tid & 31;

    float lm = -3.4e38f;
    for (int i = tid; i < N; i += 256) lm = fmaxf(lm, row[i]);
#pragma unroll
    for (int o = 16; o; o >>= 1) lm = fmaxf(lm, __shfl_xor_sync(0xffffffffu, lm, o));
    if (!ln) s1[wid] = lm;
    __syncthreads();
    if (tid == 0) {
        float v = s1[0];
#pragma unroll
        for (int q = 1; q < 8; q++) v = fmaxf(v, s1[q]);
        sb = v;
    }
    __syncthreads();
    float mx = sb;
    __syncthreads();

    float ls = 0.f;
    for (int i = tid; i < N; i += 256) ls += __expf(row[i] - mx);
#pragma unroll
    for (int o = 16; o; o >>= 1) ls += __shfl_xor_sync(0xffffffffu, ls, o);
    if (!ln) s1[wid] = ls;
    __syncthreads();
    if (tid == 0) {
        float v = 0.f;
#pragma unroll
        for (int q = 0; q < 8; q++) v += s1[q];
        sb = 1.f / v;
    }
    __syncthreads();
    float inv = sb;

    for (int i = tid; i < N; i += 256) row[i] = __expf(row[i] - mx) * inv;
}

// ---------------- launch ----------------
extern "C" void kernel_launch(void* const* d_in, const int* in_sizes, int n_in,
                              void* d_out, int out_size)
{
    (void)in_sizes; (void)n_in; (void)out_size;
    const int*   tok = (const int*)d_in[0];
    const float* emb = (const float*)d_in[1];
    const float* W0  = (const float*)d_in[2];
    const float* U0  = (const float*)d_in[3];
    const float* b0  = (const float*)d_in[4];
    const float* W1  = (const float*)d_in[5];
    const float* U1  = (const float*)d_in[6];
    const float* b1  = (const float*)d_in[7];
    const float* W2  = (const float*)d_in[8];
    const float* U2  = (const float*)d_in[9];
    const float* b2  = (const float*)d_in[10];
    float* out = (float*)d_out;

    float *xa, *xb, *xg;
    cudaGetSymbolAddress((void**)&xa, g_xa);
    cudaGetSymbolAddress((void**)&xb, g_xb);
    cudaGetSymbolAddress((void**)&xg, g_xg);

    // smem: U_s[U][32] + max(h_s[U][16], red+gat)
    auto smem_for = [](int U) {
        int hreg = U * 16 > RED_FLOATS ? U * 16 : RED_FLOATS;
        return (U * 32 + hreg) * 4;
    };
    const int SMEM_BIG   = smem_for(NHID);   // 220800
    const int SMEM_SMALL = smem_for(NINP);   // 119808
    cudaFuncSetAttribute(lstm_k<NHID, 144>, cudaFuncAttributeMaxDynamicSharedMemorySize, SMEM_BIG);
    cudaFuncSetAttribute(lstm_k<NINP, 50>,  cudaFuncAttributeMaxDynamicSharedMemorySize, SMEM_SMALL);

    // 1) embedding
    embed_k<<<M_TOK, 128>>>(tok, emb, xa);

    // 2) layer 0: xg = x @ W0 + b0 ; recurrence
    mma_gemm_k<false, true><<<dim3((4 * NHID + 127) / 128, M_TOK / 128), 256>>>(
        xa, W0, b0, xg, M_TOK, 4 * NHID, NINP);
    bar_reset_k<<<1, 1>>>();
    lstm_k<NHID, 144><<<144, 256, SMEM_BIG>>>(U0, xg, xb);

    // 3) layer 1
    mma_gemm_k<false, true><<<dim3((4 * NHID + 127) / 128, M_TOK / 128), 256>>>(
        xb, W1, b1, xg, M_TOK, 4 * NHID, NHID);
    bar_reset_k<<<1, 1>>>();
    lstm_k<NHID, 144><<<144, 256, SMEM_BIG>>>(U1, xg, xa);

    // 4) layer 2 (units = 400)
    mma_gemm_k<false, true><<<dim3((4 * NINP + 127) / 128, M_TOK / 128), 256>>>(
        xa, W2, b2, xg, M_TOK, 4 * NINP, NHID);
    bar_reset_k<<<1, 1>>>();
    lstm_k<NINP, 50><<<50, 256, SMEM_SMALL>>>(U2, xg, xb);

    // 5) tied decode: logits = x @ emb^T   -> write straight into d_out
    mma_gemm_k<true, false><<<dim3((VOCABP1 + 127) / 128, M_TOK / 128), 256>>>(
        xb, emb, nullptr, out, M_TOK, VOCABP1, NINP);

    // 6) in-place softmax
    softmax_k<<<M_TOK, 256>>>(out, VOCABP1);
}

// round 10
// speedup vs baseline: 2.2682x; 1.0689x over previous
#include <cuda_runtime.h>
#include <cuda_bf16.h>
#include <cstdint>
#include <math.h>

#define T_SEQ   256
#define BATCH   16
#define NINP    400
#define NHID    1150
#define VOCABP1 33279
#define M_TOK   (BATCH * T_SEQ)   // 4096

// K padded to multiples of 64 for the bf16 activation / weight buffers
#define KP_400  448
#define KP_1150 1152

// ---------------- scratch (static device globals; no allocation) ----------------
__device__ float g_xg[(size_t)M_TOK * 4 * NHID];      // gate preactivations
__device__ float g_h[2][BATCH * NHID];                // recurrent h ping-pong [u][b]
__device__ float g_c[BATCH * NHID];                   // cell state [u][b]
__device__ unsigned g_bar;

__device__ __nv_bfloat16 g_ab0[(size_t)M_TOK * KP_400];    // embed out   [4096][448]
__device__ __nv_bfloat16 g_ab1[(size_t)M_TOK * KP_1150];   // layer0 out  [4096][1152]
__device__ __nv_bfloat16 g_ab2[(size_t)M_TOK * KP_1150];   // layer1 out  [4096][1152]
__device__ __nv_bfloat16 g_ab3[(size_t)M_TOK * KP_400];    // layer2 out  [4096][448]
__device__ __nv_bfloat16 g_w0t[(size_t)4600 * KP_400];     // W0^T
__device__ __nv_bfloat16 g_w1t[(size_t)4600 * KP_1150];    // W1^T
__device__ __nv_bfloat16 g_w2t[(size_t)1600 * KP_1150];    // W2^T
__device__ __nv_bfloat16 g_embb[(size_t)VOCABP1 * KP_400]; // emb bf16 padded

// ---------------- small helpers ----------------
__device__ __forceinline__ uint32_t smem_to_u32(const void* p) {
    uint32_t a;
    asm("{ .reg .u64 t; cvta.to.shared.u64 t, %1; cvt.u32.u64 %0, t; }"
        : "=r"(a) : "l"(p));
    return a;
}
#define SMEM_SWIZZLE_128B(b) ((b) ^ (((b) >> 3) & 0x70))

__device__ __forceinline__ unsigned long long dup2(float x) {
    unsigned long long d;
    asm("mov.b64 %0, {%1, %1};" : "=l"(d) : "f"(x));
    return d;
}
__device__ __forceinline__ void fma2(unsigned long long& d,
                                     unsigned long long a, unsigned long long b) {
    asm("fma.rn.f32x2 %0, %1, %2, %0;" : "+l"(d) : "l"(a), "l"(b));
}
__device__ __forceinline__ void unpack2(unsigned long long v, float& lo, float& hi) {
    asm("mov.b64 {%0, %1}, %2;" : "=f"(lo), "=f"(hi) : "l"(v));
}

#define MMA_BF16(d, a, b)                                                     \
    asm volatile("mma.sync.aligned.m16n8k16.row.col.f32.bf16.bf16.f32 "      \
                 "{%0,%1,%2,%3}, {%4,%5,%6,%7}, {%8,%9}, {%0,%1,%2,%3};"      \
                 : "+f"(d[0]), "+f"(d[1]), "+f"(d[2]), "+f"(d[3])             \
                 : "r"(a[0]), "r"(a[1]), "r"(a[2]), "r"(a[3]),                \
                   "r"(b[0]), "r"(b[1]))

// ---------------- grid barrier ----------------
__device__ __forceinline__ void grid_sync(unsigned target) {
    __syncthreads();
    if (threadIdx.x == 0) {
        __threadfence();
        atomicAdd(&g_bar, 1u);
        while (*(volatile unsigned*)&g_bar < target) { __nanosleep(40); }
        __threadfence();
    }
    __syncthreads();
}
__global__ void bar_reset_k() { g_bar = 0u; }

// ---------------- prep kernels ----------------
// W [K][N] fp32 -> Wt [N][Kpad] bf16 (zero-padded in k)
__global__ __launch_bounds__(256) void transpose_bf_k(
    const float* __restrict__ W, __nv_bfloat16* __restrict__ Wt,
    int K, int N, int Kpad)
{
    __shared__ float tile[32][33];
    int n0 = blockIdx.x * 32, k0 = blockIdx.y * 32;
    int tx = threadIdx.x & 31, ty = threadIdx.x >> 5;
    for (int i = ty; i < 32; i += 8) {
        int k = k0 + i, n = n0 + tx;
        tile[i][tx] = (k < K && n < N) ? W[(size_t)k * N + n] : 0.f;
    }
    __syncthreads();
    for (int i = ty; i < 32; i += 8) {
        int n = n0 + i, k = k0 + tx;
        if (n < N && k < Kpad)
            Wt[(size_t)n * Kpad + k] = __float2bfloat16(tile[tx][i]);
    }
}

__global__ __launch_bounds__(256) void convert_emb_k(
    const float* __restrict__ emb, __nv_bfloat16* __restrict__ out)
{
    int r = blockIdx.x;
    for (int c = threadIdx.x; c < KP_400; c += 256)
        out[(size_t)r * KP_400 + c] =
            (c < NINP) ? __float2bfloat16(emb[(size_t)r * NINP + c]) : __nv_bfloat16(0.f);
}

// zero the k-pad columns of the LSTM output buffers (written only for k < U)
__global__ __launch_bounds__(256) void zeropad_k(
    __nv_bfloat16* a1, __nv_bfloat16* a2, __nv_bfloat16* a3)
{
    int m = blockIdx.x * 256 + threadIdx.x;
    if (m < M_TOK) {
        a1[(size_t)m * KP_1150 + 1150] = __nv_bfloat16(0.f);
        a1[(size_t)m * KP_1150 + 1151] = __nv_bfloat16(0.f);
        a2[(size_t)m * KP_1150 + 1150] = __nv_bfloat16(0.f);
        a2[(size_t)m * KP_1150 + 1151] = __nv_bfloat16(0.f);
        for (int c = NINP; c < KP_400; c++)
            a3[(size_t)m * KP_400 + c] = __nv_bfloat16(0.f);
    }
}

// embedding gather in bf16 (rows of the padded bf16 table)
__global__ void embed_bf_k(const int* __restrict__ tok,
                           const __nv_bfloat16* __restrict__ embb,
                           __nv_bfloat16* __restrict__ x0) {
    int m = blockIdx.x;
    int t = tok[m];
    const uint4* src = (const uint4*)(embb + (size_t)t * KP_400);
    uint4* dst = (uint4*)(x0 + (size_t)m * KP_400);
    for (int i = threadIdx.x; i < KP_400 * 2 / 16; i += blockDim.x) dst[i] = src[i];
}

// ================= bf16 GEMM: C[M,N] = A[M,Kpad] @ B[N,Kpad]^T (+bias) ==========
// cp.async 3-stage pipeline, BK=64 (128B SW128 rows), ldmatrix fragment loads,
// 8 warps x (64x32) warp tiles, m16n8k16 bf16 MMA fp32 accumulate.
// M multiple of 128; Kpad multiple of 64 (zero-padded); N arbitrary (B rows
// beyond N zero-filled via cp.async src-size-0).
#define GSTAGES 3
#define GEMM_SMEM (GSTAGES * 32768)

template<bool BIAS>
__global__ __launch_bounds__(256) void bf16_gemm_k(
    const __nv_bfloat16* __restrict__ A, const __nv_bfloat16* __restrict__ B,
    const float* __restrict__ bias, float* __restrict__ C,
    int M, int N, int Kpad)
{
    extern __shared__ char smem[];
    const uint32_t sbase = smem_to_u32(smem);

    const int tid  = threadIdx.x;
    const int wid  = tid >> 5;
    const int lane = tid & 31;
    const int bm   = blockIdx.y * 128;
    const int bn   = blockIdx.x * 128;
    const int wm   = (wid >> 2) * 64;
    const int wn   = (wid & 3) * 32;

    // cp.async mapping: thread -> (row, 64B half), 4x 16B chunks
    const int lrow  = tid >> 1;
    const int lhalf = tid & 1;
    const __nv_bfloat16* Asrc = A + (size_t)(bm + lrow) * Kpad + lhalf * 32;
    const int gnrow = bn + lrow;
    const __nv_bfloat16* Bsrc = B + (size_t)gnrow * Kpad + lhalf * 32;
    const int bvalid = (gnrow < N) ? 16 : 0;

    // ldmatrix lane mappings
    const int lm16 = lane & 15;
    const int lk16 = lane >> 4;          // 0/1 : 16B k-half (A)
    const int ln8  = lane & 7;
    const int lkb  = (lane >> 3) & 1;    // 0/1 : 16B k-half (B, lanes 0-15)

    float acc[4][4][4];
#pragma unroll
    for (int mf = 0; mf < 4; mf++)
#pragma unroll
        for (int nf = 0; nf < 4; nf++)
#pragma unroll
            for (int i = 0; i < 4; i++) acc[mf][nf][i] = 0.f;

    auto load_tile = [&](int stage, int kt) {
        uint32_t sa = sbase + stage * 32768;
        uint32_t sb = sa + 16384;
        const __nv_bfloat16* ap = Asrc + kt * 64;
        const __nv_bfloat16* bp = Bsrc + kt * 64;
#pragma unroll
        for (int j = 0; j < 4; j++) {
            uint32_t off = SMEM_SWIZZLE_128B((uint32_t)(lrow * 128 + lhalf * 64 + j * 16));
            asm volatile("cp.async.cg.shared.global [%0], [%1], 16;"
                         :: "r"(sa + off), "l"(ap + j * 8));
            asm volatile("cp.async.cg.shared.global [%0], [%1], 16, %2;"
                         :: "r"(sb + off), "l"(bp + j * 8), "r"(bvalid));
        }
    };

    const int nkt = Kpad >> 6;

    // prologue: stages 0..GSTAGES-2
#pragma unroll
    for (int s = 0; s < GSTAGES - 1; s++) {
        load_tile(s, s);
        asm volatile("cp.async.commit_group;" ::: "memory");
    }

    for (int kt = 0; kt < nkt; kt++) {
        if (kt + GSTAGES - 1 < nkt)
            load_tile((kt + GSTAGES - 1) % GSTAGES, kt + GSTAGES - 1);
        asm volatile("cp.async.commit_group;" ::: "memory");
        asm volatile("cp.async.wait_group %0;" :: "n"(GSTAGES - 1) : "memory");
        __syncthreads();

        uint32_t sa = sbase + (kt % GSTAGES) * 32768;
        uint32_t sb = sa + 16384;
#pragma unroll
        for (int s = 0; s < 4; s++) {
            uint32_t af[4][4], bfr[4][2];
#pragma unroll
            for (int mf = 0; mf < 4; mf++) {
                uint32_t off = (uint32_t)((wm + mf * 16 + lm16) * 128 + s * 32 + lk16 * 16);
                uint32_t ad = sa + SMEM_SWIZZLE_128B(off);
                asm volatile("ldmatrix.sync.aligned.m8n8.x4.shared.b16 "
                             "{%0,%1,%2,%3}, [%4];"
                             : "=r"(af[mf][0]), "=r"(af[mf][1]),
                               "=r"(af[mf][2]), "=r"(af[mf][3]) : "r"(ad));
            }
#pragma unroll
            for (int nf = 0; nf < 4; nf++) {
                uint32_t off = (uint32_t)((wn + nf * 8 + ln8) * 128 + s * 32 + lkb * 16);
                uint32_t ad = sb + SMEM_SWIZZLE_128B(off);
                asm volatile("ldmatrix.sync.aligned.m8n8.x2.shared.b16 "
                             "{%0,%1}, [%2];"
                             : "=r"(bfr[nf][0]), "=r"(bfr[nf][1]) : "r"(ad));
            }
#pragma unroll
            for (int mf = 0; mf < 4; mf++)
#pragma unroll
                for (int nf = 0; nf < 4; nf++)
                    MMA_BF16(acc[mf][nf], af[mf], bfr[nf]);
        }
        __syncthreads();
    }

    // epilogue (same acc layout as R8)
    const int gID = lane >> 2;
    const int tg  = lane & 3;
#pragma unroll
    for (int mf = 0; mf < 4; mf++) {
        int r0 = bm + wm + mf * 16 + gID;
#pragma unroll
        for (int nf = 0; nf < 4; nf++) {
            int c0 = bn + wn + nf * 8 + tg * 2;
            float b0v = 0.f, b1v = 0.f;
            if (BIAS) {
                if (c0 < N)     b0v = bias[c0];
                if (c0 + 1 < N) b1v = bias[c0 + 1];
            }
            if (c0 < N) {
                C[(size_t)r0 * N + c0]       = acc[mf][nf][0] + b0v;
                C[(size_t)(r0 + 8) * N + c0] = acc[mf][nf][2] + b0v;
            }
            if (c0 + 1 < N) {
                C[(size_t)r0 * N + c0 + 1]       = acc[mf][nf][1] + b1v;
                C[(size_t)(r0 + 8) * N + c0 + 1] = acc[mf][nf][3] + b1v;
            }
        }
    }
}

// ---------------- persistent LSTM recurrence (bf16 xout) ----------------
#define RED_STRIDE 520
#define RED_FLOATS (32 * RED_STRIDE + 512)

template<int U, int NCTA>
__global__ __launch_bounds__(256) void lstm_k(
    const float* __restrict__ Um,        // [U][4U]
    const float* __restrict__ xg,        // [4096][4U]
    __nv_bfloat16* __restrict__ xout,    // [4096][ostride]
    int ostride)
{
    constexpr int N4  = 4 * U;
    constexpr int KC  = (U + 31) / 32;

    extern __shared__ float sm[];
    float* U_s = sm;
    float* h_s = sm + U * 32;
    float* red = h_s;
    float* gat = h_s + 32 * RED_STRIDE;

    const int tid  = threadIdx.x;
    const int w    = tid >> 5;
    const int lane = tid & 31;
    const int kk   = lane >> 3;
    const int cg   = (lane >> 1) & 3;
    const int bh   = lane & 1;
    const int cgbh = lane & 7;
    const int kc   = w * 4 + kk;
    const int k0   = kc * KC;
    const int k1   = (k0 + KC < U) ? (k0 + KC) : U;
    const int ub   = blockIdx.x * 8;

    for (int idx = tid; idx < U * 32; idx += 256) {
        int k = idx >> 5, cc = idx & 31;
        int g = cc >> 3, ul = cc & 7;
        int uu = ub + ul;
        U_s[idx] = (uu < U) ? Um[(size_t)k * N4 + (size_t)g * U + uu] : 0.f;
    }
    for (int idx = blockIdx.x * 256 + tid; idx < 16 * U; idx += NCTA * 256) {
        g_h[0][idx] = 0.f; g_h[1][idx] = 0.f; g_c[idx] = 0.f;
    }
    unsigned gen = 1;
    grid_sync(gen * NCTA);

    const float* ubp = U_s + cg * 8;

    for (int t = 0; t < T_SEQ; ++t) {
        const float* hg = g_h[t & 1];
        float* hn = g_h[(t & 1) ^ 1];

        for (int idx = tid; idx < U * 16; idx += 256) h_s[idx] = __ldcg(&hg[idx]);
        __syncthreads();

        unsigned long long acc[32];
#pragma unroll
        for (int i = 0; i < 32; i++) acc[i] = 0ull;

        const float* hb = h_s + bh * 8;
#pragma unroll 2
        for (int k = k0; k < k1; ++k) {
            ulonglong2 hpa = *(const ulonglong2*)(hb + k * 16);
            ulonglong2 hpb = *(const ulonglong2*)(hb + k * 16 + 4);
            float4 ua = *(const float4*)(ubp + k * 32);
            float4 ubv = *(const float4*)(ubp + k * 32 + 4);
            unsigned long long hh[4] = { hpa.x, hpa.y, hpb.x, hpb.y };
            unsigned long long uu8[8] = {
                dup2(ua.x), dup2(ua.y), dup2(ua.z), dup2(ua.w),
                dup2(ubv.x), dup2(ubv.y), dup2(ubv.z), dup2(ubv.w)
            };
#pragma unroll
            for (int c = 0; c < 8; c++)
#pragma unroll
                for (int p = 0; p < 4; p++)
                    fma2(acc[c * 4 + p], hh[p], uu8[c]);
        }
        __syncthreads();

#pragma unroll
        for (int c = 0; c < 8; c++)
#pragma unroll
            for (int p = 0; p < 4; p++) {
                float lo, hi;
                unpack2(acc[c * 4 + p], lo, hi);
                red[kc * RED_STRIDE + (c * 8 + 2 * p) * 8 + cgbh]     = lo;
                red[kc * RED_STRIDE + (c * 8 + 2 * p + 1) * 8 + cgbh] = hi;
            }
        __syncthreads();

#pragma unroll
        for (int r = 0; r < 2; r++) {
            int s   = tid + r * 256;
            int i8j = s >> 3, cb = s & 7;
            int i   = i8j >> 3, j = i8j & 7;
            int cg2 = cb >> 1, bh2 = cb & 1;
            int cc  = cg2 * 8 + i;
            int b   = bh2 * 8 + j;
            float v = 0.f;
#pragma unroll
            for (int q = 0; q < 32; q++) v += red[q * RED_STRIDE + s];
            int g = cc >> 3, ul = cc & 7;
            int uu = ub + ul;
            float xv = (uu < U)
                ? __ldg(&xg[((size_t)b * T_SEQ + t) * N4 + (size_t)g * U + uu]) : 0.f;
            gat[cc * 16 + b] = v + xv;
        }
        __syncthreads();

        if (tid < 128) {
            int b = tid & 15, ul = tid >> 4;
            int uu = ub + ul;
            if (uu < U) {
                float iv = gat[(0 * 8 + ul) * 16 + b];
                float fv = gat[(1 * 8 + ul) * 16 + b];
                float cgv = gat[(2 * 8 + ul) * 16 + b];
                float ov = gat[(3 * 8 + ul) * 16 + b];
                iv = 1.f / (1.f + __expf(-iv));
                fv = 1.f / (1.f + __expf(-fv));
                ov = 1.f / (1.f + __expf(-ov));
                cgv = tanhf(cgv);
                float cold = g_c[uu * 16 + b];
                float cn = fv * cold + iv * cgv;
                float hv = ov * tanhf(cn);
                g_c[uu * 16 + b] = cn;
                hn[uu * 16 + b] = hv;
                xout[((size_t)b * T_SEQ + t) * ostride + uu] = __float2bfloat16(hv);
            }
        }
        gen++;
        grid_sync(gen * NCTA);
    }
}

// ---------------- online 2-pass row softmax ----------------
__global__ __launch_bounds__(256) void softmax_k(float* __restrict__ out, int N) {
    int m = blockIdx.x;
    float* row = out + (size_t)m * N;
    __shared__ float sm_[8], ss_[8];
    __shared__ float fm, fs;
    int tid = threadIdx.x, w = tid >> 5, ln = tid & 31;

    float mx = -3.4e38f, s = 0.f;
    for (int i = tid; i < N; i += 256) {
        float v = row[i];
        float nm = fmaxf(mx, v);
        s = s * __expf(mx - nm) + __expf(v - nm);
        mx = nm;
    }
#pragma unroll
    for (int o = 16; o; o >>= 1) {
        float om = __shfl_xor_sync(0xffffffffu, mx, o);
        float os = __shfl_xor_sync(0xffffffffu, s, o);
        float nm = fmaxf(mx, om);
        s = s * __expf(mx - nm) + os * __expf(om - nm);
        mx = nm;
    }
    if (!ln) { sm_[w] = mx; ss_[w] = s; }
    __syncthreads();
    if (tid == 0) {
        float M2 = sm_[0], S2 = ss_[0];
#pragma unroll
        for (int q = 1; q < 8; q++) {
            float nm = fmaxf(M2, sm_[q]);
            S2 = S2 * __expf(M2 - nm) + ss_[q] * __expf(sm_[q] - nm);
            M2 = nm;
        }
        fm = M2; fs = 1.f / S2;
    }
    __syncthreads();
    float MM = fm, IS = fs;
    for (int i = tid; i < N; i += 256) row[i] = __expf(row[i] - MM) * IS;
}

// ---------------- launch ----------------
extern "C" void kernel_launch(void* const* d_in, const int* in_sizes, int n_in,
                              void* d_out, int out_size)
{
    (void)in_sizes; (void)n_in; (void)out_size;
    const int*   tok = (const int*)d_in[0];
    const float* emb = (const float*)d_in[1];
    const float* W0  = (const float*)d_in[2];
    const float* U0  = (const float*)d_in[3];
    const float* b0  = (const float*)d_in[4];
    const float* W1  = (const float*)d_in[5];
    const float* U1  = (const float*)d_in[6];
    const float* b1  = (const float*)d_in[7];
    const float* W2  = (const float*)d_in[8];
    const float* U2  = (const float*)d_in[9];
    const float* b2  = (const float*)d_in[10];
    float* out = (float*)d_out;

    float* xg;
    __nv_bfloat16 *ab0, *ab1, *ab2, *ab3, *w0t, *w1t, *w2t, *embb;
    cudaGetSymbolAddress((void**)&xg, g_xg);
    cudaGetSymbolAddress((void**)&ab0, g_ab0);
    cudaGetSymbolAddress((void**)&ab1, g_ab1);
    cudaGetSymbolAddress((void**)&ab2, g_ab2);
    cudaGetSymbolAddress((void**)&ab3, g_ab3);
    cudaGetSymbolAddress((void**)&w0t, g_w0t);
    cudaGetSymbolAddress((void**)&w1t, g_w1t);
    cudaGetSymbolAddress((void**)&w2t, g_w2t);
    cudaGetSymbolAddress((void**)&embb, g_embb);

    auto smem_for = [](int U) {
        int hreg = U * 16 > RED_FLOATS ? U * 16 : RED_FLOATS;
        return (U * 32 + hreg) * 4;
    };
    const int SMEM_BIG   = smem_for(NHID);
    const int SMEM_SMALL = smem_for(NINP);
    cudaFuncSetAttribute(lstm_k<NHID, 144>, cudaFuncAttributeMaxDynamicSharedMemorySize, SMEM_BIG);
    cudaFuncSetAttribute(lstm_k<NINP, 50>,  cudaFuncAttributeMaxDynamicSharedMemorySize, SMEM_SMALL);
    cudaFuncSetAttribute(bf16_gemm_k<true>,  cudaFuncAttributeMaxDynamicSharedMemorySize, GEMM_SMEM);
    cudaFuncSetAttribute(bf16_gemm_k<false>, cudaFuncAttributeMaxDynamicSharedMemorySize, GEMM_SMEM);

    // 0) prep: bf16 operand buffers + pad zeroing
    convert_emb_k<<<VOCABP1, 256>>>(emb, embb);
    transpose_bf_k<<<dim3((4 * NHID + 31) / 32, (KP_400 + 31) / 32), 256>>>(
        W0, w0t, NINP, 4 * NHID, KP_400);
    transpose_bf_k<<<dim3((4 * NHID + 31) / 32, (KP_1150 + 31) / 32), 256>>>(
        W1, w1t, NHID, 4 * NHID, KP_1150);
    transpose_bf_k<<<dim3((4 * NINP + 31) / 32, (KP_1150 + 31) / 32), 256>>>(
        W2, w2t, NHID, 4 * NINP, KP_1150);
    zeropad_k<<<(M_TOK + 255) / 256, 256>>>(ab1, ab2, ab3);

    // 1) embedding (bf16 K-major, padded)
    embed_bf_k<<<M_TOK, 128>>>(tok, embb, ab0);

    // 2) layer 0
    bf16_gemm_k<true><<<dim3((4 * NHID + 127) / 128, M_TOK / 128), 256, GEMM_SMEM>>>(
        ab0, w0t, b0, xg, M_TOK, 4 * NHID, KP_400);
    bar_reset_k<<<1, 1>>>();
    lstm_k<NHID, 144><<<144, 256, SMEM_BIG>>>(U0, xg, ab1, KP_1150);

    // 3) layer 1
    bf16_gemm_k<true><<<dim3((4 * NHID + 127) / 128, M_TOK / 128), 256, GEMM_SMEM>>>(
        ab1, w1t, b1, xg, M_TOK, 4 * NHID, KP_1150);
    bar_reset_k<<<1, 1>>>();
    lstm_k<NHID, 144><<<144, 256, SMEM_BIG>>>(U1, xg, ab2, KP_1150);

    // 4) layer 2
    bf16_gemm_k<true><<<dim3((4 * NINP + 127) / 128, M_TOK / 128), 256, GEMM_SMEM>>>(
        ab2, w2t, b2, xg, M_TOK, 4 * NINP, KP_1150);
    bar_reset_k<<<1, 1>>>();
    lstm_k<NINP, 50><<<50, 256, SMEM_SMALL>>>(U2, xg, ab3, KP_400);

    // 5) tied decode straight into d_out
    bf16_gemm_k<false><<<dim3((VOCABP1 + 127) / 128, M_TOK / 128), 256, GEMM_SMEM>>>(
        ab3, embb, nullptr, out, M_TOK, VOCABP1, KP_400);

    // 6) in-place softmax
    softmax_k<<<M_TOK, 256>>>(out, VOCABP1);
}

// round 11
// speedup vs baseline: 3.7190x; 1.6396x over previous
#include <cuda_runtime.h>
#include <cuda_bf16.h>
#include <cstdint>
#include <math.h>

#define T_SEQ   256
#define BATCH   16
#define NINP    400
#define NHID    1150
#define VOCABP1 33279
#define M_TOK   (BATCH * T_SEQ)   // 4096

#define KP_400  448
#define KP_1150 1152

// ---------------- scratch (static device globals; no allocation) ----------------
__device__ float g_xg[(size_t)M_TOK * 4 * NHID];           // gate preactivations
__device__ __nv_bfloat16 g_hb[2][16 * 1160];               // h ping-pong, [b][u], SH stride
__device__ unsigned g_bar;

__device__ __nv_bfloat16 g_ab0[(size_t)M_TOK * KP_400];
__device__ __nv_bfloat16 g_ab1[(size_t)M_TOK * KP_1150];
__device__ __nv_bfloat16 g_ab2[(size_t)M_TOK * KP_1150];
__device__ __nv_bfloat16 g_ab3[(size_t)M_TOK * KP_400];
__device__ __nv_bfloat16 g_w0t[(size_t)4600 * KP_400];
__device__ __nv_bfloat16 g_w1t[(size_t)4600 * KP_1150];
__device__ __nv_bfloat16 g_w2t[(size_t)1600 * KP_1150];
__device__ __nv_bfloat16 g_embb[(size_t)VOCABP1 * KP_400];

// ---------------- helpers ----------------
__device__ __forceinline__ uint32_t smem_to_u32(const void* p) {
    uint32_t a;
    asm("{ .reg .u64 t; cvta.to.shared.u64 t, %1; cvt.u32.u64 %0, t; }"
        : "=r"(a) : "l"(p));
    return a;
}
#define SMEM_SWIZZLE_128B(b) ((b) ^ (((b) >> 3) & 0x70))

#define MMA_BF16(d, a, b)                                                     \
    asm volatile("mma.sync.aligned.m16n8k16.row.col.f32.bf16.bf16.f32 "      \
                 "{%0,%1,%2,%3}, {%4,%5,%6,%7}, {%8,%9}, {%0,%1,%2,%3};"      \
                 : "+f"(d[0]), "+f"(d[1]), "+f"(d[2]), "+f"(d[3])             \
                 : "r"(a[0]), "r"(a[1]), "r"(a[2]), "r"(a[3]),                \
                   "r"(b[0]), "r"(b[1]))

// ---------------- grid barrier ----------------
__device__ __forceinline__ void grid_sync(unsigned target) {
    __syncthreads();
    if (threadIdx.x == 0) {
        __threadfence();
        atomicAdd(&g_bar, 1u);
        while (*(volatile unsigned*)&g_bar < target) { __nanosleep(40); }
        __threadfence();
    }
    __syncthreads();
}
__global__ void bar_reset_k() { g_bar = 0u; }

// ---------------- prep kernels ----------------
__global__ __launch_bounds__(256) void transpose_bf_k(
    const float* __restrict__ W, __nv_bfloat16* __restrict__ Wt,
    int K, int N, int Kpad)
{
    __shared__ float tile[32][33];
    int n0 = blockIdx.x * 32, k0 = blockIdx.y * 32;
    int tx = threadIdx.x & 31, ty = threadIdx.x >> 5;
    for (int i = ty; i < 32; i += 8) {
        int k = k0 + i, n = n0 + tx;
        tile[i][tx] = (k < K && n < N) ? W[(size_t)k * N + n] : 0.f;
    }
    __syncthreads();
    for (int i = ty; i < 32; i += 8) {
        int n = n0 + i, k = k0 + tx;
        if (n < N && k < Kpad)
            Wt[(size_t)n * Kpad + k] = __float2bfloat16(tile[tx][i]);
    }
}

__global__ __launch_bounds__(256) void convert_emb_k(
    const float* __restrict__ emb, __nv_bfloat16* __restrict__ out)
{
    int r = blockIdx.x;
    for (int c = threadIdx.x; c < KP_400; c += 256)
        out[(size_t)r * KP_400 + c] =
            (c < NINP) ? __float2bfloat16(emb[(size_t)r * NINP + c]) : __nv_bfloat16(0.f);
}

__global__ __launch_bounds__(256) void zeropad_k(
    __nv_bfloat16* a1, __nv_bfloat16* a2, __nv_bfloat16* a3)
{
    int m = blockIdx.x * 256 + threadIdx.x;
    if (m < M_TOK) {
        a1[(size_t)m * KP_1150 + 1150] = __nv_bfloat16(0.f);
        a1[(size_t)m * KP_1150 + 1151] = __nv_bfloat16(0.f);
        a2[(size_t)m * KP_1150 + 1150] = __nv_bfloat16(0.f);
        a2[(size_t)m * KP_1150 + 1151] = __nv_bfloat16(0.f);
        for (int c = NINP; c < KP_400; c++)
            a3[(size_t)m * KP_400 + c] = __nv_bfloat16(0.f);
    }
}

__global__ void embed_bf_k(const int* __restrict__ tok,
                           const __nv_bfloat16* __restrict__ embb,
                           __nv_bfloat16* __restrict__ x0) {
    int m = blockIdx.x;
    int t = tok[m];
    const uint4* src = (const uint4*)(embb + (size_t)t * KP_400);
    uint4* dst = (uint4*)(x0 + (size_t)m * KP_400);
    for (int i = threadIdx.x; i < KP_400 * 2 / 16; i += blockDim.x) dst[i] = src[i];
}

// ================= bf16 GEMM (unchanged from R10) ================================
#define GSTAGES 3
#define GEMM_SMEM (GSTAGES * 32768)

template<bool BIAS>
__global__ __launch_bounds__(256) void bf16_gemm_k(
    const __nv_bfloat16* __restrict__ A, const __nv_bfloat16* __restrict__ B,
    const float* __restrict__ bias, float* __restrict__ C,
    int M, int N, int Kpad)
{
    extern __shared__ char smem[];
    const uint32_t sbase = smem_to_u32(smem);

    const int tid  = threadIdx.x;
    const int wid  = tid >> 5;
    const int lane = tid & 31;
    const int bm   = blockIdx.y * 128;
    const int bn   = blockIdx.x * 128;
    const int wm   = (wid >> 2) * 64;
    const int wn   = (wid & 3) * 32;

    const int lrow  = tid >> 1;
    const int lhalf = tid & 1;
    const __nv_bfloat16* Asrc = A + (size_t)(bm + lrow) * Kpad + lhalf * 32;
    const int gnrow = bn + lrow;
    const __nv_bfloat16* Bsrc = B + (size_t)gnrow * Kpad + lhalf * 32;
    const int bvalid = (gnrow < N) ? 16 : 0;

    const int lm16 = lane & 15;
    const int lk16 = lane >> 4;
    const int ln8  = lane & 7;
    const int lkb  = (lane >> 3) & 1;

    float acc[4][4][4];
#pragma unroll
    for (int mf = 0; mf < 4; mf++)
#pragma unroll
        for (int nf = 0; nf < 4; nf++)
#pragma unroll
            for (int i = 0; i < 4; i++) acc[mf][nf][i] = 0.f;

    auto load_tile = [&](int stage, int kt) {
        uint32_t sa = sbase + stage * 32768;
        uint32_t sb = sa + 16384;
        const __nv_bfloat16* ap = Asrc + kt * 64;
        const __nv_bfloat16* bp = Bsrc + kt * 64;
#pragma unroll
        for (int j = 0; j < 4; j++) {
            uint32_t off = SMEM_SWIZZLE_128B((uint32_t)(lrow * 128 + lhalf * 64 + j * 16));
            asm volatile("cp.async.cg.shared.global [%0], [%1], 16;"
                         :: "r"(sa + off), "l"(ap + j * 8));
            asm volatile("cp.async.cg.shared.global [%0], [%1], 16, %2;"
                         :: "r"(sb + off), "l"(bp + j * 8), "r"(bvalid));
        }
    };

    const int nkt = Kpad >> 6;

#pragma unroll
    for (int s = 0; s < GSTAGES - 1; s++) {
        load_tile(s, s);
        asm volatile("cp.async.commit_group;" ::: "memory");
    }

    for (int kt = 0; kt < nkt; kt++) {
        if (kt + GSTAGES - 1 < nkt)
            load_tile((kt + GSTAGES - 1) % GSTAGES, kt + GSTAGES - 1);
        asm volatile("cp.async.commit_group;" ::: "memory");
        asm volatile("cp.async.wait_group %0;" :: "n"(GSTAGES - 1) : "memory");
        __syncthreads();

        uint32_t sa = sbase + (kt % GSTAGES) * 32768;
        uint32_t sb = sa + 16384;
#pragma unroll
        for (int s = 0; s < 4; s++) {
            uint32_t af[4][4], bfr[4][2];
#pragma unroll
            for (int mf = 0; mf < 4; mf++) {
                uint32_t off = (uint32_t)((wm + mf * 16 + lm16) * 128 + s * 32 + lk16 * 16);
                uint32_t ad = sa + SMEM_SWIZZLE_128B(off);
                asm volatile("ldmatrix.sync.aligned.m8n8.x4.shared.b16 "
                             "{%0,%1,%2,%3}, [%4];"
                             : "=r"(af[mf][0]), "=r"(af[mf][1]),
                               "=r"(af[mf][2]), "=r"(af[mf][3]) : "r"(ad));
            }
#pragma unroll
            for (int nf = 0; nf < 4; nf++) {
                uint32_t off = (uint32_t)((wn + nf * 8 + ln8) * 128 + s * 32 + lkb * 16);
                uint32_t ad = sb + SMEM_SWIZZLE_128B(off);
                asm volatile("ldmatrix.sync.aligned.m8n8.x2.shared.b16 "
                             "{%0,%1}, [%2];"
                             : "=r"(bfr[nf][0]), "=r"(bfr[nf][1]) : "r"(ad));
            }
#pragma unroll
            for (int mf = 0; mf < 4; mf++)
#pragma unroll
                for (int nf = 0; nf < 4; nf++)
                    MMA_BF16(acc[mf][nf], af[mf], bfr[nf]);
        }
        __syncthreads();
    }

    const int gID = lane >> 2;
    const int tg  = lane & 3;
#pragma unroll
    for (int mf = 0; mf < 4; mf++) {
        int r0 = bm + wm + mf * 16 + gID;
#pragma unroll
        for (int nf = 0; nf < 4; nf++) {
            int c0 = bn + wn + nf * 8 + tg * 2;
            float b0v = 0.f, b1v = 0.f;
            if (BIAS) {
                if (c0 < N)     b0v = bias[c0];
                if (c0 + 1 < N) b1v = bias[c0 + 1];
            }
            if (c0 < N) {
                C[(size_t)r0 * N + c0]       = acc[mf][nf][0] + b0v;
                C[(size_t)(r0 + 8) * N + c0] = acc[mf][nf][2] + b0v;
            }
            if (c0 + 1 < N) {
                C[(size_t)r0 * N + c0 + 1]       = acc[mf][nf][1] + b1v;
                C[(size_t)(r0 + 8) * N + c0 + 1] = acc[mf][nf][3] + b1v;
            }
        }
    }
}

// ============== tensor-core persistent LSTM recurrence ==========================
// grid = NCTA co-resident CTAs; CTA owns 8 units -> 32 gate-columns (4 n-tiles).
// U slice in smem bf16 [32][SH] (loaded once); h staged per step bf16 [16][SH]
// via cp.async from g_hb. 8 warps = 4 n-tiles x 2 k-halves; warp does
// mma.m16n8k16 over its k-tiles (2 interleaved accumulators). Cross-k reduce via
// smem (2 partials), gate exchange via smem, c state in registers of thr 0-127.
template<int U, int KPU, int NCTA>
__global__ __launch_bounds__(256) void lstm_tc_k(
    const float* __restrict__ Um,        // [U][4U] fp32
    const float* __restrict__ xg,        // [4096][4U] fp32
    __nv_bfloat16* __restrict__ xout,    // [4096][ostride] bf16
    int ostride)
{
    constexpr int N4 = 4 * U;
    constexpr int KT = KPU / 16;         // k-tiles of 16
    constexpr int SH = KPU + 8;          // padded row stride (elements)

    extern __shared__ char smraw[];
    const uint32_t ubase = smem_to_u32(smraw);            // U_s bf16 [32][SH]
    const uint32_t hbase = ubase + 32 * SH * 2;           // h_s bf16 [16][SH]
    float* red = (float*)(smraw + 32 * SH * 2 + 16 * SH * 2);   // [4][128]
    float* gat = red + 512;                                      // [4][128]
    __nv_bfloat16* U_s = (__nv_bfloat16*)smraw;

    const int tid  = threadIdx.x;
    const int wid  = tid >> 5;
    const int lane = tid & 31;
    const int nt   = wid & 3;            // gate tile (= gate index)
    const int kh   = wid >> 2;           // k-half
    const int lm16 = lane & 15;
    const int lk16 = lane >> 4;
    const int ln8  = lane & 7;
    const int lkb  = (lane >> 3) & 1;
    const int gID  = lane >> 2;
    const int tg   = lane & 3;
    const int ub   = blockIdx.x * 8;

    // one-time: U slice -> smem bf16 (zero for k>=U or invalid unit)
    for (int idx = tid; idx < 32 * KPU; idx += 256) {
        int k = idx >> 5, cc = idx & 31;
        int g = cc >> 3, ul = cc & 7;
        int uu = ub + ul;
        float v = (k < U && uu < U) ? Um[(size_t)k * N4 + (size_t)g * U + uu] : 0.f;
        U_s[cc * SH + k] = __float2bfloat16(v);
    }
    // zero h ping-pong (global)
    for (int idx = blockIdx.x * 256 + tid; idx < 2 * 16 * SH; idx += NCTA * 256)
        ((__nv_bfloat16*)g_hb)[idx] = __nv_bfloat16(0.f);

    float creg = 0.f;
    unsigned gen = 1;
    grid_sync(gen * NCTA);

    const uint32_t aaddr0 = hbase + lm16 * (SH * 2) + lk16 * 16;
    const uint32_t baddr0 = ubase + (nt * 8 + ln8) * (SH * 2) + lkb * 16;

    for (int t = 0; t < T_SEQ; ++t) {
        // stage h (bf16) into smem: flat copy 16*SH*2 bytes
        {
            const char* src = (const char*)&g_hb[t & 1][0];
            for (int i = tid; i < 2 * SH; i += 256) {
                asm volatile("cp.async.cg.shared.global [%0], [%1], 16;"
                             :: "r"(hbase + i * 16), "l"(src + i * 16));
            }
            asm volatile("cp.async.commit_group;" ::: "memory");
            asm volatile("cp.async.wait_group 0;" ::: "memory");
            __syncthreads();
        }

        float accA[4] = {0.f, 0.f, 0.f, 0.f};
        float accB[4] = {0.f, 0.f, 0.f, 0.f};
#pragma unroll
        for (int kt = kh; kt < KT; kt += 2) {
            uint32_t a[4], b[2];
            asm volatile("ldmatrix.sync.aligned.m8n8.x4.shared.b16 "
                         "{%0,%1,%2,%3}, [%4];"
                         : "=r"(a[0]), "=r"(a[1]), "=r"(a[2]), "=r"(a[3])
                         : "r"(aaddr0 + kt * 32));
            asm volatile("ldmatrix.sync.aligned.m8n8.x2.shared.b16 "
                         "{%0,%1}, [%2];"
                         : "=r"(b[0]), "=r"(b[1])
                         : "r"(baddr0 + kt * 32));
            if ((kt >> 1) & 1) { MMA_BF16(accB, a, b); }
            else               { MMA_BF16(accA, a, b); }
        }
#pragma unroll
        for (int i = 0; i < 4; i++) accA[i] += accB[i];

        // cross-k reduce: kh=1 writes partials, kh=0 adds + xg, writes gates
        const int i00 = nt * 128 + gID * 8 + tg * 2;        // (b=gID,  ul=tg*2)
        const int i10 = nt * 128 + (gID + 8) * 8 + tg * 2;  // (b=gID+8,ul=tg*2)
        if (kh == 1) {
            red[i00]     = accA[0];
            red[i00 + 1] = accA[1];
            red[i10]     = accA[2];
            red[i10 + 1] = accA[3];
        }
        __syncthreads();
        if (kh == 0) {
            accA[0] += red[i00];
            accA[1] += red[i00 + 1];
            accA[2] += red[i10];
            accA[3] += red[i10 + 1];
            const int uu0 = ub + tg * 2, uu1 = uu0 + 1;
            const float* xr0 = xg + ((size_t)gID * T_SEQ + t) * N4 + (size_t)nt * U;
            const float* xr1 = xg + ((size_t)(gID + 8) * T_SEQ + t) * N4 + (size_t)nt * U;
            if (uu0 < U) { accA[0] += __ldg(&xr0[uu0]); accA[2] += __ldg(&xr1[uu0]); }
            if (uu1 < U) { accA[1] += __ldg(&xr0[uu1]); accA[3] += __ldg(&xr1[uu1]); }
            gat[i00]     = accA[0];
            gat[i00 + 1] = accA[1];
            gat[i10]     = accA[2];
            gat[i10 + 1] = accA[3];
        }
        __syncthreads();

        // gate math + state update; c in registers (threads 0-127)
        if (tid < 128) {
            int b = tid >> 3, ul = tid & 7;
            int uu = ub + ul;
            float iv  = gat[0 * 128 + tid];
            float fv  = gat[1 * 128 + tid];
            float cgv = gat[2 * 128 + tid];
            float ov  = gat[3 * 128 + tid];
            iv = 1.f / (1.f + __expf(-iv));
            fv = 1.f / (1.f + __expf(-fv));
            ov = 1.f / (1.f + __expf(-ov));
            cgv = tanhf(cgv);
            creg = fv * creg + iv * cgv;
            float hv = ov * tanhf(creg);
            if (uu < U) {
                __nv_bfloat16 hb = __float2bfloat16(hv);
                g_hb[(t & 1) ^ 1][b * SH + uu] = hb;
                xout[((size_t)b * T_SEQ + t) * ostride + uu] = hb;
            }
            __threadfence();
        }
        gen++;
        grid_sync(gen * NCTA);
    }
}

// ---------------- online row softmax ----------------
__global__ __launch_bounds__(256) void softmax_k(float* __restrict__ out, int N) {
    int m = blockIdx.x;
    float* row = out + (size_t)m * N;
    __shared__ float sm_[8], ss_[8];
    __shared__ float fm, fs;
    int tid = threadIdx.x, w = tid >> 5, ln = tid & 31;

    float mx = -3.4e38f, s = 0.f;
    for (int i = tid; i < N; i += 256) {
        float v = row[i];
        float nm = fmaxf(mx, v);
        s = s * __expf(mx - nm) + __expf(v - nm);
        mx = nm;
    }
#pragma unroll
    for (int o = 16; o; o >>= 1) {
        float om = __shfl_xor_sync(0xffffffffu, mx, o);
        float os = __shfl_xor_sync(0xffffffffu, s, o);
        float nm = fmaxf(mx, om);
        s = s * __expf(mx - nm) + os * __expf(om - nm);
        mx = nm;
    }
    if (!ln) { sm_[w] = mx; ss_[w] = s; }
    __syncthreads();
    if (tid == 0) {
        float M2 = sm_[0], S2 = ss_[0];
#pragma unroll
        for (int q = 1; q < 8; q++) {
            float nm = fmaxf(M2, sm_[q]);
            S2 = S2 * __expf(M2 - nm) + ss_[q] * __expf(sm_[q] - nm);
            M2 = nm;
        }
        fm = M2; fs = 1.f / S2;
    }
    __syncthreads();
    float MM = fm, IS = fs;
    for (int i = tid; i < N; i += 256) row[i] = __expf(row[i] - MM) * IS;
}

// ---------------- launch ----------------
extern "C" void kernel_launch(void* const* d_in, const int* in_sizes, int n_in,
                              void* d_out, int out_size)
{
    (void)in_sizes; (void)n_in; (void)out_size;
    const int*   tok = (const int*)d_in[0];
    const float* emb = (const float*)d_in[1];
    const float* W0  = (const float*)d_in[2];
    const float* U0  = (const float*)d_in[3];
    const float* b0  = (const float*)d_in[4];
    const float* W1  = (const float*)d_in[5];
    const float* U1  = (const float*)d_in[6];
    const float* b1  = (const float*)d_in[7];
    const float* W2  = (const float*)d_in[8];
    const float* U2  = (const float*)d_in[9];
    const float* b2  = (const float*)d_in[10];
    float* out = (float*)d_out;

    float* xg;
    __nv_bfloat16 *ab0, *ab1, *ab2, *ab3, *w0t, *w1t, *w2t, *embb;
    cudaGetSymbolAddress((void**)&xg, g_xg);
    cudaGetSymbolAddress((void**)&ab0, g_ab0);
    cudaGetSymbolAddress((void**)&ab1, g_ab1);
    cudaGetSymbolAddress((void**)&ab2, g_ab2);
    cudaGetSymbolAddress((void**)&ab3, g_ab3);
    cudaGetSymbolAddress((void**)&w0t, g_w0t);
    cudaGetSymbolAddress((void**)&w1t, g_w1t);
    cudaGetSymbolAddress((void**)&w2t, g_w2t);
    cudaGetSymbolAddress((void**)&embb, g_embb);

    // dynamic smem: U_s + h_s + red + gat
    const int SMEM_BIG   = 32 * 1160 * 2 + 16 * 1160 * 2 + 4096;   // 115456
    const int SMEM_SMALL = 32 * 408 * 2 + 16 * 408 * 2 + 4096;     // 43264
    cudaFuncSetAttribute((const void*)lstm_tc_k<NHID, 1152, 144>,
                         cudaFuncAttributeMaxDynamicSharedMemorySize, SMEM_BIG);
    cudaFuncSetAttribute((const void*)lstm_tc_k<NINP, 400, 50>,
                         cudaFuncAttributeMaxDynamicSharedMemorySize, SMEM_SMALL);
    cudaFuncSetAttribute(bf16_gemm_k<true>,  cudaFuncAttributeMaxDynamicSharedMemorySize, GEMM_SMEM);
    cudaFuncSetAttribute(bf16_gemm_k<false>, cudaFuncAttributeMaxDynamicSharedMemorySize, GEMM_SMEM);

    // 0) prep
    convert_emb_k<<<VOCABP1, 256>>>(emb, embb);
    transpose_bf_k<<<dim3((4 * NHID + 31) / 32, (KP_400 + 31) / 32), 256>>>(
        W0, w0t, NINP, 4 * NHID, KP_400);
    transpose_bf_k<<<dim3((4 * NHID + 31) / 32, (KP_1150 + 31) / 32), 256>>>(
        W1, w1t, NHID, 4 * NHID, KP_1150);
    transpose_bf_k<<<dim3((4 * NINP + 31) / 32, (KP_1150 + 31) / 32), 256>>>(
        W2, w2t, NHID, 4 * NINP, KP_1150);
    zeropad_k<<<(M_TOK + 255) / 256, 256>>>(ab1, ab2, ab3);

    // 1) embedding
    embed_bf_k<<<M_TOK, 128>>>(tok, embb, ab0);

    // 2) layer 0
    bf16_gemm_k<true><<<dim3((4 * NHID + 127) / 128, M_TOK / 128), 256, GEMM_SMEM>>>(
        ab0, w0t, b0, xg, M_TOK, 4 * NHID, KP_400);
    bar_reset_k<<<1, 1>>>();
    lstm_tc_k<NHID, 1152, 144><<<144, 256, SMEM_BIG>>>(U0, xg, ab1, KP_1150);

    // 3) layer 1
    bf16_gemm_k<true><<<dim3((4 * NHID + 127) / 128, M_TOK / 128), 256, GEMM_SMEM>>>(
        ab1, w1t, b1, xg, M_TOK, 4 * NHID, KP_1150);
    bar_reset_k<<<1, 1>>>();
    lstm_tc_k<NHID, 1152, 144><<<144, 256, SMEM_BIG>>>(U1, xg, ab2, KP_1150);

    // 4) layer 2
    bf16_gemm_k<true><<<dim3((4 * NINP + 127) / 128, M_TOK / 128), 256, GEMM_SMEM>>>(
        ab2, w2t, b2, xg, M_TOK, 4 * NINP, KP_1150);
    bar_reset_k<<<1, 1>>>();
    lstm_tc_k<NINP, 400, 50><<<50, 256, SMEM_SMALL>>>(U2, xg, ab3, KP_400);

    // 5) tied decode straight into d_out
    bf16_gemm_k<false><<<dim3((VOCABP1 + 127) / 128, M_TOK / 128), 256, GEMM_SMEM>>>(
        ab3, embb, nullptr, out, M_TOK, VOCABP1, KP_400);

    // 6) in-place softmax
    softmax_k<<<M_TOK, 256>>>(out, VOCABP1);
}

// round 12
// speedup vs baseline: 3.7719x; 1.0142x over previous
#include <cuda_runtime.h>
#include <cuda_bf16.h>
#include <cstdint>
#include <math.h>

#define T_SEQ   256
#define BATCH   16
#define NINP    400
#define NHID    1150
#define VOCABP1 33279
#define M_TOK   (BATCH * T_SEQ)   // 4096

#define KP_400  448
#define KP_1150 1152

// ---------------- scratch (static device globals; no allocation) ----------------
__device__ float g_xg[(size_t)M_TOK * 4 * NHID];           // gate preactivations
__device__ __nv_bfloat16 g_hb[2][16 * 1160];               // h ping-pong, [b][u], SH stride
__device__ unsigned g_bar;

__device__ __nv_bfloat16 g_ab0[(size_t)M_TOK * KP_400];
__device__ __nv_bfloat16 g_ab1[(size_t)M_TOK * KP_1150];
__device__ __nv_bfloat16 g_ab2[(size_t)M_TOK * KP_1150];
__device__ __nv_bfloat16 g_ab3[(size_t)M_TOK * KP_400];
__device__ __nv_bfloat16 g_w0t[(size_t)4600 * KP_400];
__device__ __nv_bfloat16 g_w1t[(size_t)4600 * KP_1150];
__device__ __nv_bfloat16 g_w2t[(size_t)1600 * KP_1150];
__device__ __nv_bfloat16 g_embb[(size_t)VOCABP1 * KP_400];

// ---------------- helpers ----------------
__device__ __forceinline__ uint32_t smem_to_u32(const void* p) {
    uint32_t a;
    asm("{ .reg .u64 t; cvta.to.shared.u64 t, %1; cvt.u32.u64 %0, t; }"
        : "=r"(a) : "l"(p));
    return a;
}
#define SMEM_SWIZZLE_128B(b) ((b) ^ (((b) >> 3) & 0x70))

#define MMA_BF16(d, a, b)                                                     \
    asm volatile("mma.sync.aligned.m16n8k16.row.col.f32.bf16.bf16.f32 "      \
                 "{%0,%1,%2,%3}, {%4,%5,%6,%7}, {%8,%9}, {%0,%1,%2,%3};"      \
                 : "+f"(d[0]), "+f"(d[1]), "+f"(d[2]), "+f"(d[3])             \
                 : "r"(a[0]), "r"(a[1]), "r"(a[2]), "r"(a[3]),                \
                   "r"(b[0]), "r"(b[1]))

// ---------------- grid barrier ----------------
__device__ __forceinline__ void grid_sync(unsigned target) {
    __syncthreads();
    if (threadIdx.x == 0) {
        __threadfence();
        atomicAdd(&g_bar, 1u);
        while (*(volatile unsigned*)&g_bar < target) { __nanosleep(40); }
        __threadfence();
    }
    __syncthreads();
}
__global__ void bar_reset_k() { g_bar = 0u; }

// ---------------- prep kernels ----------------
__global__ __launch_bounds__(256) void transpose_bf_k(
    const float* __restrict__ W, __nv_bfloat16* __restrict__ Wt,
    int K, int N, int Kpad)
{
    __shared__ float tile[32][33];
    int n0 = blockIdx.x * 32, k0 = blockIdx.y * 32;
    int tx = threadIdx.x & 31, ty = threadIdx.x >> 5;
    for (int i = ty; i < 32; i += 8) {
        int k = k0 + i, n = n0 + tx;
        tile[i][tx] = (k < K && n < N) ? W[(size_t)k * N + n] : 0.f;
    }
    __syncthreads();
    for (int i = ty; i < 32; i += 8) {
        int n = n0 + i, k = k0 + tx;
        if (n < N && k < Kpad)
            Wt[(size_t)n * Kpad + k] = __float2bfloat16(tile[tx][i]);
    }
}

__global__ __launch_bounds__(256) void convert_emb_k(
    const float* __restrict__ emb, __nv_bfloat16* __restrict__ out)
{
    int r = blockIdx.x;
    for (int c = threadIdx.x; c < KP_400; c += 256)
        out[(size_t)r * KP_400 + c] =
            (c < NINP) ? __float2bfloat16(emb[(size_t)r * NINP + c]) : __nv_bfloat16(0.f);
}

__global__ __launch_bounds__(256) void zeropad_k(
    __nv_bfloat16* a1, __nv_bfloat16* a2, __nv_bfloat16* a3)
{
    int m = blockIdx.x * 256 + threadIdx.x;
    if (m < M_TOK) {
        a1[(size_t)m * KP_1150 + 1150] = __nv_bfloat16(0.f);
        a1[(size_t)m * KP_1150 + 1151] = __nv_bfloat16(0.f);
        a2[(size_t)m * KP_1150 + 1150] = __nv_bfloat16(0.f);
        a2[(size_t)m * KP_1150 + 1151] = __nv_bfloat16(0.f);
        for (int c = NINP; c < KP_400; c++)
            a3[(size_t)m * KP_400 + c] = __nv_bfloat16(0.f);
    }
}

__global__ void embed_bf_k(const int* __restrict__ tok,
                           const __nv_bfloat16* __restrict__ embb,
                           __nv_bfloat16* __restrict__ x0) {
    int m = blockIdx.x;
    int t = tok[m];
    const uint4* src = (const uint4*)(embb + (size_t)t * KP_400);
    uint4* dst = (uint4*)(x0 + (size_t)m * KP_400);
    for (int i = threadIdx.x; i < KP_400 * 2 / 16; i += blockDim.x) dst[i] = src[i];
}

// ================= bf16 GEMM: C[M,N] = A[M,Kpad] @ B[N,Kpad]^T (+bias) ==========
// cp.async 3-stage, ONE __syncthreads per K-tile (wait -> sync -> issue loads ->
// compute), 2 CTAs/SM, skips all-zero 16-k sub-tiles beyond Kreal.
#define GSTAGES 3
#define GEMM_SMEM (GSTAGES * 32768)

template<bool BIAS>
__global__ __launch_bounds__(256, 2) void bf16_gemm_k(
    const __nv_bfloat16* __restrict__ A, const __nv_bfloat16* __restrict__ B,
    const float* __restrict__ bias, float* __restrict__ C,
    int M, int N, int Kpad, int Kreal)
{
    extern __shared__ char smem[];
    const uint32_t sbase = smem_to_u32(smem);

    const int tid  = threadIdx.x;
    const int wid  = tid >> 5;
    const int lane = tid & 31;
    const int bm   = blockIdx.y * 128;
    const int bn   = blockIdx.x * 128;
    const int wm   = (wid >> 2) * 64;
    const int wn   = (wid & 3) * 32;

    const int lrow  = tid >> 1;
    const int lhalf = tid & 1;
    const __nv_bfloat16* Asrc = A + (size_t)(bm + lrow) * Kpad + lhalf * 32;
    const int gnrow = bn + lrow;
    const __nv_bfloat16* Bsrc = B + (size_t)gnrow * Kpad + lhalf * 32;
    const int bvalid = (gnrow < N) ? 16 : 0;

    const int lm16 = lane & 15;
    const int lk16 = lane >> 4;
    const int ln8  = lane & 7;
    const int lkb  = (lane >> 3) & 1;

    float acc[4][4][4];
#pragma unroll
    for (int mf = 0; mf < 4; mf++)
#pragma unroll
        for (int nf = 0; nf < 4; nf++)
#pragma unroll
            for (int i = 0; i < 4; i++) acc[mf][nf][i] = 0.f;

    auto load_tile = [&](int stage, int kt) {
        uint32_t sa = sbase + stage * 32768;
        uint32_t sb = sa + 16384;
        const __nv_bfloat16* ap = Asrc + kt * 64;
        const __nv_bfloat16* bp = Bsrc + kt * 64;
#pragma unroll
        for (int j = 0; j < 4; j++) {
            uint32_t off = SMEM_SWIZZLE_128B((uint32_t)(lrow * 128 + lhalf * 64 + j * 16));
            asm volatile("cp.async.cg.shared.global [%0], [%1], 16;"
                         :: "r"(sa + off), "l"(ap + j * 8));
            asm volatile("cp.async.cg.shared.global [%0], [%1], 16, %2;"
                         :: "r"(sb + off), "l"(bp + j * 8), "r"(bvalid));
        }
    };

    const int nkt = Kpad >> 6;

#pragma unroll
    for (int s = 0; s < GSTAGES - 1; s++) {
        load_tile(s, s);
        asm volatile("cp.async.commit_group;" ::: "memory");
    }

    for (int kt = 0; kt < nkt; kt++) {
        asm volatile("cp.async.wait_group %0;" :: "n"(GSTAGES - 2) : "memory");
        __syncthreads();   // all warps done with compute(kt-1); stage kt ready

        if (kt + GSTAGES - 1 < nkt) {
            load_tile((kt + GSTAGES - 1) % GSTAGES, kt + GSTAGES - 1);
            asm volatile("cp.async.commit_group;" ::: "memory");
        } else {
            asm volatile("cp.async.commit_group;" ::: "memory"); // keep group count aligned
        }

        uint32_t sa = sbase + (kt % GSTAGES) * 32768;
        uint32_t sb = sa + 16384;
#pragma unroll
        for (int s = 0; s < 4; s++) {
            if (kt * 64 + s * 16 >= Kreal) break;   // skip all-zero sub-tiles
            uint32_t af[4][4], bfr[4][2];
#pragma unroll
            for (int mf = 0; mf < 4; mf++) {
                uint32_t off = (uint32_t)((wm + mf * 16 + lm16) * 128 + s * 32 + lk16 * 16);
                uint32_t ad = sa + SMEM_SWIZZLE_128B(off);
                asm volatile("ldmatrix.sync.aligned.m8n8.x4.shared.b16 "
                             "{%0,%1,%2,%3}, [%4];"
                             : "=r"(af[mf][0]), "=r"(af[mf][1]),
                               "=r"(af[mf][2]), "=r"(af[mf][3]) : "r"(ad));
            }
#pragma unroll
            for (int nf = 0; nf < 4; nf++) {
                uint32_t off = (uint32_t)((wn + nf * 8 + ln8) * 128 + s * 32 + lkb * 16);
                uint32_t ad = sb + SMEM_SWIZZLE_128B(off);
                asm volatile("ldmatrix.sync.aligned.m8n8.x2.shared.b16 "
                             "{%0,%1}, [%2];"
                             : "=r"(bfr[nf][0]), "=r"(bfr[nf][1]) : "r"(ad));
            }
#pragma unroll
            for (int mf = 0; mf < 4; mf++)
#pragma unroll
                for (int nf = 0; nf < 4; nf++)
                    MMA_BF16(acc[mf][nf], af[mf], bfr[nf]);
        }
    }

    const int gID = lane >> 2;
    const int tg  = lane & 3;
#pragma unroll
    for (int mf = 0; mf < 4; mf++) {
        int r0 = bm + wm + mf * 16 + gID;
#pragma unroll
        for (int nf = 0; nf < 4; nf++) {
            int c0 = bn + wn + nf * 8 + tg * 2;
            float b0v = 0.f, b1v = 0.f;
            if (BIAS) {
                if (c0 < N)     b0v = bias[c0];
                if (c0 + 1 < N) b1v = bias[c0 + 1];
            }
            if (c0 < N) {
                C[(size_t)r0 * N + c0]       = acc[mf][nf][0] + b0v;
                C[(size_t)(r0 + 8) * N + c0] = acc[mf][nf][2] + b0v;
            }
            if (c0 + 1 < N) {
                C[(size_t)r0 * N + c0 + 1]       = acc[mf][nf][1] + b1v;
                C[(size_t)(r0 + 8) * N + c0 + 1] = acc[mf][nf][3] + b1v;
            }
        }
    }
}

// ============== tensor-core persistent LSTM recurrence (unchanged R11) ==========
template<int U, int KPU, int NCTA>
__global__ __launch_bounds__(256) void lstm_tc_k(
    const float* __restrict__ Um,
    const float* __restrict__ xg,
    __nv_bfloat16* __restrict__ xout,
    int ostride)
{
    constexpr int N4 = 4 * U;
    constexpr int KT = KPU / 16;
    constexpr int SH = KPU + 8;

    extern __shared__ char smraw[];
    const uint32_t ubase = smem_to_u32(smraw);
    const uint32_t hbase = ubase + 32 * SH * 2;
    float* red = (float*)(smraw + 32 * SH * 2 + 16 * SH * 2);
    float* gat = red + 512;
    __nv_bfloat16* U_s = (__nv_bfloat16*)smraw;

    const int tid  = threadIdx.x;
    const int wid  = tid >> 5;
    const int lane = tid & 31;
    const int nt   = wid & 3;
    const int kh   = wid >> 2;
    const int lm16 = lane & 15;
    const int lk16 = lane >> 4;
    const int ln8  = lane & 7;
    const int lkb  = (lane >> 3) & 1;
    const int gID  = lane >> 2;
    const int tg   = lane & 3;
    const int ub   = blockIdx.x * 8;

    for (int idx = tid; idx < 32 * KPU; idx += 256) {
        int k = idx >> 5, cc = idx & 31;
        int g = cc >> 3, ul = cc & 7;
        int uu = ub + ul;
        float v = (k < U && uu < U) ? Um[(size_t)k * N4 + (size_t)g * U + uu] : 0.f;
        U_s[cc * SH + k] = __float2bfloat16(v);
    }
    for (int idx = blockIdx.x * 256 + tid; idx < 2 * 16 * SH; idx += NCTA * 256)
        ((__nv_bfloat16*)g_hb)[idx] = __nv_bfloat16(0.f);

    float creg = 0.f;
    unsigned gen = 1;
    grid_sync(gen * NCTA);

    const uint32_t aaddr0 = hbase + lm16 * (SH * 2) + lk16 * 16;
    const uint32_t baddr0 = ubase + (nt * 8 + ln8) * (SH * 2) + lkb * 16;

    for (int t = 0; t < T_SEQ; ++t) {
        {
            const char* src = (const char*)&g_hb[t & 1][0];
            for (int i = tid; i < 2 * SH; i += 256) {
                asm volatile("cp.async.cg.shared.global [%0], [%1], 16;"
                             :: "r"(hbase + i * 16), "l"(src + i * 16));
            }
            asm volatile("cp.async.commit_group;" ::: "memory");
            asm volatile("cp.async.wait_group 0;" ::: "memory");
            __syncthreads();
        }

        float accA[4] = {0.f, 0.f, 0.f, 0.f};
        float accB[4] = {0.f, 0.f, 0.f, 0.f};
#pragma unroll
        for (int kt = kh; kt < KT; kt += 2) {
            uint32_t a[4], b[2];
            asm volatile("ldmatrix.sync.aligned.m8n8.x4.shared.b16 "
                         "{%0,%1,%2,%3}, [%4];"
                         : "=r"(a[0]), "=r"(a[1]), "=r"(a[2]), "=r"(a[3])
                         : "r"(aaddr0 + kt * 32));
            asm volatile("ldmatrix.sync.aligned.m8n8.x2.shared.b16 "
                         "{%0,%1}, [%2];"
                         : "=r"(b[0]), "=r"(b[1])
                         : "r"(baddr0 + kt * 32));
            if ((kt >> 1) & 1) { MMA_BF16(accB, a, b); }
            else               { MMA_BF16(accA, a, b); }
        }
#pragma unroll
        for (int i = 0; i < 4; i++) accA[i] += accB[i];

        const int i00 = nt * 128 + gID * 8 + tg * 2;
        const int i10 = nt * 128 + (gID + 8) * 8 + tg * 2;
        if (kh == 1) {
            red[i00]     = accA[0];
            red[i00 + 1] = accA[1];
            red[i10]     = accA[2];
            red[i10 + 1] = accA[3];
        }
        __syncthreads();
        if (kh == 0) {
            accA[0] += red[i00];
            accA[1] += red[i00 + 1];
            accA[2] += red[i10];
            accA[3] += red[i10 + 1];
            const int uu0 = ub + tg * 2, uu1 = uu0 + 1;
            const float* xr0 = xg + ((size_t)gID * T_SEQ + t) * N4 + (size_t)nt * U;
            const float* xr1 = xg + ((size_t)(gID + 8) * T_SEQ + t) * N4 + (size_t)nt * U;
            if (uu0 < U) { accA[0] += __ldg(&xr0[uu0]); accA[2] += __ldg(&xr1[uu0]); }
            if (uu1 < U) { accA[1] += __ldg(&xr0[uu1]); accA[3] += __ldg(&xr1[uu1]); }
            gat[i00]     = accA[0];
            gat[i00 + 1] = accA[1];
            gat[i10]     = accA[2];
            gat[i10 + 1] = accA[3];
        }
        __syncthreads();

        if (tid < 128) {
            int b = tid >> 3, ul = tid & 7;
            int uu = ub + ul;
            float iv  = gat[0 * 128 + tid];
            float fv  = gat[1 * 128 + tid];
            float cgv = gat[2 * 128 + tid];
            float ov  = gat[3 * 128 + tid];
            iv = 1.f / (1.f + __expf(-iv));
            fv = 1.f / (1.f + __expf(-fv));
            ov = 1.f / (1.f + __expf(-ov));
            cgv = tanhf(cgv);
            creg = fv * creg + iv * cgv;
            float hv = ov * tanhf(creg);
            if (uu < U) {
                __nv_bfloat16 hb = __float2bfloat16(hv);
                g_hb[(t & 1) ^ 1][b * SH + uu] = hb;
                xout[((size_t)b * T_SEQ + t) * ostride + uu] = hb;
            }
            __threadfence();
        }
        gen++;
        grid_sync(gen * NCTA);
    }
}

// ---------------- online row softmax ----------------
__global__ __launch_bounds__(256) void softmax_k(float* __restrict__ out, int N) {
    int m = blockIdx.x;
    float* row = out + (size_t)m * N;
    __shared__ float sm_[8], ss_[8];
    __shared__ float fm, fs;
    int tid = threadIdx.x, w = tid >> 5, ln = tid & 31;

    float mx = -3.4e38f, s = 0.f;
    for (int i = tid; i < N; i += 256) {
        float v = row[i];
        float nm = fmaxf(mx, v);
        s = s * __expf(mx - nm) + __expf(v - nm);
        mx = nm;
    }
#pragma unroll
    for (int o = 16; o; o >>= 1) {
        float om = __shfl_xor_sync(0xffffffffu, mx, o);
        float os = __shfl_xor_sync(0xffffffffu, s, o);
        float nm = fmaxf(mx, om);
        s = s * __expf(mx - nm) + os * __expf(om - nm);
        mx = nm;
    }
    if (!ln) { sm_[w] = mx; ss_[w] = s; }
    __syncthreads();
    if (tid == 0) {
        float M2 = sm_[0], S2 = ss_[0];
#pragma unroll
        for (int q = 1; q < 8; q++) {
            float nm = fmaxf(M2, sm_[q]);
            S2 = S2 * __expf(M2 - nm) + ss_[q] * __expf(sm_[q] - nm);
            M2 = nm;
        }
        fm = M2; fs = 1.f / S2;
    }
    __syncthreads();
    float MM = fm, IS = fs;
    for (int i = tid; i < N; i += 256) row[i] = __expf(row[i] - MM) * IS;
}

// ---------------- launch ----------------
extern "C" void kernel_launch(void* const* d_in, const int* in_sizes, int n_in,
                              void* d_out, int out_size)
{
    (void)in_sizes; (void)n_in; (void)out_size;
    const int*   tok = (const int*)d_in[0];
    const float* emb = (const float*)d_in[1];
    const float* W0  = (const float*)d_in[2];
    const float* U0  = (const float*)d_in[3];
    const float* b0  = (const float*)d_in[4];
    const float* W1  = (const float*)d_in[5];
    const float* U1  = (const float*)d_in[6];
    const float* b1  = (const float*)d_in[7];
    const float* W2  = (const float*)d_in[8];
    const float* U2  = (const float*)d_in[9];
    const float* b2  = (const float*)d_in[10];
    float* out = (float*)d_out;

    float* xg;
    __nv_bfloat16 *ab0, *ab1, *ab2, *ab3, *w0t, *w1t, *w2t, *embb;
    cudaGetSymbolAddress((void**)&xg, g_xg);
    cudaGetSymbolAddress((void**)&ab0, g_ab0);
    cudaGetSymbolAddress((void**)&ab1, g_ab1);
    cudaGetSymbolAddress((void**)&ab2, g_ab2);
    cudaGetSymbolAddress((void**)&ab3, g_ab3);
    cudaGetSymbolAddress((void**)&w0t, g_w0t);
    cudaGetSymbolAddress((void**)&w1t, g_w1t);
    cudaGetSymbolAddress((void**)&w2t, g_w2t);
    cudaGetSymbolAddress((void**)&embb, g_embb);

    const int SMEM_BIG   = 32 * 1160 * 2 + 16 * 1160 * 2 + 4096;   // 115456
    const int SMEM_SMALL = 32 * 408 * 2 + 16 * 408 * 2 + 4096;     // 43264
    cudaFuncSetAttribute((const void*)lstm_tc_k<NHID, 1152, 144>,
                         cudaFuncAttributeMaxDynamicSharedMemorySize, SMEM_BIG);
    cudaFuncSetAttribute((const void*)lstm_tc_k<NINP, 400, 50>,
                         cudaFuncAttributeMaxDynamicSharedMemorySize, SMEM_SMALL);
    cudaFuncSetAttribute(bf16_gemm_k<true>,  cudaFuncAttributeMaxDynamicSharedMemorySize, GEMM_SMEM);
    cudaFuncSetAttribute(bf16_gemm_k<false>, cudaFuncAttributeMaxDynamicSharedMemorySize, GEMM_SMEM);

    // 0) prep
    convert_emb_k<<<VOCABP1, 256>>>(emb, embb);
    transpose_bf_k<<<dim3((4 * NHID + 31) / 32, (KP_400 + 31) / 32), 256>>>(
        W0, w0t, NINP, 4 * NHID, KP_400);
    transpose_bf_k<<<dim3((4 * NHID + 31) / 32, (KP_1150 + 31) / 32), 256>>>(
        W1, w1t, NHID, 4 * NHID, KP_1150);
    transpose_bf_k<<<dim3((4 * NINP + 31) / 32, (KP_1150 + 31) / 32), 256>>>(
        W2, w2t, NHID, 4 * NINP, KP_1150);
    zeropad_k<<<(M_TOK + 255) / 256, 256>>>(ab1, ab2, ab3);

    // 1) embedding
    embed_bf_k<<<M_TOK, 128>>>(tok, embb, ab0);

    // 2) layer 0
    bf16_gemm_k<true><<<dim3((4 * NHID + 127) / 128, M_TOK / 128), 256, GEMM_SMEM>>>(
        ab0, w0t, b0, xg, M_TOK, 4 * NHID, KP_400, NINP);
    bar_reset_k<<<1, 1>>>();
    lstm_tc_k<NHID, 1152, 144><<<144, 256, SMEM_BIG>>>(U0, xg, ab1, KP_1150);

    // 3) layer 1
    bf16_gemm_k<true><<<dim3((4 * NHID + 127) / 128, M_TOK / 128), 256, GEMM_SMEM>>>(
        ab1, w1t, b1, xg, M_TOK, 4 * NHID, KP_1150, NHID);
    bar_reset_k<<<1, 1>>>();
    lstm_tc_k<NHID, 1152, 144><<<144, 256, SMEM_BIG>>>(U1, xg, ab2, KP_1150);

    // 4) layer 2
    bf16_gemm_k<true><<<dim3((4 * NINP + 127) / 128, M_TOK / 128), 256, GEMM_SMEM>>>(
        ab2, w2t, b2, xg, M_TOK, 4 * NINP, KP_1150, NHID);
    bar_reset_k<<<1, 1>>>();
    lstm_tc_k<NINP, 400, 50><<<50, 256, SMEM_SMALL>>>(U2, xg, ab3, KP_400);

    // 5) tied decode straight into d_out
    bf16_gemm_k<false><<<dim3((VOCABP1 + 127) / 128, M_TOK / 128), 256, GEMM_SMEM>>>(
        ab3, embb, nullptr, out, M_TOK, VOCABP1, KP_400, NINP);

    // 6) in-place softmax
    softmax_k<<<M_TOK, 256>>>(out, VOCABP1);
}

// round 13
// speedup vs baseline: 3.8470x; 1.0199x over previous
#include <cuda_runtime.h>
#include <cuda_bf16.h>
#include <cstdint>
#include <math.h>

#define T_SEQ   256
#define BATCH   16
#define NINP    400
#define NHID    1150
#define VOCABP1 33279
#define M_TOK   (BATCH * T_SEQ)   // 4096

#define KP_400  448
#define KP_1150 1152

// ---------------- scratch (static device globals; no allocation) ----------------
__device__ float g_xg[(size_t)M_TOK * 4 * NHID];           // gate preactivations
__device__ __nv_bfloat16 g_hb[2][16 * 1160];               // h ping-pong, [b][u], SH stride
__device__ unsigned g_bar;

__device__ __nv_bfloat16 g_ab0[(size_t)M_TOK * KP_400];
__device__ __nv_bfloat16 g_ab1[(size_t)M_TOK * KP_1150];
__device__ __nv_bfloat16 g_ab2[(size_t)M_TOK * KP_1150];
__device__ __nv_bfloat16 g_ab3[(size_t)M_TOK * KP_400];
__device__ __nv_bfloat16 g_w0t[(size_t)4600 * KP_400];
__device__ __nv_bfloat16 g_w1t[(size_t)4600 * KP_1150];
__device__ __nv_bfloat16 g_w2t[(size_t)1600 * KP_1150];
__device__ __nv_bfloat16 g_embb[(size_t)VOCABP1 * KP_400];

// ---------------- helpers ----------------
__device__ __forceinline__ uint32_t smem_to_u32(const void* p) {
    uint32_t a;
    asm("{ .reg .u64 t; cvta.to.shared.u64 t, %1; cvt.u32.u64 %0, t; }"
        : "=r"(a) : "l"(p));
    return a;
}
#define SMEM_SWIZZLE_128B(b) ((b) ^ (((b) >> 3) & 0x70))

#define MMA_BF16(d, a, b)                                                     \
    asm volatile("mma.sync.aligned.m16n8k16.row.col.f32.bf16.bf16.f32 "      \
                 "{%0,%1,%2,%3}, {%4,%5,%6,%7}, {%8,%9}, {%0,%1,%2,%3};"      \
                 : "+f"(d[0]), "+f"(d[1]), "+f"(d[2]), "+f"(d[3])             \
                 : "r"(a[0]), "r"(a[1]), "r"(a[2]), "r"(a[3]),                \
                   "r"(b[0]), "r"(b[1]))

// ---------------- grid barrier (tight spin, no nanosleep) ----------------
__device__ __forceinline__ void grid_sync(unsigned target) {
    __syncthreads();
    if (threadIdx.x == 0) {
        __threadfence();
        atomicAdd(&g_bar, 1u);
        while (*(volatile unsigned*)&g_bar < target) {}
        __threadfence();
    }
    __syncthreads();
}
__global__ void bar_reset_k() { g_bar = 0u; }

// ---------------- fused prep kernel (ONE launch) ----------------
// sections by blockIdx.x:
//   [0,512)            : emb fp32 [V][400] -> bf16 [V][448]
//   [512, 512+2016)    : W0 transpose  (K=400 -> Kpad 448, N=4600)
//   [2528, 2528+5184)  : W1 transpose  (K=1150 -> 1152, N=4600)
//   [7712, 7712+1800)  : W2 transpose  (K=1150 -> 1152, N=1600)
//   [9512, 9512+16)    : zero k-pad cols of ab1/ab2/ab3
#define PREP_BLOCKS 9528

__device__ __forceinline__ void transpose_tile(
    const float* __restrict__ W, __nv_bfloat16* __restrict__ Wt,
    int K, int N, int Kpad, int bt, int nyb, float (*tile)[33])
{
    int n0 = (bt / nyb) * 32, k0 = (bt % nyb) * 32;
    int tx = threadIdx.x & 31, ty = threadIdx.x >> 5;
    for (int i = ty; i < 32; i += 8) {
        int k = k0 + i, n = n0 + tx;
        tile[i][tx] = (k < K && n < N) ? W[(size_t)k * N + n] : 0.f;
    }
    __syncthreads();
    for (int i = ty; i < 32; i += 8) {
        int n = n0 + i, k = k0 + tx;
        if (n < N && k < Kpad)
            Wt[(size_t)n * Kpad + k] = __float2bfloat16(tile[tx][i]);
    }
}

__global__ __launch_bounds__(256) void prep_k(
    const float* __restrict__ emb,
    const float* __restrict__ W0, const float* __restrict__ W1,
    const float* __restrict__ W2)
{
    __shared__ float tile[32][33];
    int b = blockIdx.x;
    if (b < 512) {
        // emb convert, flat grid-stride
        const size_t tot = (size_t)VOCABP1 * KP_400;
        for (size_t idx = (size_t)b * 256 + threadIdx.x; idx < tot; idx += 512 * 256) {
            int r = (int)(idx / KP_400), c = (int)(idx % KP_400);
            g_embb[idx] = (c < NINP) ? __float2bfloat16(emb[(size_t)r * NINP + c])
                                     : __nv_bfloat16(0.f);
        }
    } else if (b < 2528) {
        transpose_tile(W0, g_w0t, NINP, 4 * NHID, KP_400, b - 512, 14, tile);
    } else if (b < 7712) {
        transpose_tile(W1, g_w1t, NHID, 4 * NHID, KP_1150, b - 2528, 36, tile);
    } else if (b < 9512) {
        transpose_tile(W2, g_w2t, NHID, 4 * NINP, KP_1150, b - 7712, 36, tile);
    } else {
        int m = (b - 9512) * 256 + threadIdx.x;
        if (m < M_TOK) {
            g_ab1[(size_t)m * KP_1150 + 1150] = __nv_bfloat16(0.f);
            g_ab1[(size_t)m * KP_1150 + 1151] = __nv_bfloat16(0.f);
            g_ab2[(size_t)m * KP_1150 + 1150] = __nv_bfloat16(0.f);
            g_ab2[(size_t)m * KP_1150 + 1151] = __nv_bfloat16(0.f);
            for (int c = NINP; c < KP_400; c++)
                g_ab3[(size_t)m * KP_400 + c] = __nv_bfloat16(0.f);
        }
    }
}

// embedding gather in bf16 (rows of the padded bf16 table)
__global__ void embed_bf_k(const int* __restrict__ tok,
                           const __nv_bfloat16* __restrict__ embb,
                           __nv_bfloat16* __restrict__ x0) {
    int m = blockIdx.x;
    int t = tok[m];
    const uint4* src = (const uint4*)(embb + (size_t)t * KP_400);
    uint4* dst = (uint4*)(x0 + (size_t)m * KP_400);
    for (int i = threadIdx.x; i < KP_400 * 2 / 16; i += blockDim.x) dst[i] = src[i];
}

// ================= bf16 GEMM: C[M,N] = A[M,Kpad] @ B[N,Kpad]^T (+bias) ==========
// cp.async 3-stage, one __syncthreads per K-tile, 2 CTAs/SM.
// KTAIL = number of real 16-k sub-tiles in the LAST 64-k tile (compile-time).
#define GSTAGES 3
#define GEMM_SMEM (GSTAGES * 32768)

template<bool BIAS, int KTAIL>
__global__ __launch_bounds__(256, 2) void bf16_gemm_k(
    const __nv_bfloat16* __restrict__ A, const __nv_bfloat16* __restrict__ B,
    const float* __restrict__ bias, float* __restrict__ C,
    int M, int N, int Kpad)
{
    extern __shared__ char smem[];
    const uint32_t sbase = smem_to_u32(smem);

    const int tid  = threadIdx.x;
    const int wid  = tid >> 5;
    const int lane = tid & 31;
    const int bm   = blockIdx.y * 128;
    const int bn   = blockIdx.x * 128;
    const int wm   = (wid >> 2) * 64;
    const int wn   = (wid & 3) * 32;

    const int lrow  = tid >> 1;
    const int lhalf = tid & 1;
    const __nv_bfloat16* Asrc = A + (size_t)(bm + lrow) * Kpad + lhalf * 32;
    const int gnrow = bn + lrow;
    const __nv_bfloat16* Bsrc = B + (size_t)gnrow * Kpad + lhalf * 32;
    const int bvalid = (gnrow < N) ? 16 : 0;

    const int lm16 = lane & 15;
    const int lk16 = lane >> 4;
    const int ln8  = lane & 7;
    const int lkb  = (lane >> 3) & 1;

    float acc[4][4][4];
#pragma unroll
    for (int mf = 0; mf < 4; mf++)
#pragma unroll
        for (int nf = 0; nf < 4; nf++)
#pragma unroll
            for (int i = 0; i < 4; i++) acc[mf][nf][i] = 0.f;

    auto load_tile = [&](int stage, int kt) {
        uint32_t sa = sbase + stage * 32768;
        uint32_t sb = sa + 16384;
        const __nv_bfloat16* ap = Asrc + kt * 64;
        const __nv_bfloat16* bp = Bsrc + kt * 64;
#pragma unroll
        for (int j = 0; j < 4; j++) {
            uint32_t off = SMEM_SWIZZLE_128B((uint32_t)(lrow * 128 + lhalf * 64 + j * 16));
            asm volatile("cp.async.cg.shared.global [%0], [%1], 16;"
                         :: "r"(sa + off), "l"(ap + j * 8));
            asm volatile("cp.async.cg.shared.global [%0], [%1], 16, %2;"
                         :: "r"(sb + off), "l"(bp + j * 8), "r"(bvalid));
        }
    };

    const int nkt = Kpad >> 6;

#pragma unroll
    for (int s = 0; s < GSTAGES - 1; s++) {
        load_tile(s, s);
        asm volatile("cp.async.commit_group;" ::: "memory");
    }

    for (int kt = 0; kt < nkt; kt++) {
        asm volatile("cp.async.wait_group %0;" :: "n"(GSTAGES - 2) : "memory");
        __syncthreads();

        if (kt + GSTAGES - 1 < nkt) {
            load_tile((kt + GSTAGES - 1) % GSTAGES, kt + GSTAGES - 1);
            asm volatile("cp.async.commit_group;" ::: "memory");
        } else {
            asm volatile("cp.async.commit_group;" ::: "memory");
        }

        uint32_t sa = sbase + (kt % GSTAGES) * 32768;
        uint32_t sb = sa + 16384;
        const bool last = (kt == nkt - 1);
#pragma unroll
        for (int s = 0; s < 4; s++) {
            if (s >= KTAIL && last) break;   // compile-time fold for s < KTAIL
            uint32_t af[4][4], bfr[4][2];
#pragma unroll
            for (int mf = 0; mf < 4; mf++) {
                uint32_t off = (uint32_t)((wm + mf * 16 + lm16) * 128 + s * 32 + lk16 * 16);
                uint32_t ad = sa + SMEM_SWIZZLE_128B(off);
                asm volatile("ldmatrix.sync.aligned.m8n8.x4.shared.b16 "
                             "{%0,%1,%2,%3}, [%4];"
                             : "=r"(af[mf][0]), "=r"(af[mf][1]),
                               "=r"(af[mf][2]), "=r"(af[mf][3]) : "r"(ad));
            }
#pragma unroll
            for (int nf = 0; nf < 4; nf++) {
                uint32_t off = (uint32_t)((wn + nf * 8 + ln8) * 128 + s * 32 + lkb * 16);
                uint32_t ad = sb + SMEM_SWIZZLE_128B(off);
                asm volatile("ldmatrix.sync.aligned.m8n8.x2.shared.b16 "
                             "{%0,%1}, [%2];"
                             : "=r"(bfr[nf][0]), "=r"(bfr[nf][1]) : "r"(ad));
            }
#pragma unroll
            for (int mf = 0; mf < 4; mf++)
#pragma unroll
                for (int nf = 0; nf < 4; nf++)
                    MMA_BF16(acc[mf][nf], af[mf], bfr[nf]);
        }
    }

    const int gID = lane >> 2;
    const int tg  = lane & 3;
#pragma unroll
    for (int mf = 0; mf < 4; mf++) {
        int r0 = bm + wm + mf * 16 + gID;
#pragma unroll
        for (int nf = 0; nf < 4; nf++) {
            int c0 = bn + wn + nf * 8 + tg * 2;
            float b0v = 0.f, b1v = 0.f;
            if (BIAS) {
                if (c0 < N)     b0v = bias[c0];
                if (c0 + 1 < N) b1v = bias[c0 + 1];
            }
            if (c0 < N) {
                C[(size_t)r0 * N + c0]       = acc[mf][nf][0] + b0v;
                C[(size_t)(r0 + 8) * N + c0] = acc[mf][nf][2] + b0v;
            }
            if (c0 + 1 < N) {
                C[(size_t)r0 * N + c0 + 1]       = acc[mf][nf][1] + b1v;
                C[(size_t)(r0 + 8) * N + c0 + 1] = acc[mf][nf][3] + b1v;
            }
        }
    }
}

// ============== tensor-core persistent LSTM recurrence (R11/R12) ================
template<int U, int KPU, int NCTA>
__global__ __launch_bounds__(256) void lstm_tc_k(
    const float* __restrict__ Um,
    const float* __restrict__ xg,
    __nv_bfloat16* __restrict__ xout,
    int ostride)
{
    constexpr int N4 = 4 * U;
    constexpr int KT = KPU / 16;
    constexpr int SH = KPU + 8;

    extern __shared__ char smraw[];
    const uint32_t ubase = smem_to_u32(smraw);
    const uint32_t hbase = ubase + 32 * SH * 2;
    float* red = (float*)(smraw + 32 * SH * 2 + 16 * SH * 2);
    float* gat = red + 512;
    __nv_bfloat16* U_s = (__nv_bfloat16*)smraw;

    const int tid  = threadIdx.x;
    const int wid  = tid >> 5;
    const int lane = tid & 31;
    const int nt   = wid & 3;
    const int kh   = wid >> 2;
    const int lm16 = lane & 15;
    const int lk16 = lane >> 4;
    const int ln8  = lane & 7;
    const int lkb  = (lane >> 3) & 1;
    const int gID  = lane >> 2;
    const int tg   = lane & 3;
    const int ub   = blockIdx.x * 8;

    for (int idx = tid; idx < 32 * KPU; idx += 256) {
        int k = idx >> 5, cc = idx & 31;
        int g = cc >> 3, ul = cc & 7;
        int uu = ub + ul;
        float v = (k < U && uu < U) ? Um[(size_t)k * N4 + (size_t)g * U + uu] : 0.f;
        U_s[cc * SH + k] = __float2bfloat16(v);
    }
    for (int idx = blockIdx.x * 256 + tid; idx < 2 * 16 * SH; idx += NCTA * 256)
        ((__nv_bfloat16*)g_hb)[idx] = __nv_bfloat16(0.f);

    float creg = 0.f;
    unsigned gen = 1;
    grid_sync(gen * NCTA);

    const uint32_t aaddr0 = hbase + lm16 * (SH * 2) + lk16 * 16;
    const uint32_t baddr0 = ubase + (nt * 8 + ln8) * (SH * 2) + lkb * 16;

    for (int t = 0; t < T_SEQ; ++t) {
        {
            const char* src = (const char*)&g_hb[t & 1][0];
            for (int i = tid; i < 2 * SH; i += 256) {
                asm volatile("cp.async.cg.shared.global [%0], [%1], 16;"
                             :: "r"(hbase + i * 16), "l"(src + i * 16));
            }
            asm volatile("cp.async.commit_group;" ::: "memory");
            asm volatile("cp.async.wait_group 0;" ::: "memory");
            __syncthreads();
        }

        float accA[4] = {0.f, 0.f, 0.f, 0.f};
        float accB[4] = {0.f, 0.f, 0.f, 0.f};
#pragma unroll
        for (int kt = kh; kt < KT; kt += 2) {
            uint32_t a[4], b[2];
            asm volatile("ldmatrix.sync.aligned.m8n8.x4.shared.b16 "
                         "{%0,%1,%2,%3}, [%4];"
                         : "=r"(a[0]), "=r"(a[1]), "=r"(a[2]), "=r"(a[3])
                         : "r"(aaddr0 + kt * 32));
            asm volatile("ldmatrix.sync.aligned.m8n8.x2.shared.b16 "
                         "{%0,%1}, [%2];"
                         : "=r"(b[0]), "=r"(b[1])
                         : "r"(baddr0 + kt * 32));
            if ((kt >> 1) & 1) { MMA_BF16(accB, a, b); }
            else               { MMA_BF16(accA, a, b); }
        }
#pragma unroll
        for (int i = 0; i < 4; i++) accA[i] += accB[i];

        const int i00 = nt * 128 + gID * 8 + tg * 2;
        const int i10 = nt * 128 + (gID + 8) * 8 + tg * 2;
        if (kh == 1) {
            red[i00]     = accA[0];
            red[i00 + 1] = accA[1];
            red[i10]     = accA[2];
            red[i10 + 1] = accA[3];
        }
        __syncthreads();
        if (kh == 0) {
            accA[0] += red[i00];
            accA[1] += red[i00 + 1];
            accA[2] += red[i10];
            accA[3] += red[i10 + 1];
            const int uu0 = ub + tg * 2, uu1 = uu0 + 1;
            const float* xr0 = xg + ((size_t)gID * T_SEQ + t) * N4 + (size_t)nt * U;
            const float* xr1 = xg + ((size_t)(gID + 8) * T_SEQ + t) * N4 + (size_t)nt * U;
            if (uu0 < U) { accA[0] += __ldg(&xr0[uu0]); accA[2] += __ldg(&xr1[uu0]); }
            if (uu1 < U) { accA[1] += __ldg(&xr0[uu1]); accA[3] += __ldg(&xr1[uu1]); }
            gat[i00]     = accA[0];
            gat[i00 + 1] = accA[1];
            gat[i10]     = accA[2];
            gat[i10 + 1] = accA[3];
        }
        __syncthreads();

        if (tid < 128) {
            int b = tid >> 3, ul = tid & 7;
            int uu = ub + ul;
            float iv  = gat[0 * 128 + tid];
            float fv  = gat[1 * 128 + tid];
            float cgv = gat[2 * 128 + tid];
            float ov  = gat[3 * 128 + tid];
            iv = 1.f / (1.f + __expf(-iv));
            fv = 1.f / (1.f + __expf(-fv));
            ov = 1.f / (1.f + __expf(-ov));
            cgv = tanhf(cgv);
            creg = fv * creg + iv * cgv;
            float hv = ov * tanhf(creg);
            if (uu < U) {
                __nv_bfloat16 hb = __float2bfloat16(hv);
                g_hb[(t & 1) ^ 1][b * SH + uu] = hb;
                xout[((size_t)b * T_SEQ + t) * ostride + uu] = hb;
            }
            __threadfence();
        }
        gen++;
        grid_sync(gen * NCTA);
    }
}

// ---------------- online row softmax (512 threads) ----------------
__global__ __launch_bounds__(512) void softmax_k(float* __restrict__ out, int N) {
    int m = blockIdx.x;
    float* row = out + (size_t)m * N;
    __shared__ float sm_[16], ss_[16];
    __shared__ float fm, fs;
    int tid = threadIdx.x, w = tid >> 5, ln = tid & 31;

    float mx = -3.4e38f, s = 0.f;
    for (int i = tid; i < N; i += 512) {
        float v = row[i];
        float nm = fmaxf(mx, v);
        s = s * __expf(mx - nm) + __expf(v - nm);
        mx = nm;
    }
#pragma unroll
    for (int o = 16; o; o >>= 1) {
        float om = __shfl_xor_sync(0xffffffffu, mx, o);
        float os = __shfl_xor_sync(0xffffffffu, s, o);
        float nm = fmaxf(mx, om);
        s = s * __expf(mx - nm) + os * __expf(om - nm);
        mx = nm;
    }
    if (!ln) { sm_[w] = mx; ss_[w] = s; }
    __syncthreads();
    if (tid == 0) {
        float M2 = sm_[0], S2 = ss_[0];
#pragma unroll
        for (int q = 1; q < 16; q++) {
            float nm = fmaxf(M2, sm_[q]);
            S2 = S2 * __expf(M2 - nm) + ss_[q] * __expf(sm_[q] - nm);
            M2 = nm;
        }
        fm = M2; fs = 1.f / S2;
    }
    __syncthreads();
    float MM = fm, IS = fs;
    for (int i = tid; i < N; i += 512) row[i] = __expf(row[i] - MM) * IS;
}

// ---------------- launch ----------------
extern "C" void kernel_launch(void* const* d_in, const int* in_sizes, int n_in,
                              void* d_out, int out_size)
{
    (void)in_sizes; (void)n_in; (void)out_size;
    const int*   tok = (const int*)d_in[0];
    const float* emb = (const float*)d_in[1];
    const float* W0  = (const float*)d_in[2];
    const float* U0  = (const float*)d_in[3];
    const float* b0  = (const float*)d_in[4];
    const float* W1  = (const float*)d_in[5];
    const float* U1  = (const float*)d_in[6];
    const float* b1  = (const float*)d_in[7];
    const float* W2  = (const float*)d_in[8];
    const float* U2  = (const float*)d_in[9];
    const float* b2  = (const float*)d_in[10];
    float* out = (float*)d_out;

    float* xg;
    __nv_bfloat16 *ab0, *ab1, *ab2, *ab3, *w0t, *w1t, *w2t, *embb;
    cudaGetSymbolAddress((void**)&xg, g_xg);
    cudaGetSymbolAddress((void**)&ab0, g_ab0);
    cudaGetSymbolAddress((void**)&ab1, g_ab1);
    cudaGetSymbolAddress((void**)&ab2, g_ab2);
    cudaGetSymbolAddress((void**)&ab3, g_ab3);
    cudaGetSymbolAddress((void**)&w0t, g_w0t);
    cudaGetSymbolAddress((void**)&w1t, g_w1t);
    cudaGetSymbolAddress((void**)&w2t, g_w2t);
    cudaGetSymbolAddress((void**)&embb, g_embb);

    const int SMEM_BIG   = 32 * 1160 * 2 + 16 * 1160 * 2 + 4096;   // 115456
    const int SMEM_SMALL = 32 * 408 * 2 + 16 * 408 * 2 + 4096;     // 43264
    cudaFuncSetAttribute((const void*)lstm_tc_k<NHID, 1152, 144>,
                         cudaFuncAttributeMaxDynamicSharedMemorySize, SMEM_BIG);
    cudaFuncSetAttribute((const void*)lstm_tc_k<NINP, 400, 50>,
                         cudaFuncAttributeMaxDynamicSharedMemorySize, SMEM_SMALL);
    cudaFuncSetAttribute((const void*)bf16_gemm_k<true, 1>,
                         cudaFuncAttributeMaxDynamicSharedMemorySize, GEMM_SMEM);
    cudaFuncSetAttribute((const void*)bf16_gemm_k<true, 4>,
                         cudaFuncAttributeMaxDynamicSharedMemorySize, GEMM_SMEM);
    cudaFuncSetAttribute((const void*)bf16_gemm_k<false, 1>,
                         cudaFuncAttributeMaxDynamicSharedMemorySize, GEMM_SMEM);

    // 1) fused prep (one launch)
    prep_k<<<PREP_BLOCKS, 256>>>(emb, W0, W1, W2);

    // 2) embedding
    embed_bf_k<<<M_TOK, 128>>>(tok, embb, ab0);

    // 3) layer 0  (K=400 in Kpad=448 -> KTAIL=1)
    bf16_gemm_k<true, 1><<<dim3((4 * NHID + 127) / 128, M_TOK / 128), 256, GEMM_SMEM>>>(
        ab0, w0t, b0, xg, M_TOK, 4 * NHID, KP_400);
    bar_reset_k<<<1, 1>>>();
    lstm_tc_k<NHID, 1152, 144><<<144, 256, SMEM_BIG>>>(U0, xg, ab1, KP_1150);

    // 4) layer 1  (K=1150 in 1152 -> KTAIL=4)
    bf16_gemm_k<true, 4><<<dim3((4 * NHID + 127) / 128, M_TOK / 128), 256, GEMM_SMEM>>>(
        ab1, w1t, b1, xg, M_TOK, 4 * NHID, KP_1150);
    bar_reset_k<<<1, 1>>>();
    lstm_tc_k<NHID, 1152, 144><<<144, 256, SMEM_BIG>>>(U1, xg, ab2, KP_1150);

    // 5) layer 2
    bf16_gemm_k<true, 4><<<dim3((4 * NINP + 127) / 128, M_TOK / 128), 256, GEMM_SMEM>>>(
        ab2, w2t, b2, xg, M_TOK, 4 * NINP, KP_1150);
    bar_reset_k<<<1, 1>>>();
    lstm_tc_k<NINP, 400, 50><<<50, 256, SMEM_SMALL>>>(U2, xg, ab3, KP_400);

    // 6) tied decode straight into d_out (KTAIL=1)
    bf16_gemm_k<false, 1><<<dim3((VOCABP1 + 127) / 128, M_TOK / 128), 256, GEMM_SMEM>>>(
        ab3, embb, nullptr, out, M_TOK, VOCABP1, KP_400);

    // 7) in-place softmax
    softmax_k<<<M_TOK, 512>>>(out, VOCABP1);
}